// round 12
// baseline (speedup 1.0000x reference)
#include <cuda_runtime.h>
#include <cuda_bf16.h>
#include <math_constants.h>
#include <stdint.h>

// ---------------------------------------------------------------------------
// Arch-variant gate: tcgen05 exists only in the sm_103a pass; the harness also
// builds compute_103 (non-a). Guarded kernels; host launches both variants,
// exactly one has a body per cubin.
// ---------------------------------------------------------------------------
#if defined(__CUDA_ARCH__)
#  if defined(__CUDA_ARCH_FEAT_SM103_ALL) || \
      (defined(__CUDA_ARCH_SPECIFIC__) && (__CUDA_ARCH_SPECIFIC__ == 1030))
#    define TC_OK 1
#  endif
#endif

// ---------------------------------------------------------------------------
#define B_   8
#define L_   1024
#define E_   1024
#define H_   16
#define D_   64
#define M_ROWS (B_ * L_)

__device__ float g_Q[B_ * H_ * L_ * D_];
__device__ float g_K[B_ * H_ * L_ * D_];
__device__ float g_V[B_ * H_ * L_ * D_];
__device__ float g_X[M_ROWS * E_];
__device__ float g_W[3 * E_ * E_];

// ---------------------------------------------------------------------------
// Common helpers
// ---------------------------------------------------------------------------
__device__ __forceinline__ float tf32r(float x) {
    uint32_t u;
    asm("cvt.rna.tf32.f32 %0, %1;" : "=r"(u) : "f"(x));
    return __uint_as_float(u);
}

__device__ __forceinline__ void mma_tf32(float c[4], const float a[4], const float b[2]) {
    asm volatile(
        "mma.sync.aligned.m16n8k8.row.col.f32.tf32.tf32.f32 "
        "{%0,%1,%2,%3}, {%4,%5,%6,%7}, {%8,%9}, {%0,%1,%2,%3};"
        : "+f"(c[0]), "+f"(c[1]), "+f"(c[2]), "+f"(c[3])
        : "r"(__float_as_uint(a[0])), "r"(__float_as_uint(a[1])),
          "r"(__float_as_uint(a[2])), "r"(__float_as_uint(a[3])),
          "r"(__float_as_uint(b[0])), "r"(__float_as_uint(b[1])));
}

#define CP_ASYNC_CG(dst, src) \
    asm volatile("cp.async.cg.shared.global [%0], [%1], 16;\n" :: "r"(dst), "l"(src))
#define CP_ASYNC_COMMIT() asm volatile("cp.async.commit_group;\n" ::: "memory")
#define CP_ASYNC_WAIT(n)  asm volatile("cp.async.wait_group %0;\n" :: "n"(n) : "memory")

__device__ __forceinline__ uint32_t smem_u32(const void* p) {
    uint32_t a;
    asm("{ .reg .u64 t; cvta.to.shared.u64 t, %1; cvt.u32.u64 %0, t; }" : "=r"(a) : "l"(p));
    return a;
}

#define SWZ(o) ((o) ^ (((o) >> 3) & 0x70))

// ---------------------------------------------------------------------------
// Kernel 0: fused fp32 -> tf32(rna) for X and all three W (single launch).
// ---------------------------------------------------------------------------
#define NX4 (M_ROWS * E_ / 4)     // 2097152
#define NW4 (E_ * E_ / 4)         // 262144

__global__ void cvt_all_kernel(const float4* __restrict__ x,
                               const float4* __restrict__ wq,
                               const float4* __restrict__ wk,
                               const float4* __restrict__ wv)
{
    const int i = blockIdx.x * blockDim.x + threadIdx.x;
    const float4* src;
    float4* dst;
    if (i < NX4) {
        src = x + i;
        dst = reinterpret_cast<float4*>(g_X) + i;
    } else {
        const int j = i - NX4;
        const int w = j >> 18;                 // NW4 == 1<<18
        const int r = j & (NW4 - 1);
        src = ((w == 0) ? wq : (w == 1) ? wk : wv) + r;
        dst = reinterpret_cast<float4*>(g_W) + j;
    }
    float4 v = *src;
    v.x = tf32r(v.x); v.y = tf32r(v.y); v.z = tf32r(v.z); v.w = tf32r(v.w);
    *dst = v;
}

// ---------------------------------------------------------------------------
// tcgen05 machinery (sm_103a pass only)
// ---------------------------------------------------------------------------
#ifdef TC_OK
__device__ __forceinline__ uint32_t elect_one() {
    uint32_t pred;
    asm volatile("{\n\t.reg .pred p;\n\telect.sync _|p, 0xFFFFFFFF;\n\t"
                 "selp.b32 %0, 1, 0, p;\n\t}" : "=r"(pred));
    return pred;
}

#define MBAR_INIT(a, c) \
    asm volatile("mbarrier.init.shared.b64 [%0], %1;" :: "r"(a), "r"(c) : "memory")
#define MBAR_WAIT(a, ph) do {                                                   \
    asm volatile("{\n\t.reg .pred P1;\n\t"                                      \
        "WAIT_LOOP_%=:\n\t"                                                     \
        "mbarrier.try_wait.parity.acquire.cta.shared::cta.b64 P1, [%0], %1, 0x989680;\n\t" \
        "@P1 bra.uni WAIT_DONE_%=;\n\t"                                         \
        "bra.uni WAIT_LOOP_%=;\n\t"                                             \
        "WAIT_DONE_%=:\n\t}"                                                    \
        :: "r"(a), "r"(ph) : "memory");                                         \
} while (0)

#define TCG_ALLOC(slot, n) \
    asm volatile("tcgen05.alloc.cta_group::1.sync.aligned.shared::cta.b32 [%0], %1;" \
                 :: "r"(slot), "r"((uint32_t)(n)) : "memory")
#define TCG_DEALLOC(t, n) \
    asm volatile("tcgen05.dealloc.cta_group::1.sync.aligned.b32 %0, %1;" :: "r"(t), "r"((uint32_t)(n)))
#define TCG_RELINQ() \
    asm volatile("tcgen05.relinquish_alloc_permit.cta_group::1.sync.aligned;")
#define TCG_COMMIT(mb) \
    asm volatile("tcgen05.commit.cta_group::1.mbarrier::arrive::one.shared::cluster.b64 [%0];" \
                 :: "r"(mb) : "memory")
#define TCG_FENCE_AFTER()  asm volatile("tcgen05.fence::after_thread_sync;" ::: "memory")
#define TCG_FENCE_BEFORE() asm volatile("tcgen05.fence::before_thread_sync;" ::: "memory")
#define TCG_WAIT_LD() asm volatile("tcgen05.wait::ld.sync.aligned;" ::: "memory")

#define TCG_LD_X32(r, addr)                                                      \
    asm volatile("tcgen05.ld.sync.aligned.32x32b.x32.b32 "                       \
        "{%0,%1,%2,%3,%4,%5,%6,%7,%8,%9,%10,%11,%12,%13,%14,%15,"               \
        "%16,%17,%18,%19,%20,%21,%22,%23,%24,%25,%26,%27,%28,%29,%30,%31}, [%32];" \
        : "=r"((r)[0]), "=r"((r)[1]), "=r"((r)[2]), "=r"((r)[3]),                \
          "=r"((r)[4]), "=r"((r)[5]), "=r"((r)[6]), "=r"((r)[7]),                \
          "=r"((r)[8]), "=r"((r)[9]), "=r"((r)[10]), "=r"((r)[11]),              \
          "=r"((r)[12]), "=r"((r)[13]), "=r"((r)[14]), "=r"((r)[15]),            \
          "=r"((r)[16]), "=r"((r)[17]), "=r"((r)[18]), "=r"((r)[19]),            \
          "=r"((r)[20]), "=r"((r)[21]), "=r"((r)[22]), "=r"((r)[23]),            \
          "=r"((r)[24]), "=r"((r)[25]), "=r"((r)[26]), "=r"((r)[27]),            \
          "=r"((r)[28]), "=r"((r)[29]), "=r"((r)[30]), "=r"((r)[31])             \
        : "r"(addr))

__device__ __forceinline__ uint64_t make_desc_sw128(uint32_t addr) {
    const uint64_t base = (uint64_t(2) << 61) | (uint64_t(1) << 46)
                        | (uint64_t(64) << 32) | (uint64_t(1) << 16);
    return base | ((uint64_t)(addr >> 4) & 0x3FFF);
}

// idesc kind::tf32: dtype F32@4, a/b TF32(2)@7/10, N/8@17, M/16@24
__device__ __forceinline__ uint32_t idesc_tf32(int n) {
    return (1u << 4) | (2u << 7) | (2u << 10) | (((uint32_t)n / 8) << 17) | (8u << 24);
}

__device__ __forceinline__ void mma_ss_tf32(uint32_t d, uint64_t a, uint64_t b,
                                            uint32_t idesc, uint32_t en) {
    asm volatile(
        "{\n\t.reg .pred p;\n\tsetp.ne.u32 p, %4, 0;\n\t"
        "tcgen05.mma.cta_group::1.kind::tf32 [%0], %1, %2, %3, {%5,%5,%5,%5}, p;\n\t}"
        :: "r"(d), "l"(a), "l"(b), "r"(idesc), "r"(en), "r"(0u) : "memory");
}
#endif  // TC_OK

// ---------------------------------------------------------------------------
// Kernel 1a: QKV projection on tcgen05 (sm_103a pass).  BM=256 x BN=256, BK=32.
// (verbatim R8 — proven)
// ---------------------------------------------------------------------------
#define NSTAGE 3
#define STAGE_BYTES 65536
#define QKV_TC_SMEM (NSTAGE * STAGE_BYTES)

__global__ __launch_bounds__(256, 1)
void qkv_tc_kernel(const float* __restrict__ bq,
                   const float* __restrict__ bk,
                   const float* __restrict__ bv)
{
#ifdef TC_OK
    extern __shared__ __align__(1024) char smem[];
    __shared__ uint32_t s_tmem;
    __shared__ __align__(8) uint64_t s_mbar[NSTAGE];

    const int t    = threadIdx.x;
    const int wid  = t >> 5;
    const int lane = t & 31;
    const int z    = blockIdx.z;
    const int m0   = blockIdx.y * 256;
    const int n0   = blockIdx.x * 256;

    const float* __restrict__ Wz   = g_W + (size_t)z * E_ * E_;
    const float* __restrict__ bias = (z == 0) ? bq : (z == 1) ? bk : bv;
    float* __restrict__ out        = (z == 0) ? g_Q : (z == 1) ? g_K : g_V;

    const uint32_t smem_u = smem_u32(smem);

    if (wid == 0) TCG_ALLOC(smem_u32(&s_tmem), 512);
    if (t == 0) {
#pragma unroll
        for (int s = 0; s < NSTAGE; s++) MBAR_INIT(smem_u32(&s_mbar[s]), 1);
    }
    __syncthreads();
    const uint32_t tmem = s_tmem;

    uint32_t phbits = 0;
    const uint32_t idq = idesc_tf32(256);

    for (int kt = 0; kt < 34; kt++) {
        if (kt < 32) {
            const int s = kt % 3;
            const int k0 = kt * 32;
            const uint32_t stg = smem_u + (uint32_t)s * STAGE_BYTES;
            if (kt >= 3) {
                MBAR_WAIT(smem_u32(&s_mbar[s]), (phbits >> s) & 1u);
                phbits ^= (1u << s);
            }
#pragma unroll
            for (int u = 0; u < 16; u++) {
                const int f = u * 256 + t;
                const float* src;
                uint32_t dst;
                if (u < 8) {
                    const int ti  = u >> 2;
                    const int fa  = f & 1023;
                    const int row = fa >> 3;
                    const int c   = fa & 7;
                    src = g_X + (size_t)(m0 + ti * 128 + row) * E_ + k0 + c * 4;
                    dst = stg + ti * 16384 + SWZ(row * 128 + c * 16);
                } else {
                    const int fb  = f - 2048;
                    const int row = fb >> 3;
                    const int c   = fb & 7;
                    src = Wz + (size_t)(n0 + row) * E_ + k0 + c * 4;
                    dst = stg + 32768 + SWZ(row * 128 + c * 16);
                }
                CP_ASYNC_CG(dst, src);
            }
            CP_ASYNC_COMMIT();
        }
        if (kt >= 2) {
            const int c  = kt - 2;
            const int sc = c % 3;
            if (kt < 32)       { CP_ASYNC_WAIT(2); }
            else if (kt == 32) { CP_ASYNC_WAIT(1); }
            else               { CP_ASYNC_WAIT(0); }
            asm volatile("fence.proxy.async.shared::cta;" ::: "memory");
            __syncthreads();
            if (wid == 0 && elect_one()) {
                const uint32_t stc = smem_u + (uint32_t)sc * STAGE_BYTES;
                const uint64_t bdesc = make_desc_sw128(stc + 32768);
#pragma unroll
                for (int ti = 0; ti < 2; ti++) {
                    const uint64_t adesc = make_desc_sw128(stc + ti * 16384);
#pragma unroll
                    for (int ks = 0; ks < 4; ks++) {
                        mma_ss_tf32(tmem + ti * 256, adesc + ks * 2, bdesc + ks * 2,
                                    idq, (c > 0 || ks > 0) ? 1u : 0u);
                    }
                }
                TCG_COMMIT(smem_u32(&s_mbar[sc]));
            }
        }
    }

    MBAR_WAIT(smem_u32(&s_mbar[1]), (phbits >> 1) & 1u);
    TCG_FENCE_AFTER();
    __syncthreads();

    // epilogue: LDTM -> smem transpose -> tf32r(bias add) -> coalesced scatter
    {
        const int ti = wid >> 2;
        const int sp = wid & 3;
        float* patch = reinterpret_cast<float*>(smem) + wid * (33 * 32);
        const int mr_base = m0 + ti * 128 + sp * 32;
#pragma unroll
        for (int cb = 0; cb < 8; cb++) {
            const int nb  = n0 + cb * 32;
            const int h   = nb >> 6;
            const int dd0 = nb & 63;
            const float bl = bias[nb + lane];
            uint32_t r[32];
            TCG_LD_X32(r, tmem + ti * 256 + cb * 32);
            TCG_WAIT_LD();
#pragma unroll
            for (int j = 0; j < 32; j++) patch[j * 33 + lane] = __uint_as_float(r[j]);
            __syncwarp();
#pragma unroll
            for (int rr = 0; rr < 32; rr++) {
                const int m = mr_base + rr;
                const int b = m >> 10;
                const int l = m & 1023;
                out[(((size_t)(b * H_ + h)) * L_ + l) * D_ + dd0 + lane] =
                    tf32r(patch[lane * 33 + rr] + bl);
            }
            __syncwarp();
        }
    }

    TCG_FENCE_BEFORE();
    __syncthreads();
    if (wid == 0) { TCG_RELINQ(); TCG_DEALLOC(tmem, 512); }
#else
    (void)bq; (void)bk; (void)bv;
#endif
}

// ---------------------------------------------------------------------------
// Kernel 1b: QKV fallback (non-a pass), mma.sync + cp.async (proven)
// ---------------------------------------------------------------------------
#define BK 32
#define STG_FLOATS (2 * 128 * BK)
#define STG_BYTES  (STG_FLOATS * 4)
#define NST 3
#define QKV_MMA_SMEM (NST * STG_BYTES)

__global__ __launch_bounds__(256, 2)
void qkv_mma2_kernel(const float* __restrict__ bq,
                     const float* __restrict__ bk,
                     const float* __restrict__ bv)
{
#ifndef TC_OK
    extern __shared__ __align__(128) float smemf[];

    const int t    = threadIdx.x;
    const int lane = t & 31;
    const int wid  = t >> 5;
    const int gid  = lane >> 2;
    const int tig  = lane & 3;
    const int wm   = (wid >> 1) * 32;
    const int wn   = (wid & 1) * 64;
    const int z    = blockIdx.z;
    const int m0   = blockIdx.y * 128;
    const int n0   = blockIdx.x * 128;

    const float* __restrict__ Wz   = g_W + (size_t)z * E_ * E_;
    const float* __restrict__ bias = (z == 0) ? bq : (z == 1) ? bk : bv;
    float* __restrict__ out        = (z == 0) ? g_Q : (z == 1) ? g_K : g_V;

    const uint32_t smem_b = smem_u32(smemf);
    const int lrow_base = t >> 3;
    const int lc        = (t & 7) * 16;

    float acc[2][8][4];
#pragma unroll
    for (int i = 0; i < 2; i++)
#pragma unroll
        for (int j = 0; j < 8; j++)
#pragma unroll
            for (int c = 0; c < 4; c++) acc[i][j][c] = 0.f;

    auto issue = [&](int kt, int s) {
        const uint32_t stg = smem_b + (uint32_t)s * STG_BYTES;
        const int k0 = kt * BK;
#pragma unroll
        for (int u = 0; u < 4; u++) {
            const int row = lrow_base + u * 32;
            const uint32_t sw = (uint32_t)(lc ^ ((row & 7) << 4));
            const uint32_t da = stg + (uint32_t)row * 128 + sw;
            const uint32_t db = da + 16384;
            const float* sa = g_X + (size_t)(m0 + row) * E_ + k0 + (lc >> 2);
            const float* sb = Wz  + (size_t)(n0 + row) * E_ + k0 + (lc >> 2);
            CP_ASYNC_CG(da, sa);
            CP_ASYNC_CG(db, sb);
        }
        CP_ASYNC_COMMIT();
    };

    issue(0, 0); issue(1, 1); issue(2, 2);
    const int x0 = 4 * gid;

    for (int kt = 0; kt < 32; kt++) {
        const int s = kt % 3;
        CP_ASYNC_WAIT(2);
        __syncthreads();
        const float* sA = smemf + (size_t)s * STG_FLOATS;
        const float* sB = sA + 4096;
#pragma unroll
        for (int ks = 0; ks < 4; ks++) {
            const int k  = ks * 8;
            const int c0 = (k + tig) ^ x0;
            const int c1 = (k + tig + 4) ^ x0;
            float a[2][4];
#pragma unroll
            for (int im = 0; im < 2; im++) {
                const int r0 = wm + im * 16 + gid;
                a[im][0] = sA[r0 * 32 + c0];
                a[im][1] = sA[(r0 + 8) * 32 + c0];
                a[im][2] = sA[r0 * 32 + c1];
                a[im][3] = sA[(r0 + 8) * 32 + c1];
            }
            float b[8][2];
#pragma unroll
            for (int jn = 0; jn < 8; jn++) {
                const int rn = wn + jn * 8 + gid;
                b[jn][0] = sB[rn * 32 + c0];
                b[jn][1] = sB[rn * 32 + c1];
            }
#pragma unroll
            for (int im = 0; im < 2; im++)
#pragma unroll
                for (int jn = 0; jn < 8; jn++)
                    mma_tf32(acc[im][jn], a[im], b[jn]);
        }
        __syncthreads();
        if (kt + 3 < 32) issue(kt + 3, s);
    }

#pragma unroll
    for (int im = 0; im < 2; im++) {
        const int mr = m0 + wm + im * 16 + gid;
        const int b0r = mr >> 10, l0r = mr & 1023;
        const int b1r = (mr + 8) >> 10, l1r = (mr + 8) & 1023;
#pragma unroll
        for (int jn = 0; jn < 8; jn++) {
            const int n  = n0 + wn + jn * 8 + 2 * tig;
            const int h  = n >> 6;
            const int dd = n & 63;
            const float bi0 = bias[n], bi1 = bias[n + 1];
            float2 v0, v1;
            v0.x = acc[im][jn][0] + bi0; v0.y = acc[im][jn][1] + bi1;
            v1.x = acc[im][jn][2] + bi0; v1.y = acc[im][jn][3] + bi1;
            *reinterpret_cast<float2*>(
                &out[(((size_t)(b0r * H_ + h)) * L_ + l0r) * D_ + dd]) = v0;
            *reinterpret_cast<float2*>(
                &out[(((size_t)(b1r * H_ + h)) * L_ + l1r) * D_ + dd]) = v1;
        }
    }
#else
    (void)bq; (void)bk; (void)bv;
#endif
}

// ---------------------------------------------------------------------------
// Kernel 2a: attention on tcgen05 (sm_103a pass), 2-CTA/SM variant.
// Same sync skeleton as R8 (mb_s wait -> consume -> mb_pv wait -> stores ->
// barrier -> bottom S-MMA(kt+1)+PV-MMA(kt) by warp 0). Changes: key-tile 64
// (16 iterations), K and Vt single-buffered (loads issued after the mbar
// waits that prove the buffers free), smem 96KB -> occupancy 2.
// SMEM: Q 32K @0 | K 16K @32768 | Vt 16K @49152 | P 32K @65536 = 96K.
// TMEM (alloc 256): S slots @0,@64 (64 cols each) | O @128 (64 cols).
// ---------------------------------------------------------------------------
#define AQ_OFF   0
#define AK_OFF   32768
#define AVT_OFF  49152
#define AP_OFF   65536
#define ATTN_TC_SMEM 98304

__global__ __launch_bounds__(256, 2)
void attn_tc_kernel(float* __restrict__ O)
{
#ifdef TC_OK
    extern __shared__ __align__(1024) char smem[];
    __shared__ uint32_t s_tmem;
    __shared__ __align__(8) uint64_t s_mbar_s, s_mbar_pv;
    __shared__ float s_l[2][128];

    const int t    = threadIdx.x;
    const int wid  = t >> 5;
    const int lane = t & 31;
    const int pr   = wid >> 2;          // column-half (0: cols 0-31, 1: 32-63)
    const int sp   = wid & 3;           // TMEM subpartition -> rows sp*32..+31
    const int bh   = blockIdx.y;
    const int q0   = blockIdx.x * 128;

    const float* __restrict__ Qb = g_Q + (size_t)bh * L_ * D_;
    const float* __restrict__ Kb = g_K + (size_t)bh * L_ * D_;
    const float* __restrict__ Vb = g_V + (size_t)bh * L_ * D_;

    const uint32_t su   = smem_u32(smem);
    const uint32_t qb   = su + AQ_OFF;
    const uint32_t kbuf = su + AK_OFF;
    const uint32_t vtb  = su + AVT_OFF;
    const uint32_t pb   = su + AP_OFF;

    if (wid == 0) TCG_ALLOC(smem_u32(&s_tmem), 256);
    if (t == 0) {
        MBAR_INIT(smem_u32(&s_mbar_s), 1);
        MBAR_INIT(smem_u32(&s_mbar_pv), 1);
    }
    __syncthreads();
    const uint32_t tmem = s_tmem;
    const uint32_t TM_O = tmem + 128;
    const uint32_t mb_s  = smem_u32(&s_mbar_s);
    const uint32_t mb_pv = smem_u32(&s_mbar_pv);

    // Q loader: 128 rows x 64 tf32 (2 chunks of 128B rows), 8 float4/thread
    auto load_q = [&]() {
#pragma unroll
        for (int c = 0; c < 2; c++) {
#pragma unroll
            for (int u = 0; u < 4; u++) {
                const int f   = u * 256 + t;
                const int row = f >> 3;
                const int cg  = f & 7;
                const float* src = Qb + (size_t)(q0 + row) * D_ + c * 32 + cg * 4;
                CP_ASYNC_CG(qb + c * 16384 + SWZ(row * 128 + cg * 16), src);
            }
        }
    };
    // K loader: 64 rows x 64 tf32 (2 chunks of 8KB), 2 float4/thread
    auto load_k = [&](int row0) {
#pragma unroll
        for (int c = 0; c < 2; c++) {
            const int f   = t;                  // 256 threads cover 64 rows x 8 f4 / 2... 512 f4 per chunk? 64*8=512 -> 2 per thread
#pragma unroll
            for (int u = 0; u < 2; u++) {
                const int g   = u * 256 + f;
                const int row = g >> 3;
                const int cg  = g & 7;
                const float* src = Kb + (size_t)(row0 + row) * D_ + c * 32 + cg * 4;
                CP_ASYNC_CG(kbuf + c * 8192 + SWZ(row * 128 + cg * 16), src);
            }
        }
    };

    // prologue: Q + K0
    load_q();
    load_k(0);
    CP_ASYNC_COMMIT();
    CP_ASYNC_WAIT(0);
    asm volatile("fence.proxy.async.shared::cta;" ::: "memory");
    __syncthreads();

    const uint32_t id_64 = idesc_tf32(64);

    // S-MMA(0)
    if (wid == 0 && elect_one()) {
#pragma unroll
        for (int c = 0; c < 2; c++) {
            const uint64_t adesc = make_desc_sw128(qb + c * 16384);
            const uint64_t bdesc = make_desc_sw128(kbuf + c * 8192);
#pragma unroll
            for (int ks = 0; ks < 4; ks++)
                mma_ss_tf32(tmem, adesc + ks * 2, bdesc + ks * 2,
                            id_64, (c > 0 || ks > 0) ? 1u : 0u);
        }
        TCG_COMMIT(mb_s);
    }

    float lpart = 0.f;
    const float scale = 0.125f;
    // V mapping: warp handles keys [wid*8, wid*8+8); lane: vrow8 = lane&7,
    // vdh = lane>>3 covers d-group of 16. Vt chunk = wid>>2 (keys 32/chunk),
    // col within chunk = (wid&3)*8 + vrow8.
    const int vrow8 = lane & 7;
    const int vdh   = lane >> 3;
    const int vcol  = (wid & 3) * 8 + vrow8;
    const int vchnk = wid >> 2;

    for (int kt = 0; kt < 16; kt++) {
        // --- V(kt) loads into registers ---
        float4 vr[4];
        {
            const float* vrow = Vb + (size_t)(kt * 64 + wid * 8 + vrow8) * D_ + vdh * 16;
#pragma unroll
            for (int j = 0; j < 4; j++)
                vr[j] = *reinterpret_cast<const float4*>(vrow + j * 4);
        }

        // --- wait S(kt); kbuf now free -> issue K(kt+1) load immediately ---
        MBAR_WAIT(mb_s, kt & 1);
        TCG_FENCE_AFTER();
        if (kt < 15) {
            load_k((kt + 1) * 64);
            CP_ASYNC_COMMIT();
        }

        // --- read S(kt) + exp (one 32-col LDTM per warp) ---
        uint32_t r0[32];
        TCG_LD_X32(r0, tmem + (kt & 1) * 64 + pr * 32);
        TCG_WAIT_LD();
        float p[32];
#pragma unroll
        for (int j = 0; j < 32; j++) {
            p[j] = tf32r(__expf(__uint_as_float(r0[j]) * scale));
            lpart += p[j];
        }

        // --- wait PV(kt-1) before overwriting P and Vt ---
        if (kt > 0) MBAR_WAIT(mb_pv, (kt - 1) & 1);

        // --- store P (tf32): row = sp*32+lane, key chunk pr ---
        {
            const int row = sp * 32 + lane;
#pragma unroll
            for (int jb = 0; jb < 8; jb++) {
                const uint32_t addr = pb + pr * 16384 + SWZ(row * 128 + jb * 16);
                float4 v4 = make_float4(p[jb * 4], p[jb * 4 + 1], p[jb * 4 + 2], p[jb * 4 + 3]);
                *reinterpret_cast<float4*>((char*)smem + (addr - su)) = v4;
            }
        }

        // --- store Vt(kt) transposed: Vt[d][key], chunk = key/32 ---
        {
            const uint32_t vdst = vtb + vchnk * 8192;
#pragma unroll
            for (int j = 0; j < 4; j++) {
                const int d = vdh * 16 + j * 4;
                float e0 = tf32r(vr[j].x), e1 = tf32r(vr[j].y),
                      e2 = tf32r(vr[j].z), e3 = tf32r(vr[j].w);
                *reinterpret_cast<float*>((char*)smem + (vdst + SWZ((d + 0) * 128 + vcol * 4) - su)) = e0;
                *reinterpret_cast<float*>((char*)smem + (vdst + SWZ((d + 1) * 128 + vcol * 4) - su)) = e1;
                *reinterpret_cast<float*>((char*)smem + (vdst + SWZ((d + 2) * 128 + vcol * 4) - su)) = e2;
                *reinterpret_cast<float*>((char*)smem + (vdst + SWZ((d + 3) * 128 + vcol * 4) - su)) = e3;
            }
        }

        // K(kt+1) completion (only group in flight), then rendezvous
        if (kt < 15) CP_ASYNC_WAIT(0);
        asm volatile("fence.proxy.async.shared::cta;" ::: "memory");
        __syncthreads();

        if (wid == 0 && elect_one()) {
            if (kt < 15) {   // S-MMA(kt+1) into the other slot
                const uint32_t dslot = tmem + ((kt + 1) & 1) * 64;
#pragma unroll
                for (int c = 0; c < 2; c++) {
                    const uint64_t adesc = make_desc_sw128(qb + c * 16384);
                    const uint64_t bdesc = make_desc_sw128(kbuf + c * 8192);
#pragma unroll
                    for (int ks = 0; ks < 4; ks++)
                        mma_ss_tf32(dslot, adesc + ks * 2, bdesc + ks * 2,
                                    id_64, (c > 0 || ks > 0) ? 1u : 0u);
                }
                TCG_COMMIT(mb_s);
            }
            // PV-MMA(kt): O += P x Vt (contraction over 64 keys, 8 k-steps)
            {
#pragma unroll
                for (int ks = 0; ks < 8; ks++) {
                    const int ch = ks >> 2;
                    const uint64_t adesc = make_desc_sw128(pb + ch * 16384) + (ks & 3) * 2;
                    const uint64_t bdesc = make_desc_sw128(vtb + ch * 8192) + (ks & 3) * 2;
                    mma_ss_tf32(TM_O, adesc, bdesc, id_64,
                                (kt > 0 || ks > 0) ? 1u : 0u);
                }
                TCG_COMMIT(mb_pv);
            }
        }
    }

    // combine row sums across column-halves
    s_l[pr][sp * 32 + lane] = lpart;
    __syncthreads();
    const int myrow = sp * 32 + lane;
    const float linv = 1.f / (s_l[0][myrow] + s_l[1][myrow]);

    // wait PV(15), read O, scale, transpose, coalesced store
    MBAR_WAIT(mb_pv, 15 & 1);
    TCG_FENCE_AFTER();
    {
        uint32_t r[32];
        TCG_LD_X32(r, TM_O + pr * 32);
        TCG_WAIT_LD();
        float* patch = reinterpret_cast<float*>(smem) + wid * (33 * 32);   // Q region reuse
        __syncthreads();   // all Q reads done long ago; ensure ordering vs patch writes
#pragma unroll
        for (int j = 0; j < 32; j++)
            patch[j * 33 + lane] = __uint_as_float(r[j]) * linv;
        __syncwarp();
        const int rbase = q0 + sp * 32;
        const int dcol  = pr * 32 + lane;
#pragma unroll
        for (int rr = 0; rr < 32; rr++) {
            O[((size_t)bh * L_ + rbase + rr) * D_ + dcol] = patch[lane * 33 + rr];
        }
    }

    TCG_FENCE_BEFORE();
    __syncthreads();
    if (wid == 0) { TCG_RELINQ(); TCG_DEALLOC(tmem, 256); }
#else
    (void)O;
#endif
}

// ---------------------------------------------------------------------------
// Kernel 2b: attention fallback (non-a pass), tf32 mma.sync (proven, 256 thr)
// ---------------------------------------------------------------------------
#define QP 68
#define VP 72
#define SM_Q  0
#define SM_P  (128 * QP)
#define SM_K  (2 * 128 * QP)
#define SM_V  (2 * 128 * QP + 64 * QP)
#define ATTN_SMEM_FLOATS (2 * 128 * QP + 64 * QP + 64 * VP)
#define ATTN_SMEM_BYTES  (ATTN_SMEM_FLOATS * 4)

__global__ __launch_bounds__(256, 2)
void attn_mma_kernel(float* __restrict__ O)
{
#ifndef TC_OK
    extern __shared__ float sm[];
    float* Qs = sm + SM_Q;
    float* Ps = sm + SM_P;
    float* Ks = sm + SM_K;
    float* Vs = sm + SM_V;

    const int bh = blockIdx.y;
    const int q0 = blockIdx.x * 128;
    const float* __restrict__ Qb = g_Q + (size_t)bh * L_ * D_;
    const float* __restrict__ Kb = g_K + (size_t)bh * L_ * D_;
    const float* __restrict__ Vb = g_V + (size_t)bh * L_ * D_;

    const int t    = threadIdx.x;
    const int lane = t & 31;
    const int wid  = t >> 5;
    const int gid  = lane >> 2;
    const int tig  = lane & 3;
    const int qb   = wid * 16;

#pragma unroll
    for (int u = 0; u < 8; u++) {
        const int g  = u * 256 + t;
        const int r  = g >> 4;
        const int c4 = (g & 15) * 4;
        float4 v = *reinterpret_cast<const float4*>(&Qb[(size_t)(q0 + r) * D_ + c4]);
        v.x = tf32r(v.x); v.y = tf32r(v.y); v.z = tf32r(v.z); v.w = tf32r(v.w);
        *reinterpret_cast<float4*>(&Qs[r * QP + c4]) = v;
    }

    float m_i[2] = {-CUDART_INF_F, -CUDART_INF_F};
    float l_i[2] = {0.f, 0.f};
    float o[8][4];
#pragma unroll
    for (int j = 0; j < 8; j++)
#pragma unroll
        for (int c = 0; c < 4; c++) o[j][c] = 0.f;

    for (int kt = 0; kt < L_ / 64; kt++) {
        __syncthreads();
        const int k0g = kt * 64;
#pragma unroll
        for (int u = 0; u < 4; u++) {
            const int g  = u * 256 + t;
            const int r  = g >> 4;
            const int c4 = (g & 15) * 4;
            float4 kv = *reinterpret_cast<const float4*>(&Kb[(size_t)(k0g + r) * D_ + c4]);
            float4 vv = *reinterpret_cast<const float4*>(&Vb[(size_t)(k0g + r) * D_ + c4]);
            kv.x = tf32r(kv.x); kv.y = tf32r(kv.y); kv.z = tf32r(kv.z); kv.w = tf32r(kv.w);
            vv.x = tf32r(vv.x); vv.y = tf32r(vv.y); vv.z = tf32r(vv.z); vv.w = tf32r(vv.w);
            *reinterpret_cast<float4*>(&Ks[r * QP + c4]) = kv;
            *reinterpret_cast<float4*>(&Vs[r * VP + c4]) = vv;
        }
        __syncthreads();

        float s[8][4];
#pragma unroll
        for (int j = 0; j < 8; j++)
#pragma unroll
            for (int c = 0; c < 4; c++) s[j][c] = 0.f;

#pragma unroll
        for (int ks = 0; ks < 8; ks++) {
            const int k = ks * 8;
            float a[4];
            a[0] = Qs[(qb + gid) * QP + k + tig];
            a[1] = Qs[(qb + gid + 8) * QP + k + tig];
            a[2] = Qs[(qb + gid) * QP + k + tig + 4];
            a[3] = Qs[(qb + gid + 8) * QP + k + tig + 4];
            float b[8][2];
#pragma unroll
            for (int jn = 0; jn < 8; jn++) {
                const int n = jn * 8;
                b[jn][0] = Ks[(n + gid) * QP + k + tig];
                b[jn][1] = Ks[(n + gid) * QP + k + tig + 4];
            }
#pragma unroll
            for (int jn = 0; jn < 8; jn++)
                mma_tf32(s[jn], a, b[jn]);
        }

        const float scale = 0.125f;
        float mt0 = -CUDART_INF_F, mt1 = -CUDART_INF_F;
#pragma unroll
        for (int jn = 0; jn < 8; jn++) {
            mt0 = fmaxf(mt0, fmaxf(s[jn][0], s[jn][1]));
            mt1 = fmaxf(mt1, fmaxf(s[jn][2], s[jn][3]));
        }
        mt0 *= scale; mt1 *= scale;
#pragma unroll
        for (int off = 1; off < 4; off <<= 1) {
            mt0 = fmaxf(mt0, __shfl_xor_sync(0xffffffffu, mt0, off));
            mt1 = fmaxf(mt1, __shfl_xor_sync(0xffffffffu, mt1, off));
        }
        const float mn0 = fmaxf(m_i[0], mt0);
        const float mn1 = fmaxf(m_i[1], mt1);
        const float cr0 = __expf(m_i[0] - mn0);
        const float cr1 = __expf(m_i[1] - mn1);
        float rs0 = 0.f, rs1 = 0.f;
#pragma unroll
        for (int jn = 0; jn < 8; jn++) {
            s[jn][0] = __expf(fmaf(s[jn][0], scale, -mn0));
            s[jn][1] = __expf(fmaf(s[jn][1], scale, -mn0));
            s[jn][2] = __expf(fmaf(s[jn][2], scale, -mn1));
            s[jn][3] = __expf(fmaf(s[jn][3], scale, -mn1));
            rs0 += s[jn][0] + s[jn][1];
            rs1 += s[jn][2] + s[jn][3];
        }
#pragma unroll
        for (int off = 1; off < 4; off <<= 1) {
            rs0 += __shfl_xor_sync(0xffffffffu, rs0, off);
            rs1 += __shfl_xor_sync(0xffffffffu, rs1, off);
        }
        l_i[0] = l_i[0] * cr0 + rs0;  m_i[0] = mn0;
        l_i[1] = l_i[1] * cr1 + rs1;  m_i[1] = mn1;
#pragma unroll
        for (int jn = 0; jn < 8; jn++) {
            o[jn][0] *= cr0; o[jn][1] *= cr0;
            o[jn][2] *= cr1; o[jn][3] *= cr1;
        }

#pragma unroll
        for (int jn = 0; jn < 8; jn++) {
            const int c = jn * 8 + 2 * tig;
            float2 p0, p1;
            p0.x = tf32r(s[jn][0]); p0.y = tf32r(s[jn][1]);
            p1.x = tf32r(s[jn][2]); p1.y = tf32r(s[jn][3]);
            *reinterpret_cast<float2*>(&Ps[(qb + gid) * QP + c]) = p0;
            *reinterpret_cast<float2*>(&Ps[(qb + gid + 8) * QP + c]) = p1;
        }
        __syncthreads();

#pragma unroll
        for (int ks = 0; ks < 8; ks++) {
            const int k = ks * 8;
            float a[4];
            a[0] = Ps[(qb + gid) * QP + k + tig];
            a[1] = Ps[(qb + gid + 8) * QP + k + tig];
            a[2] = Ps[(qb + gid) * QP + k + tig + 4];
            a[3] = Ps[(qb + gid + 8) * QP + k + tig + 4];
            float b[8][2];
#pragma unroll
            for (int jn = 0; jn < 8; jn++) {
                const int n = jn * 8;
                b[jn][0] = Vs[(k + tig) * VP + n + gid];
                b[jn][1] = Vs[(k + tig + 4) * VP + n + gid];
            }
#pragma unroll
            for (int jn = 0; jn < 8; jn++)
                mma_tf32(o[jn], a, b[jn]);
        }
    }

    const float inv0 = 1.f / l_i[0];
    const float inv1 = 1.f / l_i[1];
    const int r0 = q0 + qb + gid;
    const int r1 = r0 + 8;
#pragma unroll
    for (int jn = 0; jn < 8; jn++) {
        const int c = jn * 8 + 2 * tig;
        float2 v0, v1;
        v0.x = o[jn][0] * inv0; v0.y = o[jn][1] * inv0;
        v1.x = o[jn][2] * inv1; v1.y = o[jn][3] * inv1;
        *reinterpret_cast<float2*>(&O[((size_t)bh * L_ + r0) * D_ + c]) = v0;
        *reinterpret_cast<float2*>(&O[((size_t)bh * L_ + r1) * D_ + c]) = v1;
    }
#else
    (void)O;
#endif
}

// ---------------------------------------------------------------------------
extern "C" void kernel_launch(void* const* d_in, const int* in_sizes, int n_in,
                              void* d_out, int out_size)
{
    const float* x  = (const float*)d_in[0];
    const float* wq = (const float*)d_in[1];
    const float* bq = (const float*)d_in[2];
    const float* wk = (const float*)d_in[3];
    const float* bk = (const float*)d_in[4];
    const float* wv = (const float*)d_in[5];
    const float* bv = (const float*)d_in[6];
    float* out = (float*)d_out;

    cudaFuncSetAttribute(qkv_tc_kernel,
                         cudaFuncAttributeMaxDynamicSharedMemorySize, QKV_TC_SMEM);
    cudaFuncSetAttribute(qkv_mma2_kernel,
                         cudaFuncAttributeMaxDynamicSharedMemorySize, QKV_MMA_SMEM);
    cudaFuncSetAttribute(attn_tc_kernel,
                         cudaFuncAttributeMaxDynamicSharedMemorySize, ATTN_TC_SMEM);
    cudaFuncSetAttribute(attn_mma_kernel,
                         cudaFuncAttributeMaxDynamicSharedMemorySize, ATTN_SMEM_BYTES);

    // fused tf32(rna) rounding of X, Wq, Wk, Wv: exact grid
    const int total4 = NX4 + 3 * NW4;            // 2883584
    cvt_all_kernel<<<total4 / 256, 256>>>((const float4*)x, (const float4*)wq,
                                          (const float4*)wk, (const float4*)wv);

    // QKV: one of the two has a body per cubin
    dim3 tgrid(E_ / 256, M_ROWS / 256, 3);
    qkv_tc_kernel<<<tgrid, 256, QKV_TC_SMEM>>>(bq, bk, bv);
    dim3 fgrid(E_ / 128, M_ROWS / 128, 3);
    qkv_mma2_kernel<<<fgrid, 256, QKV_MMA_SMEM>>>(bq, bk, bv);

    // attention: same dual-variant scheme
    dim3 agrid(L_ / 128, B_ * H_);
    attn_tc_kernel<<<agrid, 256, ATTN_TC_SMEM>>>(out);
    attn_mma_kernel<<<agrid, 256, ATTN_SMEM_BYTES>>>(out);
}

// round 13
// speedup vs baseline: 1.4834x; 1.4834x over previous
#include <cuda_runtime.h>
#include <cuda_bf16.h>
#include <math_constants.h>
#include <stdint.h>

// ---------------------------------------------------------------------------
// Arch-variant gate: tcgen05 exists only in the sm_103a pass; the harness also
// builds compute_103 (non-a). Guarded kernels; host launches both variants,
// exactly one has a body per cubin.
// ---------------------------------------------------------------------------
#if defined(__CUDA_ARCH__)
#  if defined(__CUDA_ARCH_FEAT_SM103_ALL) || \
      (defined(__CUDA_ARCH_SPECIFIC__) && (__CUDA_ARCH_SPECIFIC__ == 1030))
#    define TC_OK 1
#  endif
#endif

// ---------------------------------------------------------------------------
#define B_   8
#define L_   1024
#define E_   1024
#define H_   16
#define D_   64
#define M_ROWS (B_ * L_)

__device__ float g_Q[B_ * H_ * L_ * D_];
__device__ float g_K[B_ * H_ * L_ * D_];
__device__ float g_V[B_ * H_ * L_ * D_];
__device__ float g_X[M_ROWS * E_];
__device__ float g_W[3 * E_ * E_];

// ---------------------------------------------------------------------------
// Common helpers
// ---------------------------------------------------------------------------
__device__ __forceinline__ float tf32r(float x) {
    uint32_t u;
    asm("cvt.rna.tf32.f32 %0, %1;" : "=r"(u) : "f"(x));
    return __uint_as_float(u);
}

__device__ __forceinline__ void mma_tf32(float c[4], const float a[4], const float b[2]) {
    asm volatile(
        "mma.sync.aligned.m16n8k8.row.col.f32.tf32.tf32.f32 "
        "{%0,%1,%2,%3}, {%4,%5,%6,%7}, {%8,%9}, {%0,%1,%2,%3};"
        : "+f"(c[0]), "+f"(c[1]), "+f"(c[2]), "+f"(c[3])
        : "r"(__float_as_uint(a[0])), "r"(__float_as_uint(a[1])),
          "r"(__float_as_uint(a[2])), "r"(__float_as_uint(a[3])),
          "r"(__float_as_uint(b[0])), "r"(__float_as_uint(b[1])));
}

#define CP_ASYNC_CG(dst, src) \
    asm volatile("cp.async.cg.shared.global [%0], [%1], 16;\n" :: "r"(dst), "l"(src))
#define CP_ASYNC_COMMIT() asm volatile("cp.async.commit_group;\n" ::: "memory")
#define CP_ASYNC_WAIT(n)  asm volatile("cp.async.wait_group %0;\n" :: "n"(n) : "memory")

__device__ __forceinline__ uint32_t smem_u32(const void* p) {
    uint32_t a;
    asm("{ .reg .u64 t; cvta.to.shared.u64 t, %1; cvt.u32.u64 %0, t; }" : "=r"(a) : "l"(p));
    return a;
}

#define SWZ(o) ((o) ^ (((o) >> 3) & 0x70))

// ---------------------------------------------------------------------------
// Kernel 0: fused fp32 -> tf32(rna) for X and all three W (single launch).
// ---------------------------------------------------------------------------
#define NX4 (M_ROWS * E_ / 4)     // 2097152
#define NW4 (E_ * E_ / 4)         // 262144

__global__ void cvt_all_kernel(const float4* __restrict__ x,
                               const float4* __restrict__ wq,
                               const float4* __restrict__ wk,
                               const float4* __restrict__ wv)
{
    const int i = blockIdx.x * blockDim.x + threadIdx.x;
    const float4* src;
    float4* dst;
    if (i < NX4) {
        src = x + i;
        dst = reinterpret_cast<float4*>(g_X) + i;
    } else {
        const int j = i - NX4;
        const int w = j >> 18;                 // NW4 == 1<<18
        const int r = j & (NW4 - 1);
        src = ((w == 0) ? wq : (w == 1) ? wk : wv) + r;
        dst = reinterpret_cast<float4*>(g_W) + j;
    }
    float4 v = *src;
    v.x = tf32r(v.x); v.y = tf32r(v.y); v.z = tf32r(v.z); v.w = tf32r(v.w);
    *dst = v;
}

// ---------------------------------------------------------------------------
// tcgen05 machinery (sm_103a pass only)
// ---------------------------------------------------------------------------
#ifdef TC_OK
__device__ __forceinline__ uint32_t elect_one() {
    uint32_t pred;
    asm volatile("{\n\t.reg .pred p;\n\telect.sync _|p, 0xFFFFFFFF;\n\t"
                 "selp.b32 %0, 1, 0, p;\n\t}" : "=r"(pred));
    return pred;
}

#define MBAR_INIT(a, c) \
    asm volatile("mbarrier.init.shared.b64 [%0], %1;" :: "r"(a), "r"(c) : "memory")
#define MBAR_WAIT(a, ph) do {                                                   \
    asm volatile("{\n\t.reg .pred P1;\n\t"                                      \
        "WAIT_LOOP_%=:\n\t"                                                     \
        "mbarrier.try_wait.parity.acquire.cta.shared::cta.b64 P1, [%0], %1, 0x989680;\n\t" \
        "@P1 bra.uni WAIT_DONE_%=;\n\t"                                         \
        "bra.uni WAIT_LOOP_%=;\n\t"                                             \
        "WAIT_DONE_%=:\n\t}"                                                    \
        :: "r"(a), "r"(ph) : "memory");                                         \
} while (0)

#define TCG_ALLOC(slot, n) \
    asm volatile("tcgen05.alloc.cta_group::1.sync.aligned.shared::cta.b32 [%0], %1;" \
                 :: "r"(slot), "r"((uint32_t)(n)) : "memory")
#define TCG_DEALLOC(t, n) \
    asm volatile("tcgen05.dealloc.cta_group::1.sync.aligned.b32 %0, %1;" :: "r"(t), "r"((uint32_t)(n)))
#define TCG_RELINQ() \
    asm volatile("tcgen05.relinquish_alloc_permit.cta_group::1.sync.aligned;")
#define TCG_COMMIT(mb) \
    asm volatile("tcgen05.commit.cta_group::1.mbarrier::arrive::one.shared::cluster.b64 [%0];" \
                 :: "r"(mb) : "memory")
#define TCG_FENCE_AFTER()  asm volatile("tcgen05.fence::after_thread_sync;" ::: "memory")
#define TCG_FENCE_BEFORE() asm volatile("tcgen05.fence::before_thread_sync;" ::: "memory")
#define TCG_WAIT_LD() asm volatile("tcgen05.wait::ld.sync.aligned;" ::: "memory")

#define TCG_LD_X32(r, addr)                                                      \
    asm volatile("tcgen05.ld.sync.aligned.32x32b.x32.b32 "                       \
        "{%0,%1,%2,%3,%4,%5,%6,%7,%8,%9,%10,%11,%12,%13,%14,%15,"               \
        "%16,%17,%18,%19,%20,%21,%22,%23,%24,%25,%26,%27,%28,%29,%30,%31}, [%32];" \
        : "=r"((r)[0]), "=r"((r)[1]), "=r"((r)[2]), "=r"((r)[3]),                \
          "=r"((r)[4]), "=r"((r)[5]), "=r"((r)[6]), "=r"((r)[7]),                \
          "=r"((r)[8]), "=r"((r)[9]), "=r"((r)[10]), "=r"((r)[11]),              \
          "=r"((r)[12]), "=r"((r)[13]), "=r"((r)[14]), "=r"((r)[15]),            \
          "=r"((r)[16]), "=r"((r)[17]), "=r"((r)[18]), "=r"((r)[19]),            \
          "=r"((r)[20]), "=r"((r)[21]), "=r"((r)[22]), "=r"((r)[23]),            \
          "=r"((r)[24]), "=r"((r)[25]), "=r"((r)[26]), "=r"((r)[27]),            \
          "=r"((r)[28]), "=r"((r)[29]), "=r"((r)[30]), "=r"((r)[31])             \
        : "r"(addr))

__device__ __forceinline__ uint64_t make_desc_sw128(uint32_t addr) {
    const uint64_t base = (uint64_t(2) << 61) | (uint64_t(1) << 46)
                        | (uint64_t(64) << 32) | (uint64_t(1) << 16);
    return base | ((uint64_t)(addr >> 4) & 0x3FFF);
}

// idesc kind::tf32: dtype F32@4, a/b TF32(2)@7/10, N/8@17, M/16@24
__device__ __forceinline__ uint32_t idesc_tf32(int n) {
    return (1u << 4) | (2u << 7) | (2u << 10) | (((uint32_t)n / 8) << 17) | (8u << 24);
}

__device__ __forceinline__ void mma_ss_tf32(uint32_t d, uint64_t a, uint64_t b,
                                            uint32_t idesc, uint32_t en) {
    asm volatile(
        "{\n\t.reg .pred p;\n\tsetp.ne.u32 p, %4, 0;\n\t"
        "tcgen05.mma.cta_group::1.kind::tf32 [%0], %1, %2, %3, {%5,%5,%5,%5}, p;\n\t}"
        :: "r"(d), "l"(a), "l"(b), "r"(idesc), "r"(en), "r"(0u) : "memory");
}
#endif  // TC_OK

// ---------------------------------------------------------------------------
// Kernel 1a: QKV projection on tcgen05 (sm_103a pass).  BM=256 x BN=256, BK=32.
// (verbatim R8 — proven)
// ---------------------------------------------------------------------------
#define NSTAGE 3
#define STAGE_BYTES 65536
#define QKV_TC_SMEM (NSTAGE * STAGE_BYTES)

__global__ __launch_bounds__(256, 1)
void qkv_tc_kernel(const float* __restrict__ bq,
                   const float* __restrict__ bk,
                   const float* __restrict__ bv)
{
#ifdef TC_OK
    extern __shared__ __align__(1024) char smem[];
    __shared__ uint32_t s_tmem;
    __shared__ __align__(8) uint64_t s_mbar[NSTAGE];

    const int t    = threadIdx.x;
    const int wid  = t >> 5;
    const int lane = t & 31;
    const int z    = blockIdx.z;
    const int m0   = blockIdx.y * 256;
    const int n0   = blockIdx.x * 256;

    const float* __restrict__ Wz   = g_W + (size_t)z * E_ * E_;
    const float* __restrict__ bias = (z == 0) ? bq : (z == 1) ? bk : bv;
    float* __restrict__ out        = (z == 0) ? g_Q : (z == 1) ? g_K : g_V;

    const uint32_t smem_u = smem_u32(smem);

    if (wid == 0) TCG_ALLOC(smem_u32(&s_tmem), 512);
    if (t == 0) {
#pragma unroll
        for (int s = 0; s < NSTAGE; s++) MBAR_INIT(smem_u32(&s_mbar[s]), 1);
    }
    __syncthreads();
    const uint32_t tmem = s_tmem;

    uint32_t phbits = 0;
    const uint32_t idq = idesc_tf32(256);

    for (int kt = 0; kt < 34; kt++) {
        if (kt < 32) {
            const int s = kt % 3;
            const int k0 = kt * 32;
            const uint32_t stg = smem_u + (uint32_t)s * STAGE_BYTES;
            if (kt >= 3) {
                MBAR_WAIT(smem_u32(&s_mbar[s]), (phbits >> s) & 1u);
                phbits ^= (1u << s);
            }
#pragma unroll
            for (int u = 0; u < 16; u++) {
                const int f = u * 256 + t;
                const float* src;
                uint32_t dst;
                if (u < 8) {
                    const int ti  = u >> 2;
                    const int fa  = f & 1023;
                    const int row = fa >> 3;
                    const int c   = fa & 7;
                    src = g_X + (size_t)(m0 + ti * 128 + row) * E_ + k0 + c * 4;
                    dst = stg + ti * 16384 + SWZ(row * 128 + c * 16);
                } else {
                    const int fb  = f - 2048;
                    const int row = fb >> 3;
                    const int c   = fb & 7;
                    src = Wz + (size_t)(n0 + row) * E_ + k0 + c * 4;
                    dst = stg + 32768 + SWZ(row * 128 + c * 16);
                }
                CP_ASYNC_CG(dst, src);
            }
            CP_ASYNC_COMMIT();
        }
        if (kt >= 2) {
            const int c  = kt - 2;
            const int sc = c % 3;
            if (kt < 32)       { CP_ASYNC_WAIT(2); }
            else if (kt == 32) { CP_ASYNC_WAIT(1); }
            else               { CP_ASYNC_WAIT(0); }
            asm volatile("fence.proxy.async.shared::cta;" ::: "memory");
            __syncthreads();
            if (wid == 0 && elect_one()) {
                const uint32_t stc = smem_u + (uint32_t)sc * STAGE_BYTES;
                const uint64_t bdesc = make_desc_sw128(stc + 32768);
#pragma unroll
                for (int ti = 0; ti < 2; ti++) {
                    const uint64_t adesc = make_desc_sw128(stc + ti * 16384);
#pragma unroll
                    for (int ks = 0; ks < 4; ks++) {
                        mma_ss_tf32(tmem + ti * 256, adesc + ks * 2, bdesc + ks * 2,
                                    idq, (c > 0 || ks > 0) ? 1u : 0u);
                    }
                }
                TCG_COMMIT(smem_u32(&s_mbar[sc]));
            }
        }
    }

    MBAR_WAIT(smem_u32(&s_mbar[1]), (phbits >> 1) & 1u);
    TCG_FENCE_AFTER();
    __syncthreads();

    // epilogue: LDTM -> smem transpose -> tf32r(bias add) -> coalesced scatter
    {
        const int ti = wid >> 2;
        const int sp = wid & 3;
        float* patch = reinterpret_cast<float*>(smem) + wid * (33 * 32);
        const int mr_base = m0 + ti * 128 + sp * 32;
#pragma unroll
        for (int cb = 0; cb < 8; cb++) {
            const int nb  = n0 + cb * 32;
            const int h   = nb >> 6;
            const int dd0 = nb & 63;
            const float bl = bias[nb + lane];
            uint32_t r[32];
            TCG_LD_X32(r, tmem + ti * 256 + cb * 32);
            TCG_WAIT_LD();
#pragma unroll
            for (int j = 0; j < 32; j++) patch[j * 33 + lane] = __uint_as_float(r[j]);
            __syncwarp();
#pragma unroll
            for (int rr = 0; rr < 32; rr++) {
                const int m = mr_base + rr;
                const int b = m >> 10;
                const int l = m & 1023;
                out[(((size_t)(b * H_ + h)) * L_ + l) * D_ + dd0 + lane] =
                    tf32r(patch[lane * 33 + rr] + bl);
            }
            __syncwarp();
        }
    }

    TCG_FENCE_BEFORE();
    __syncthreads();
    if (wid == 0) { TCG_RELINQ(); TCG_DEALLOC(tmem, 512); }
#else
    (void)bq; (void)bk; (void)bv;
#endif
}

// ---------------------------------------------------------------------------
// Kernel 1b: QKV fallback (non-a pass), mma.sync + cp.async (proven)
// ---------------------------------------------------------------------------
#define BK 32
#define STG_FLOATS (2 * 128 * BK)
#define STG_BYTES  (STG_FLOATS * 4)
#define NST 3
#define QKV_MMA_SMEM (NST * STG_BYTES)

__global__ __launch_bounds__(256, 2)
void qkv_mma2_kernel(const float* __restrict__ bq,
                     const float* __restrict__ bk,
                     const float* __restrict__ bv)
{
#ifndef TC_OK
    extern __shared__ __align__(128) float smemf[];

    const int t    = threadIdx.x;
    const int lane = t & 31;
    const int wid  = t >> 5;
    const int gid  = lane >> 2;
    const int tig  = lane & 3;
    const int wm   = (wid >> 1) * 32;
    const int wn   = (wid & 1) * 64;
    const int z    = blockIdx.z;
    const int m0   = blockIdx.y * 128;
    const int n0   = blockIdx.x * 128;

    const float* __restrict__ Wz   = g_W + (size_t)z * E_ * E_;
    const float* __restrict__ bias = (z == 0) ? bq : (z == 1) ? bk : bv;
    float* __restrict__ out        = (z == 0) ? g_Q : (z == 1) ? g_K : g_V;

    const uint32_t smem_b = smem_u32(smemf);
    const int lrow_base = t >> 3;
    const int lc        = (t & 7) * 16;

    float acc[2][8][4];
#pragma unroll
    for (int i = 0; i < 2; i++)
#pragma unroll
        for (int j = 0; j < 8; j++)
#pragma unroll
            for (int c = 0; c < 4; c++) acc[i][j][c] = 0.f;

    auto issue = [&](int kt, int s) {
        const uint32_t stg = smem_b + (uint32_t)s * STG_BYTES;
        const int k0 = kt * BK;
#pragma unroll
        for (int u = 0; u < 4; u++) {
            const int row = lrow_base + u * 32;
            const uint32_t sw = (uint32_t)(lc ^ ((row & 7) << 4));
            const uint32_t da = stg + (uint32_t)row * 128 + sw;
            const uint32_t db = da + 16384;
            const float* sa = g_X + (size_t)(m0 + row) * E_ + k0 + (lc >> 2);
            const float* sb = Wz  + (size_t)(n0 + row) * E_ + k0 + (lc >> 2);
            CP_ASYNC_CG(da, sa);
            CP_ASYNC_CG(db, sb);
        }
        CP_ASYNC_COMMIT();
    };

    issue(0, 0); issue(1, 1); issue(2, 2);
    const int x0 = 4 * gid;

    for (int kt = 0; kt < 32; kt++) {
        const int s = kt % 3;
        CP_ASYNC_WAIT(2);
        __syncthreads();
        const float* sA = smemf + (size_t)s * STG_FLOATS;
        const float* sB = sA + 4096;
#pragma unroll
        for (int ks = 0; ks < 4; ks++) {
            const int k  = ks * 8;
            const int c0 = (k + tig) ^ x0;
            const int c1 = (k + tig + 4) ^ x0;
            float a[2][4];
#pragma unroll
            for (int im = 0; im < 2; im++) {
                const int r0 = wm + im * 16 + gid;
                a[im][0] = sA[r0 * 32 + c0];
                a[im][1] = sA[(r0 + 8) * 32 + c0];
                a[im][2] = sA[r0 * 32 + c1];
                a[im][3] = sA[(r0 + 8) * 32 + c1];
            }
            float b[8][2];
#pragma unroll
            for (int jn = 0; jn < 8; jn++) {
                const int rn = wn + jn * 8 + gid;
                b[jn][0] = sB[rn * 32 + c0];
                b[jn][1] = sB[rn * 32 + c1];
            }
#pragma unroll
            for (int im = 0; im < 2; im++)
#pragma unroll
                for (int jn = 0; jn < 8; jn++)
                    mma_tf32(acc[im][jn], a[im], b[jn]);
        }
        __syncthreads();
        if (kt + 3 < 32) issue(kt + 3, s);
    }

#pragma unroll
    for (int im = 0; im < 2; im++) {
        const int mr = m0 + wm + im * 16 + gid;
        const int b0r = mr >> 10, l0r = mr & 1023;
        const int b1r = (mr + 8) >> 10, l1r = (mr + 8) & 1023;
#pragma unroll
        for (int jn = 0; jn < 8; jn++) {
            const int n  = n0 + wn + jn * 8 + 2 * tig;
            const int h  = n >> 6;
            const int dd = n & 63;
            const float bi0 = bias[n], bi1 = bias[n + 1];
            float2 v0, v1;
            v0.x = acc[im][jn][0] + bi0; v0.y = acc[im][jn][1] + bi1;
            v1.x = acc[im][jn][2] + bi0; v1.y = acc[im][jn][3] + bi1;
            *reinterpret_cast<float2*>(
                &out[(((size_t)(b0r * H_ + h)) * L_ + l0r) * D_ + dd]) = v0;
            *reinterpret_cast<float2*>(
                &out[(((size_t)(b1r * H_ + h)) * L_ + l1r) * D_ + dd]) = v1;
        }
    }
#else
    (void)bq; (void)bk; (void)bv;
#endif
}

// ---------------------------------------------------------------------------
// Kernel 2a: attention on tcgen05 (sm_103a pass), 2-CTA/SM variant.
// Same sync skeleton as R8 (mb_s wait -> consume -> mb_pv wait -> stores ->
// barrier -> bottom S-MMA(kt+1)+PV-MMA(kt) by warp 0). Changes: key-tile 64
// (16 iterations), K and Vt single-buffered (loads issued after the mbar
// waits that prove the buffers free), smem 96KB -> occupancy 2.
// SMEM: Q 32K @0 | K 16K @32768 | Vt 16K @49152 | P 32K @65536 = 96K.
// TMEM (alloc 256): S slots @0,@64 (64 cols each) | O @128 (64 cols).
// ---------------------------------------------------------------------------
#define AQ_OFF   0
#define AK_OFF   32768
#define AVT_OFF  49152
#define AP_OFF   65536
#define ATTN_TC_SMEM 98304

__global__ __launch_bounds__(256, 2)
void attn_tc_kernel(float* __restrict__ O)
{
#ifdef TC_OK
    extern __shared__ __align__(1024) char smem[];
    __shared__ uint32_t s_tmem;
    __shared__ __align__(8) uint64_t s_mbar_s, s_mbar_pv;
    __shared__ float s_l[2][128];

    const int t    = threadIdx.x;
    const int wid  = t >> 5;
    const int lane = t & 31;
    const int pr   = wid >> 2;          // column-half (0: cols 0-31, 1: 32-63)
    const int sp   = wid & 3;           // TMEM subpartition -> rows sp*32..+31
    const int bh   = blockIdx.y;
    const int q0   = blockIdx.x * 128;

    const float* __restrict__ Qb = g_Q + (size_t)bh * L_ * D_;
    const float* __restrict__ Kb = g_K + (size_t)bh * L_ * D_;
    const float* __restrict__ Vb = g_V + (size_t)bh * L_ * D_;

    const uint32_t su   = smem_u32(smem);
    const uint32_t qb   = su + AQ_OFF;
    const uint32_t kbuf = su + AK_OFF;
    const uint32_t vtb  = su + AVT_OFF;
    const uint32_t pb   = su + AP_OFF;

    if (wid == 0) TCG_ALLOC(smem_u32(&s_tmem), 256);
    if (t == 0) {
        MBAR_INIT(smem_u32(&s_mbar_s), 1);
        MBAR_INIT(smem_u32(&s_mbar_pv), 1);
    }
    __syncthreads();
    const uint32_t tmem = s_tmem;
    const uint32_t TM_O = tmem + 128;
    const uint32_t mb_s  = smem_u32(&s_mbar_s);
    const uint32_t mb_pv = smem_u32(&s_mbar_pv);

    // Q loader: 128 rows x 64 tf32 (2 chunks of 128B rows), 8 float4/thread
    auto load_q = [&]() {
#pragma unroll
        for (int c = 0; c < 2; c++) {
#pragma unroll
            for (int u = 0; u < 4; u++) {
                const int f   = u * 256 + t;
                const int row = f >> 3;
                const int cg  = f & 7;
                const float* src = Qb + (size_t)(q0 + row) * D_ + c * 32 + cg * 4;
                CP_ASYNC_CG(qb + c * 16384 + SWZ(row * 128 + cg * 16), src);
            }
        }
    };
    // K loader: 64 rows x 64 tf32 (2 chunks of 8KB), 2 float4/thread
    auto load_k = [&](int row0) {
#pragma unroll
        for (int c = 0; c < 2; c++) {
            const int f   = t;                  // 256 threads cover 64 rows x 8 f4 / 2... 512 f4 per chunk? 64*8=512 -> 2 per thread
#pragma unroll
            for (int u = 0; u < 2; u++) {
                const int g   = u * 256 + f;
                const int row = g >> 3;
                const int cg  = g & 7;
                const float* src = Kb + (size_t)(row0 + row) * D_ + c * 32 + cg * 4;
                CP_ASYNC_CG(kbuf + c * 8192 + SWZ(row * 128 + cg * 16), src);
            }
        }
    };

    // prologue: Q + K0
    load_q();
    load_k(0);
    CP_ASYNC_COMMIT();
    CP_ASYNC_WAIT(0);
    asm volatile("fence.proxy.async.shared::cta;" ::: "memory");
    __syncthreads();

    const uint32_t id_64 = idesc_tf32(64);

    // S-MMA(0)
    if (wid == 0 && elect_one()) {
#pragma unroll
        for (int c = 0; c < 2; c++) {
            const uint64_t adesc = make_desc_sw128(qb + c * 16384);
            const uint64_t bdesc = make_desc_sw128(kbuf + c * 8192);
#pragma unroll
            for (int ks = 0; ks < 4; ks++)
                mma_ss_tf32(tmem, adesc + ks * 2, bdesc + ks * 2,
                            id_64, (c > 0 || ks > 0) ? 1u : 0u);
        }
        TCG_COMMIT(mb_s);
    }

    float lpart = 0.f;
    const float scale = 0.125f;
    // V mapping: warp handles keys [wid*8, wid*8+8); lane: vrow8 = lane&7,
    // vdh = lane>>3 covers d-group of 16. Vt chunk = wid>>2 (keys 32/chunk),
    // col within chunk = (wid&3)*8 + vrow8.
    const int vrow8 = lane & 7;
    const int vdh   = lane >> 3;
    const int vcol  = (wid & 3) * 8 + vrow8;
    const int vchnk = wid >> 2;

    for (int kt = 0; kt < 16; kt++) {
        // --- V(kt) loads into registers ---
        float4 vr[4];
        {
            const float* vrow = Vb + (size_t)(kt * 64 + wid * 8 + vrow8) * D_ + vdh * 16;
#pragma unroll
            for (int j = 0; j < 4; j++)
                vr[j] = *reinterpret_cast<const float4*>(vrow + j * 4);
        }

        // --- wait S(kt); kbuf now free -> issue K(kt+1) load immediately ---
        MBAR_WAIT(mb_s, kt & 1);
        TCG_FENCE_AFTER();
        if (kt < 15) {
            load_k((kt + 1) * 64);
            CP_ASYNC_COMMIT();
        }

        // --- read S(kt) + exp (one 32-col LDTM per warp) ---
        uint32_t r0[32];
        TCG_LD_X32(r0, tmem + (kt & 1) * 64 + pr * 32);
        TCG_WAIT_LD();
        float p[32];
#pragma unroll
        for (int j = 0; j < 32; j++) {
            p[j] = tf32r(__expf(__uint_as_float(r0[j]) * scale));
            lpart += p[j];
        }

        // --- wait PV(kt-1) before overwriting P and Vt ---
        if (kt > 0) MBAR_WAIT(mb_pv, (kt - 1) & 1);

        // --- store P (tf32): row = sp*32+lane, key chunk pr ---
        {
            const int row = sp * 32 + lane;
#pragma unroll
            for (int jb = 0; jb < 8; jb++) {
                const uint32_t addr = pb + pr * 16384 + SWZ(row * 128 + jb * 16);
                float4 v4 = make_float4(p[jb * 4], p[jb * 4 + 1], p[jb * 4 + 2], p[jb * 4 + 3]);
                *reinterpret_cast<float4*>((char*)smem + (addr - su)) = v4;
            }
        }

        // --- store Vt(kt) transposed: Vt[d][key], chunk = key/32 ---
        {
            const uint32_t vdst = vtb + vchnk * 8192;
#pragma unroll
            for (int j = 0; j < 4; j++) {
                const int d = vdh * 16 + j * 4;
                float e0 = tf32r(vr[j].x), e1 = tf32r(vr[j].y),
                      e2 = tf32r(vr[j].z), e3 = tf32r(vr[j].w);
                *reinterpret_cast<float*>((char*)smem + (vdst + SWZ((d + 0) * 128 + vcol * 4) - su)) = e0;
                *reinterpret_cast<float*>((char*)smem + (vdst + SWZ((d + 1) * 128 + vcol * 4) - su)) = e1;
                *reinterpret_cast<float*>((char*)smem + (vdst + SWZ((d + 2) * 128 + vcol * 4) - su)) = e2;
                *reinterpret_cast<float*>((char*)smem + (vdst + SWZ((d + 3) * 128 + vcol * 4) - su)) = e3;
            }
        }

        // K(kt+1) completion (only group in flight), then rendezvous
        if (kt < 15) CP_ASYNC_WAIT(0);
        asm volatile("fence.proxy.async.shared::cta;" ::: "memory");
        __syncthreads();

        if (wid == 0 && elect_one()) {
            if (kt < 15) {   // S-MMA(kt+1) into the other slot
                const uint32_t dslot = tmem + ((kt + 1) & 1) * 64;
#pragma unroll
                for (int c = 0; c < 2; c++) {
                    const uint64_t adesc = make_desc_sw128(qb + c * 16384);
                    const uint64_t bdesc = make_desc_sw128(kbuf + c * 8192);
#pragma unroll
                    for (int ks = 0; ks < 4; ks++)
                        mma_ss_tf32(dslot, adesc + ks * 2, bdesc + ks * 2,
                                    id_64, (c > 0 || ks > 0) ? 1u : 0u);
                }
                TCG_COMMIT(mb_s);
            }
            // PV-MMA(kt): O += P x Vt (contraction over 64 keys, 8 k-steps)
            {
#pragma unroll
                for (int ks = 0; ks < 8; ks++) {
                    const int ch = ks >> 2;
                    const uint64_t adesc = make_desc_sw128(pb + ch * 16384) + (ks & 3) * 2;
                    const uint64_t bdesc = make_desc_sw128(vtb + ch * 8192) + (ks & 3) * 2;
                    mma_ss_tf32(TM_O, adesc, bdesc, id_64,
                                (kt > 0 || ks > 0) ? 1u : 0u);
                }
                TCG_COMMIT(mb_pv);
            }
        }
    }

    // combine row sums across column-halves
    s_l[pr][sp * 32 + lane] = lpart;
    __syncthreads();
    const int myrow = sp * 32 + lane;
    const float linv = 1.f / (s_l[0][myrow] + s_l[1][myrow]);

    // wait PV(15), read O, scale, transpose, coalesced store
    MBAR_WAIT(mb_pv, 15 & 1);
    TCG_FENCE_AFTER();
    {
        uint32_t r[32];
        TCG_LD_X32(r, TM_O + pr * 32);
        TCG_WAIT_LD();
        float* patch = reinterpret_cast<float*>(smem) + wid * (33 * 32);   // Q region reuse
        __syncthreads();   // all Q reads done long ago; ensure ordering vs patch writes
#pragma unroll
        for (int j = 0; j < 32; j++)
            patch[j * 33 + lane] = __uint_as_float(r[j]) * linv;
        __syncwarp();
        const int rbase = q0 + sp * 32;
        const int dcol  = pr * 32 + lane;
#pragma unroll
        for (int rr = 0; rr < 32; rr++) {
            O[((size_t)bh * L_ + rbase + rr) * D_ + dcol] = patch[lane * 33 + rr];
        }
    }

    TCG_FENCE_BEFORE();
    __syncthreads();
    if (wid == 0) { TCG_RELINQ(); TCG_DEALLOC(tmem, 256); }
#else
    (void)O;
#endif
}

// ---------------------------------------------------------------------------
// Kernel 2b: attention fallback (non-a pass), tf32 mma.sync (proven, 256 thr)
// ---------------------------------------------------------------------------
#define QP 68
#define VP 72
#define SM_Q  0
#define SM_P  (128 * QP)
#define SM_K  (2 * 128 * QP)
#define SM_V  (2 * 128 * QP + 64 * QP)
#define ATTN_SMEM_FLOATS (2 * 128 * QP + 64 * QP + 64 * VP)
#define ATTN_SMEM_BYTES  (ATTN_SMEM_FLOATS * 4)

__global__ __launch_bounds__(256, 2)
void attn_mma_kernel(float* __restrict__ O)
{
#ifndef TC_OK
    extern __shared__ float sm[];
    float* Qs = sm + SM_Q;
    float* Ps = sm + SM_P;
    float* Ks = sm + SM_K;
    float* Vs = sm + SM_V;

    const int bh = blockIdx.y;
    const int q0 = blockIdx.x * 128;
    const float* __restrict__ Qb = g_Q + (size_t)bh * L_ * D_;
    const float* __restrict__ Kb = g_K + (size_t)bh * L_ * D_;
    const float* __restrict__ Vb = g_V + (size_t)bh * L_ * D_;

    const int t    = threadIdx.x;
    const int lane = t & 31;
    const int wid  = t >> 5;
    const int gid  = lane >> 2;
    const int tig  = lane & 3;
    const int qb   = wid * 16;

#pragma unroll
    for (int u = 0; u < 8; u++) {
        const int g  = u * 256 + t;
        const int r  = g >> 4;
        const int c4 = (g & 15) * 4;
        float4 v = *reinterpret_cast<const float4*>(&Qb[(size_t)(q0 + r) * D_ + c4]);
        v.x = tf32r(v.x); v.y = tf32r(v.y); v.z = tf32r(v.z); v.w = tf32r(v.w);
        *reinterpret_cast<float4*>(&Qs[r * QP + c4]) = v;
    }

    float m_i[2] = {-CUDART_INF_F, -CUDART_INF_F};
    float l_i[2] = {0.f, 0.f};
    float o[8][4];
#pragma unroll
    for (int j = 0; j < 8; j++)
#pragma unroll
        for (int c = 0; c < 4; c++) o[j][c] = 0.f;

    for (int kt = 0; kt < L_ / 64; kt++) {
        __syncthreads();
        const int k0g = kt * 64;
#pragma unroll
        for (int u = 0; u < 4; u++) {
            const int g  = u * 256 + t;
            const int r  = g >> 4;
            const int c4 = (g & 15) * 4;
            float4 kv = *reinterpret_cast<const float4*>(&Kb[(size_t)(k0g + r) * D_ + c4]);
            float4 vv = *reinterpret_cast<const float4*>(&Vb[(size_t)(k0g + r) * D_ + c4]);
            kv.x = tf32r(kv.x); kv.y = tf32r(kv.y); kv.z = tf32r(kv.z); kv.w = tf32r(kv.w);
            vv.x = tf32r(vv.x); vv.y = tf32r(vv.y); vv.z = tf32r(vv.z); vv.w = tf32r(vv.w);
            *reinterpret_cast<float4*>(&Ks[r * QP + c4]) = kv;
            *reinterpret_cast<float4*>(&Vs[r * VP + c4]) = vv;
        }
        __syncthreads();

        float s[8][4];
#pragma unroll
        for (int j = 0; j < 8; j++)
#pragma unroll
            for (int c = 0; c < 4; c++) s[j][c] = 0.f;

#pragma unroll
        for (int ks = 0; ks < 8; ks++) {
            const int k = ks * 8;
            float a[4];
            a[0] = Qs[(qb + gid) * QP + k + tig];
            a[1] = Qs[(qb + gid + 8) * QP + k + tig];
            a[2] = Qs[(qb + gid) * QP + k + tig + 4];
            a[3] = Qs[(qb + gid + 8) * QP + k + tig + 4];
            float b[8][2];
#pragma unroll
            for (int jn = 0; jn < 8; jn++) {
                const int n = jn * 8;
                b[jn][0] = Ks[(n + gid) * QP + k + tig];
                b[jn][1] = Ks[(n + gid) * QP + k + tig + 4];
            }
#pragma unroll
            for (int jn = 0; jn < 8; jn++)
                mma_tf32(s[jn], a, b[jn]);
        }

        const float scale = 0.125f;
        float mt0 = -CUDART_INF_F, mt1 = -CUDART_INF_F;
#pragma unroll
        for (int jn = 0; jn < 8; jn++) {
            mt0 = fmaxf(mt0, fmaxf(s[jn][0], s[jn][1]));
            mt1 = fmaxf(mt1, fmaxf(s[jn][2], s[jn][3]));
        }
        mt0 *= scale; mt1 *= scale;
#pragma unroll
        for (int off = 1; off < 4; off <<= 1) {
            mt0 = fmaxf(mt0, __shfl_xor_sync(0xffffffffu, mt0, off));
            mt1 = fmaxf(mt1, __shfl_xor_sync(0xffffffffu, mt1, off));
        }
        const float mn0 = fmaxf(m_i[0], mt0);
        const float mn1 = fmaxf(m_i[1], mt1);
        const float cr0 = __expf(m_i[0] - mn0);
        const float cr1 = __expf(m_i[1] - mn1);
        float rs0 = 0.f, rs1 = 0.f;
#pragma unroll
        for (int jn = 0; jn < 8; jn++) {
            s[jn][0] = __expf(fmaf(s[jn][0], scale, -mn0));
            s[jn][1] = __expf(fmaf(s[jn][1], scale, -mn0));
            s[jn][2] = __expf(fmaf(s[jn][2], scale, -mn1));
            s[jn][3] = __expf(fmaf(s[jn][3], scale, -mn1));
            rs0 += s[jn][0] + s[jn][1];
            rs1 += s[jn][2] + s[jn][3];
        }
#pragma unroll
        for (int off = 1; off < 4; off <<= 1) {
            rs0 += __shfl_xor_sync(0xffffffffu, rs0, off);
            rs1 += __shfl_xor_sync(0xffffffffu, rs1, off);
        }
        l_i[0] = l_i[0] * cr0 + rs0;  m_i[0] = mn0;
        l_i[1] = l_i[1] * cr1 + rs1;  m_i[1] = mn1;
#pragma unroll
        for (int jn = 0; jn < 8; jn++) {
            o[jn][0] *= cr0; o[jn][1] *= cr0;
            o[jn][2] *= cr1; o[jn][3] *= cr1;
        }

#pragma unroll
        for (int jn = 0; jn < 8; jn++) {
            const int c = jn * 8 + 2 * tig;
            float2 p0, p1;
            p0.x = tf32r(s[jn][0]); p0.y = tf32r(s[jn][1]);
            p1.x = tf32r(s[jn][2]); p1.y = tf32r(s[jn][3]);
            *reinterpret_cast<float2*>(&Ps[(qb + gid) * QP + c]) = p0;
            *reinterpret_cast<float2*>(&Ps[(qb + gid + 8) * QP + c]) = p1;
        }
        __syncthreads();

#pragma unroll
        for (int ks = 0; ks < 8; ks++) {
            const int k = ks * 8;
            float a[4];
            a[0] = Ps[(qb + gid) * QP + k + tig];
            a[1] = Ps[(qb + gid + 8) * QP + k + tig];
            a[2] = Ps[(qb + gid) * QP + k + tig + 4];
            a[3] = Ps[(qb + gid + 8) * QP + k + tig + 4];
            float b[8][2];
#pragma unroll
            for (int jn = 0; jn < 8; jn++) {
                const int n = jn * 8;
                b[jn][0] = Vs[(k + tig) * VP + n + gid];
                b[jn][1] = Vs[(k + tig + 4) * VP + n + gid];
            }
#pragma unroll
            for (int jn = 0; jn < 8; jn++)
                mma_tf32(o[jn], a, b[jn]);
        }
    }

    const float inv0 = 1.f / l_i[0];
    const float inv1 = 1.f / l_i[1];
    const int r0 = q0 + qb + gid;
    const int r1 = r0 + 8;
#pragma unroll
    for (int jn = 0; jn < 8; jn++) {
        const int c = jn * 8 + 2 * tig;
        float2 v0, v1;
        v0.x = o[jn][0] * inv0; v0.y = o[jn][1] * inv0;
        v1.x = o[jn][2] * inv1; v1.y = o[jn][3] * inv1;
        *reinterpret_cast<float2*>(&O[((size_t)bh * L_ + r0) * D_ + c]) = v0;
        *reinterpret_cast<float2*>(&O[((size_t)bh * L_ + r1) * D_ + c]) = v1;
    }
#else
    (void)O;
#endif
}

// ---------------------------------------------------------------------------
extern "C" void kernel_launch(void* const* d_in, const int* in_sizes, int n_in,
                              void* d_out, int out_size)
{
    const float* x  = (const float*)d_in[0];
    const float* wq = (const float*)d_in[1];
    const float* bq = (const float*)d_in[2];
    const float* wk = (const float*)d_in[3];
    const float* bk = (const float*)d_in[4];
    const float* wv = (const float*)d_in[5];
    const float* bv = (const float*)d_in[6];
    float* out = (float*)d_out;

    cudaFuncSetAttribute(qkv_tc_kernel,
                         cudaFuncAttributeMaxDynamicSharedMemorySize, QKV_TC_SMEM);
    cudaFuncSetAttribute(qkv_mma2_kernel,
                         cudaFuncAttributeMaxDynamicSharedMemorySize, QKV_MMA_SMEM);
    cudaFuncSetAttribute(attn_tc_kernel,
                         cudaFuncAttributeMaxDynamicSharedMemorySize, ATTN_TC_SMEM);
    cudaFuncSetAttribute(attn_mma_kernel,
                         cudaFuncAttributeMaxDynamicSharedMemorySize, ATTN_SMEM_BYTES);

    // fused tf32(rna) rounding of X, Wq, Wk, Wv: exact grid
    const int total4 = NX4 + 3 * NW4;            // 2883584
    cvt_all_kernel<<<total4 / 256, 256>>>((const float4*)x, (const float4*)wq,
                                          (const float4*)wk, (const float4*)wv);

    // QKV: one of the two has a body per cubin
    dim3 tgrid(E_ / 256, M_ROWS / 256, 3);
    qkv_tc_kernel<<<tgrid, 256, QKV_TC_SMEM>>>(bq, bk, bv);
    dim3 fgrid(E_ / 128, M_ROWS / 128, 3);
    qkv_mma2_kernel<<<fgrid, 256, QKV_MMA_SMEM>>>(bq, bk, bv);

    // attention: same dual-variant scheme
    dim3 agrid(L_ / 128, B_ * H_);
    attn_tc_kernel<<<agrid, 256, ATTN_TC_SMEM>>>(out);
    attn_mma_kernel<<<agrid, 256, ATTN_SMEM_BYTES>>>(out);
}

// round 14
// speedup vs baseline: 1.6565x; 1.1167x over previous
#include <cuda_runtime.h>
#include <cuda_bf16.h>
#include <math_constants.h>
#include <stdint.h>

// ---------------------------------------------------------------------------
// Arch-variant gate: tcgen05 exists only in the sm_103a pass; the harness also
// builds compute_103 (non-a). Guarded kernels; host launches both variants,
// exactly one has a body per cubin.
// ---------------------------------------------------------------------------
#if defined(__CUDA_ARCH__)
#  if defined(__CUDA_ARCH_FEAT_SM103_ALL) || \
      (defined(__CUDA_ARCH_SPECIFIC__) && (__CUDA_ARCH_SPECIFIC__ == 1030))
#    define TC_OK 1
#  endif
#endif

// ---------------------------------------------------------------------------
#define B_   8
#define L_   1024
#define E_   1024
#define H_   16
#define D_   64
#define M_ROWS (B_ * L_)

__device__ float g_Q[B_ * H_ * L_ * D_];
__device__ float g_K[B_ * H_ * L_ * D_];
__device__ float g_V[B_ * H_ * L_ * D_];
__device__ float g_X[M_ROWS * E_];
__device__ float g_W[3 * E_ * E_];

// ---------------------------------------------------------------------------
// Common helpers
// ---------------------------------------------------------------------------
__device__ __forceinline__ float tf32r(float x) {
    uint32_t u;
    asm("cvt.rna.tf32.f32 %0, %1;" : "=r"(u) : "f"(x));
    return __uint_as_float(u);
}

__device__ __forceinline__ void mma_tf32(float c[4], const float a[4], const float b[2]) {
    asm volatile(
        "mma.sync.aligned.m16n8k8.row.col.f32.tf32.tf32.f32 "
        "{%0,%1,%2,%3}, {%4,%5,%6,%7}, {%8,%9}, {%0,%1,%2,%3};"
        : "+f"(c[0]), "+f"(c[1]), "+f"(c[2]), "+f"(c[3])
        : "r"(__float_as_uint(a[0])), "r"(__float_as_uint(a[1])),
          "r"(__float_as_uint(a[2])), "r"(__float_as_uint(a[3])),
          "r"(__float_as_uint(b[0])), "r"(__float_as_uint(b[1])));
}

#define CP_ASYNC_CG(dst, src) \
    asm volatile("cp.async.cg.shared.global [%0], [%1], 16;\n" :: "r"(dst), "l"(src))
#define CP_ASYNC_COMMIT() asm volatile("cp.async.commit_group;\n" ::: "memory")
#define CP_ASYNC_WAIT(n)  asm volatile("cp.async.wait_group %0;\n" :: "n"(n) : "memory")

__device__ __forceinline__ uint32_t smem_u32(const void* p) {
    uint32_t a;
    asm("{ .reg .u64 t; cvta.to.shared.u64 t, %1; cvt.u32.u64 %0, t; }" : "=r"(a) : "l"(p));
    return a;
}

#define SWZ(o) ((o) ^ (((o) >> 3) & 0x70))

// ---------------------------------------------------------------------------
// Kernel 0: fused fp32 -> tf32(rna) for X and all three W (single launch).
// ---------------------------------------------------------------------------
#define NX4 (M_ROWS * E_ / 4)     // 2097152
#define NW4 (E_ * E_ / 4)         // 262144

__global__ void cvt_all_kernel(const float4* __restrict__ x,
                               const float4* __restrict__ wq,
                               const float4* __restrict__ wk,
                               const float4* __restrict__ wv)
{
    const int i = blockIdx.x * blockDim.x + threadIdx.x;
    const float4* src;
    float4* dst;
    if (i < NX4) {
        src = x + i;
        dst = reinterpret_cast<float4*>(g_X) + i;
    } else {
        const int j = i - NX4;
        const int w = j >> 18;                 // NW4 == 1<<18
        const int r = j & (NW4 - 1);
        src = ((w == 0) ? wq : (w == 1) ? wk : wv) + r;
        dst = reinterpret_cast<float4*>(g_W) + j;
    }
    float4 v = *src;
    v.x = tf32r(v.x); v.y = tf32r(v.y); v.z = tf32r(v.z); v.w = tf32r(v.w);
    *dst = v;
}

// ---------------------------------------------------------------------------
// tcgen05 machinery (sm_103a pass only)
// ---------------------------------------------------------------------------
#ifdef TC_OK
__device__ __forceinline__ uint32_t elect_one() {
    uint32_t pred;
    asm volatile("{\n\t.reg .pred p;\n\telect.sync _|p, 0xFFFFFFFF;\n\t"
                 "selp.b32 %0, 1, 0, p;\n\t}" : "=r"(pred));
    return pred;
}

#define MBAR_INIT(a, c) \
    asm volatile("mbarrier.init.shared.b64 [%0], %1;" :: "r"(a), "r"(c) : "memory")
#define MBAR_WAIT(a, ph) do {                                                   \
    asm volatile("{\n\t.reg .pred P1;\n\t"                                      \
        "WAIT_LOOP_%=:\n\t"                                                     \
        "mbarrier.try_wait.parity.acquire.cta.shared::cta.b64 P1, [%0], %1, 0x989680;\n\t" \
        "@P1 bra.uni WAIT_DONE_%=;\n\t"                                         \
        "bra.uni WAIT_LOOP_%=;\n\t"                                             \
        "WAIT_DONE_%=:\n\t}"                                                    \
        :: "r"(a), "r"(ph) : "memory");                                         \
} while (0)

#define TCG_ALLOC(slot, n) \
    asm volatile("tcgen05.alloc.cta_group::1.sync.aligned.shared::cta.b32 [%0], %1;" \
                 :: "r"(slot), "r"((uint32_t)(n)) : "memory")
#define TCG_DEALLOC(t, n) \
    asm volatile("tcgen05.dealloc.cta_group::1.sync.aligned.b32 %0, %1;" :: "r"(t), "r"((uint32_t)(n)))
#define TCG_RELINQ() \
    asm volatile("tcgen05.relinquish_alloc_permit.cta_group::1.sync.aligned;")
#define TCG_COMMIT(mb) \
    asm volatile("tcgen05.commit.cta_group::1.mbarrier::arrive::one.shared::cluster.b64 [%0];" \
                 :: "r"(mb) : "memory")
#define TCG_FENCE_AFTER()  asm volatile("tcgen05.fence::after_thread_sync;" ::: "memory")
#define TCG_FENCE_BEFORE() asm volatile("tcgen05.fence::before_thread_sync;" ::: "memory")
#define TCG_WAIT_LD() asm volatile("tcgen05.wait::ld.sync.aligned;" ::: "memory")

#define TCG_LD_X32(r, addr)                                                      \
    asm volatile("tcgen05.ld.sync.aligned.32x32b.x32.b32 "                       \
        "{%0,%1,%2,%3,%4,%5,%6,%7,%8,%9,%10,%11,%12,%13,%14,%15,"               \
        "%16,%17,%18,%19,%20,%21,%22,%23,%24,%25,%26,%27,%28,%29,%30,%31}, [%32];" \
        : "=r"((r)[0]), "=r"((r)[1]), "=r"((r)[2]), "=r"((r)[3]),                \
          "=r"((r)[4]), "=r"((r)[5]), "=r"((r)[6]), "=r"((r)[7]),                \
          "=r"((r)[8]), "=r"((r)[9]), "=r"((r)[10]), "=r"((r)[11]),              \
          "=r"((r)[12]), "=r"((r)[13]), "=r"((r)[14]), "=r"((r)[15]),            \
          "=r"((r)[16]), "=r"((r)[17]), "=r"((r)[18]), "=r"((r)[19]),            \
          "=r"((r)[20]), "=r"((r)[21]), "=r"((r)[22]), "=r"((r)[23]),            \
          "=r"((r)[24]), "=r"((r)[25]), "=r"((r)[26]), "=r"((r)[27]),            \
          "=r"((r)[28]), "=r"((r)[29]), "=r"((r)[30]), "=r"((r)[31])             \
        : "r"(addr))

__device__ __forceinline__ uint64_t make_desc_sw128(uint32_t addr) {
    const uint64_t base = (uint64_t(2) << 61) | (uint64_t(1) << 46)
                        | (uint64_t(64) << 32) | (uint64_t(1) << 16);
    return base | ((uint64_t)(addr >> 4) & 0x3FFF);
}

// idesc kind::tf32: dtype F32@4, a/b TF32(2)@7/10, N/8@17, M/16@24
__device__ __forceinline__ uint32_t idesc_tf32(int n) {
    return (1u << 4) | (2u << 7) | (2u << 10) | (((uint32_t)n / 8) << 17) | (8u << 24);
}

__device__ __forceinline__ void mma_ss_tf32(uint32_t d, uint64_t a, uint64_t b,
                                            uint32_t idesc, uint32_t en) {
    asm volatile(
        "{\n\t.reg .pred p;\n\tsetp.ne.u32 p, %4, 0;\n\t"
        "tcgen05.mma.cta_group::1.kind::tf32 [%0], %1, %2, %3, {%5,%5,%5,%5}, p;\n\t}"
        :: "r"(d), "l"(a), "l"(b), "r"(idesc), "r"(en), "r"(0u) : "memory");
}
#endif  // TC_OK

// ---------------------------------------------------------------------------
// Kernel 1a: QKV projection on tcgen05 (sm_103a pass).  BM=256 x BN=256, BK=32.
// (verbatim R8 — proven; permit relinquished right after alloc)
// ---------------------------------------------------------------------------
#define NSTAGE 3
#define STAGE_BYTES 65536
#define QKV_TC_SMEM (NSTAGE * STAGE_BYTES)

__global__ __launch_bounds__(256, 1)
void qkv_tc_kernel(const float* __restrict__ bq,
                   const float* __restrict__ bk,
                   const float* __restrict__ bv)
{
#ifdef TC_OK
    extern __shared__ __align__(1024) char smem[];
    __shared__ uint32_t s_tmem;
    __shared__ __align__(8) uint64_t s_mbar[NSTAGE];

    const int t    = threadIdx.x;
    const int wid  = t >> 5;
    const int lane = t & 31;
    const int z    = blockIdx.z;
    const int m0   = blockIdx.y * 256;
    const int n0   = blockIdx.x * 256;

    const float* __restrict__ Wz   = g_W + (size_t)z * E_ * E_;
    const float* __restrict__ bias = (z == 0) ? bq : (z == 1) ? bk : bv;
    float* __restrict__ out        = (z == 0) ? g_Q : (z == 1) ? g_K : g_V;

    const uint32_t smem_u = smem_u32(smem);

    if (wid == 0) {
        TCG_ALLOC(smem_u32(&s_tmem), 512);
        TCG_RELINQ();              // release the SM-wide alloc permit immediately
    }
    if (t == 0) {
#pragma unroll
        for (int s = 0; s < NSTAGE; s++) MBAR_INIT(smem_u32(&s_mbar[s]), 1);
    }
    __syncthreads();
    const uint32_t tmem = s_tmem;

    uint32_t phbits = 0;
    const uint32_t idq = idesc_tf32(256);

    for (int kt = 0; kt < 34; kt++) {
        if (kt < 32) {
            const int s = kt % 3;
            const int k0 = kt * 32;
            const uint32_t stg = smem_u + (uint32_t)s * STAGE_BYTES;
            if (kt >= 3) {
                MBAR_WAIT(smem_u32(&s_mbar[s]), (phbits >> s) & 1u);
                phbits ^= (1u << s);
            }
#pragma unroll
            for (int u = 0; u < 16; u++) {
                const int f = u * 256 + t;
                const float* src;
                uint32_t dst;
                if (u < 8) {
                    const int ti  = u >> 2;
                    const int fa  = f & 1023;
                    const int row = fa >> 3;
                    const int c   = fa & 7;
                    src = g_X + (size_t)(m0 + ti * 128 + row) * E_ + k0 + c * 4;
                    dst = stg + ti * 16384 + SWZ(row * 128 + c * 16);
                } else {
                    const int fb  = f - 2048;
                    const int row = fb >> 3;
                    const int c   = fb & 7;
                    src = Wz + (size_t)(n0 + row) * E_ + k0 + c * 4;
                    dst = stg + 32768 + SWZ(row * 128 + c * 16);
                }
                CP_ASYNC_CG(dst, src);
            }
            CP_ASYNC_COMMIT();
        }
        if (kt >= 2) {
            const int c  = kt - 2;
            const int sc = c % 3;
            if (kt < 32)       { CP_ASYNC_WAIT(2); }
            else if (kt == 32) { CP_ASYNC_WAIT(1); }
            else               { CP_ASYNC_WAIT(0); }
            asm volatile("fence.proxy.async.shared::cta;" ::: "memory");
            __syncthreads();
            if (wid == 0 && elect_one()) {
                const uint32_t stc = smem_u + (uint32_t)sc * STAGE_BYTES;
                const uint64_t bdesc = make_desc_sw128(stc + 32768);
#pragma unroll
                for (int ti = 0; ti < 2; ti++) {
                    const uint64_t adesc = make_desc_sw128(stc + ti * 16384);
#pragma unroll
                    for (int ks = 0; ks < 4; ks++) {
                        mma_ss_tf32(tmem + ti * 256, adesc + ks * 2, bdesc + ks * 2,
                                    idq, (c > 0 || ks > 0) ? 1u : 0u);
                    }
                }
                TCG_COMMIT(smem_u32(&s_mbar[sc]));
            }
        }
    }

    MBAR_WAIT(smem_u32(&s_mbar[1]), (phbits >> 1) & 1u);
    TCG_FENCE_AFTER();
    __syncthreads();

    // epilogue: LDTM -> smem transpose -> tf32r(bias add) -> coalesced scatter
    {
        const int ti = wid >> 2;
        const int sp = wid & 3;
        float* patch = reinterpret_cast<float*>(smem) + wid * (33 * 32);
        const int mr_base = m0 + ti * 128 + sp * 32;
#pragma unroll
        for (int cb = 0; cb < 8; cb++) {
            const int nb  = n0 + cb * 32;
            const int h   = nb >> 6;
            const int dd0 = nb & 63;
            const float bl = bias[nb + lane];
            uint32_t r[32];
            TCG_LD_X32(r, tmem + ti * 256 + cb * 32);
            TCG_WAIT_LD();
#pragma unroll
            for (int j = 0; j < 32; j++) patch[j * 33 + lane] = __uint_as_float(r[j]);
            __syncwarp();
#pragma unroll
            for (int rr = 0; rr < 32; rr++) {
                const int m = mr_base + rr;
                const int b = m >> 10;
                const int l = m & 1023;
                out[(((size_t)(b * H_ + h)) * L_ + l) * D_ + dd0 + lane] =
                    tf32r(patch[lane * 33 + rr] + bl);
            }
            __syncwarp();
        }
    }

    TCG_FENCE_BEFORE();
    __syncthreads();
    if (wid == 0) { TCG_DEALLOC(tmem, 512); }
#else
    (void)bq; (void)bk; (void)bv;
#endif
}

// ---------------------------------------------------------------------------
// Kernel 1b: QKV fallback (non-a pass), mma.sync + cp.async (proven)
// ---------------------------------------------------------------------------
#define BK 32
#define STG_FLOATS (2 * 128 * BK)
#define STG_BYTES  (STG_FLOATS * 4)
#define NST 3
#define QKV_MMA_SMEM (NST * STG_BYTES)

__global__ __launch_bounds__(256, 2)
void qkv_mma2_kernel(const float* __restrict__ bq,
                     const float* __restrict__ bk,
                     const float* __restrict__ bv)
{
#ifndef TC_OK
    extern __shared__ __align__(128) float smemf[];

    const int t    = threadIdx.x;
    const int lane = t & 31;
    const int wid  = t >> 5;
    const int gid  = lane >> 2;
    const int tig  = lane & 3;
    const int wm   = (wid >> 1) * 32;
    const int wn   = (wid & 1) * 64;
    const int z    = blockIdx.z;
    const int m0   = blockIdx.y * 128;
    const int n0   = blockIdx.x * 128;

    const float* __restrict__ Wz   = g_W + (size_t)z * E_ * E_;
    const float* __restrict__ bias = (z == 0) ? bq : (z == 1) ? bk : bv;
    float* __restrict__ out        = (z == 0) ? g_Q : (z == 1) ? g_K : g_V;

    const uint32_t smem_b = smem_u32(smemf);
    const int lrow_base = t >> 3;
    const int lc        = (t & 7) * 16;

    float acc[2][8][4];
#pragma unroll
    for (int i = 0; i < 2; i++)
#pragma unroll
        for (int j = 0; j < 8; j++)
#pragma unroll
            for (int c = 0; c < 4; c++) acc[i][j][c] = 0.f;

    auto issue = [&](int kt, int s) {
        const uint32_t stg = smem_b + (uint32_t)s * STG_BYTES;
        const int k0 = kt * BK;
#pragma unroll
        for (int u = 0; u < 4; u++) {
            const int row = lrow_base + u * 32;
            const uint32_t sw = (uint32_t)(lc ^ ((row & 7) << 4));
            const uint32_t da = stg + (uint32_t)row * 128 + sw;
            const uint32_t db = da + 16384;
            const float* sa = g_X + (size_t)(m0 + row) * E_ + k0 + (lc >> 2);
            const float* sb = Wz  + (size_t)(n0 + row) * E_ + k0 + (lc >> 2);
            CP_ASYNC_CG(da, sa);
            CP_ASYNC_CG(db, sb);
        }
        CP_ASYNC_COMMIT();
    };

    issue(0, 0); issue(1, 1); issue(2, 2);
    const int x0 = 4 * gid;

    for (int kt = 0; kt < 32; kt++) {
        const int s = kt % 3;
        CP_ASYNC_WAIT(2);
        __syncthreads();
        const float* sA = smemf + (size_t)s * STG_FLOATS;
        const float* sB = sA + 4096;
#pragma unroll
        for (int ks = 0; ks < 4; ks++) {
            const int k  = ks * 8;
            const int c0 = (k + tig) ^ x0;
            const int c1 = (k + tig + 4) ^ x0;
            float a[2][4];
#pragma unroll
            for (int im = 0; im < 2; im++) {
                const int r0 = wm + im * 16 + gid;
                a[im][0] = sA[r0 * 32 + c0];
                a[im][1] = sA[(r0 + 8) * 32 + c0];
                a[im][2] = sA[r0 * 32 + c1];
                a[im][3] = sA[(r0 + 8) * 32 + c1];
            }
            float b[8][2];
#pragma unroll
            for (int jn = 0; jn < 8; jn++) {
                const int rn = wn + jn * 8 + gid;
                b[jn][0] = sB[rn * 32 + c0];
                b[jn][1] = sB[rn * 32 + c1];
            }
#pragma unroll
            for (int im = 0; im < 2; im++)
#pragma unroll
                for (int jn = 0; jn < 8; jn++)
                    mma_tf32(acc[im][jn], a[im], b[jn]);
        }
        __syncthreads();
        if (kt + 3 < 32) issue(kt + 3, s);
    }

#pragma unroll
    for (int im = 0; im < 2; im++) {
        const int mr = m0 + wm + im * 16 + gid;
        const int b0r = mr >> 10, l0r = mr & 1023;
        const int b1r = (mr + 8) >> 10, l1r = (mr + 8) & 1023;
#pragma unroll
        for (int jn = 0; jn < 8; jn++) {
            const int n  = n0 + wn + jn * 8 + 2 * tig;
            const int h  = n >> 6;
            const int dd = n & 63;
            const float bi0 = bias[n], bi1 = bias[n + 1];
            float2 v0, v1;
            v0.x = acc[im][jn][0] + bi0; v0.y = acc[im][jn][1] + bi1;
            v1.x = acc[im][jn][2] + bi0; v1.y = acc[im][jn][3] + bi1;
            *reinterpret_cast<float2*>(
                &out[(((size_t)(b0r * H_ + h)) * L_ + l0r) * D_ + dd]) = v0;
            *reinterpret_cast<float2*>(
                &out[(((size_t)(b1r * H_ + h)) * L_ + l1r) * D_ + dd]) = v1;
        }
    }
#else
    (void)bq; (void)bk; (void)bv;
#endif
}

// ---------------------------------------------------------------------------
// Kernel 2a: attention on tcgen05 (sm_103a pass), 2-CTA/SM variant.
// Identical to R11's passing kernel EXCEPT: the alloc permit is relinquished
// immediately after tcgen05.alloc so a co-resident CTA can also allocate.
// SMEM: Q 32K @0 | K 16K @32768 | Vt 16K @49152 | P 32K @65536 = 96K.
// TMEM (alloc 256): S slots @0,@64 (64 cols each) | O @128 (64 cols).
// ---------------------------------------------------------------------------
#define AQ_OFF   0
#define AK_OFF   32768
#define AVT_OFF  49152
#define AP_OFF   65536
#define ATTN_TC_SMEM 98304

__global__ __launch_bounds__(256, 2)
void attn_tc_kernel(float* __restrict__ O)
{
#ifdef TC_OK
    extern __shared__ __align__(1024) char smem[];
    __shared__ uint32_t s_tmem;
    __shared__ __align__(8) uint64_t s_mbar_s, s_mbar_pv;
    __shared__ float s_l[2][128];

    const int t    = threadIdx.x;
    const int wid  = t >> 5;
    const int lane = t & 31;
    const int pr   = wid >> 2;          // column-half (0: cols 0-31, 1: 32-63)
    const int sp   = wid & 3;           // TMEM subpartition -> rows sp*32..+31
    const int bh   = blockIdx.y;
    const int q0   = blockIdx.x * 128;

    const float* __restrict__ Qb = g_Q + (size_t)bh * L_ * D_;
    const float* __restrict__ Kb = g_K + (size_t)bh * L_ * D_;
    const float* __restrict__ Vb = g_V + (size_t)bh * L_ * D_;

    const uint32_t su   = smem_u32(smem);
    const uint32_t qb   = su + AQ_OFF;
    const uint32_t kbuf = su + AK_OFF;
    const uint32_t vtb  = su + AVT_OFF;
    const uint32_t pb   = su + AP_OFF;

    if (wid == 0) {
        TCG_ALLOC(smem_u32(&s_tmem), 256);
        TCG_RELINQ();              // release the SM-wide alloc permit immediately
    }
    if (t == 0) {
        MBAR_INIT(smem_u32(&s_mbar_s), 1);
        MBAR_INIT(smem_u32(&s_mbar_pv), 1);
    }
    __syncthreads();
    const uint32_t tmem = s_tmem;
    const uint32_t TM_O = tmem + 128;
    const uint32_t mb_s  = smem_u32(&s_mbar_s);
    const uint32_t mb_pv = smem_u32(&s_mbar_pv);

    // Q loader: 128 rows x 64 tf32 (2 chunks of 128B rows), 8 float4/thread
    auto load_q = [&]() {
#pragma unroll
        for (int c = 0; c < 2; c++) {
#pragma unroll
            for (int u = 0; u < 4; u++) {
                const int f   = u * 256 + t;
                const int row = f >> 3;
                const int cg  = f & 7;
                const float* src = Qb + (size_t)(q0 + row) * D_ + c * 32 + cg * 4;
                CP_ASYNC_CG(qb + c * 16384 + SWZ(row * 128 + cg * 16), src);
            }
        }
    };
    // K loader: 64 rows x 64 tf32 (2 chunks of 8KB), 2 float4/thread
    auto load_k = [&](int row0) {
#pragma unroll
        for (int c = 0; c < 2; c++) {
#pragma unroll
            for (int u = 0; u < 2; u++) {
                const int g   = u * 256 + t;
                const int row = g >> 3;
                const int cg  = g & 7;
                const float* src = Kb + (size_t)(row0 + row) * D_ + c * 32 + cg * 4;
                CP_ASYNC_CG(kbuf + c * 8192 + SWZ(row * 128 + cg * 16), src);
            }
        }
    };

    // prologue: Q + K0
    load_q();
    load_k(0);
    CP_ASYNC_COMMIT();
    CP_ASYNC_WAIT(0);
    asm volatile("fence.proxy.async.shared::cta;" ::: "memory");
    __syncthreads();

    const uint32_t id_64 = idesc_tf32(64);

    // S-MMA(0)
    if (wid == 0 && elect_one()) {
#pragma unroll
        for (int c = 0; c < 2; c++) {
            const uint64_t adesc = make_desc_sw128(qb + c * 16384);
            const uint64_t bdesc = make_desc_sw128(kbuf + c * 8192);
#pragma unroll
            for (int ks = 0; ks < 4; ks++)
                mma_ss_tf32(tmem, adesc + ks * 2, bdesc + ks * 2,
                            id_64, (c > 0 || ks > 0) ? 1u : 0u);
        }
        TCG_COMMIT(mb_s);
    }

    float lpart = 0.f;
    const float scale = 0.125f;
    // V mapping: warp handles keys [wid*8, wid*8+8); lane: vrow8 = lane&7,
    // vdh = lane>>3 covers d-group of 16. Vt chunk = wid>>2 (keys 32/chunk),
    // col within chunk = (wid&3)*8 + vrow8.
    const int vrow8 = lane & 7;
    const int vdh   = lane >> 3;
    const int vcol  = (wid & 3) * 8 + vrow8;
    const int vchnk = wid >> 2;

    for (int kt = 0; kt < 16; kt++) {
        // --- V(kt) loads into registers ---
        float4 vr[4];
        {
            const float* vrow = Vb + (size_t)(kt * 64 + wid * 8 + vrow8) * D_ + vdh * 16;
#pragma unroll
            for (int j = 0; j < 4; j++)
                vr[j] = *reinterpret_cast<const float4*>(vrow + j * 4);
        }

        // --- wait S(kt); kbuf now free -> issue K(kt+1) load immediately ---
        MBAR_WAIT(mb_s, kt & 1);
        TCG_FENCE_AFTER();
        if (kt < 15) {
            load_k((kt + 1) * 64);
            CP_ASYNC_COMMIT();
        }

        // --- read S(kt) + exp (one 32-col LDTM per warp) ---
        uint32_t r0[32];
        TCG_LD_X32(r0, tmem + (kt & 1) * 64 + pr * 32);
        TCG_WAIT_LD();
        float p[32];
#pragma unroll
        for (int j = 0; j < 32; j++) {
            p[j] = tf32r(__expf(__uint_as_float(r0[j]) * scale));
            lpart += p[j];
        }

        // --- wait PV(kt-1) before overwriting P and Vt ---
        if (kt > 0) MBAR_WAIT(mb_pv, (kt - 1) & 1);

        // --- store P (tf32): row = sp*32+lane, key chunk pr ---
        {
            const int row = sp * 32 + lane;
#pragma unroll
            for (int jb = 0; jb < 8; jb++) {
                const uint32_t addr = pb + pr * 16384 + SWZ(row * 128 + jb * 16);
                float4 v4 = make_float4(p[jb * 4], p[jb * 4 + 1], p[jb * 4 + 2], p[jb * 4 + 3]);
                *reinterpret_cast<float4*>((char*)smem + (addr - su)) = v4;
            }
        }

        // --- store Vt(kt) transposed: Vt[d][key], chunk = key/32 ---
        {
            const uint32_t vdst = vtb + vchnk * 8192;
#pragma unroll
            for (int j = 0; j < 4; j++) {
                const int d = vdh * 16 + j * 4;
                float e0 = tf32r(vr[j].x), e1 = tf32r(vr[j].y),
                      e2 = tf32r(vr[j].z), e3 = tf32r(vr[j].w);
                *reinterpret_cast<float*>((char*)smem + (vdst + SWZ((d + 0) * 128 + vcol * 4) - su)) = e0;
                *reinterpret_cast<float*>((char*)smem + (vdst + SWZ((d + 1) * 128 + vcol * 4) - su)) = e1;
                *reinterpret_cast<float*>((char*)smem + (vdst + SWZ((d + 2) * 128 + vcol * 4) - su)) = e2;
                *reinterpret_cast<float*>((char*)smem + (vdst + SWZ((d + 3) * 128 + vcol * 4) - su)) = e3;
            }
        }

        // K(kt+1) completion (only group in flight), then rendezvous
        if (kt < 15) CP_ASYNC_WAIT(0);
        asm volatile("fence.proxy.async.shared::cta;" ::: "memory");
        __syncthreads();

        if (wid == 0 && elect_one()) {
            if (kt < 15) {   // S-MMA(kt+1) into the other slot
                const uint32_t dslot = tmem + ((kt + 1) & 1) * 64;
#pragma unroll
                for (int c = 0; c < 2; c++) {
                    const uint64_t adesc = make_desc_sw128(qb + c * 16384);
                    const uint64_t bdesc = make_desc_sw128(kbuf + c * 8192);
#pragma unroll
                    for (int ks = 0; ks < 4; ks++)
                        mma_ss_tf32(dslot, adesc + ks * 2, bdesc + ks * 2,
                                    id_64, (c > 0 || ks > 0) ? 1u : 0u);
                }
                TCG_COMMIT(mb_s);
            }
            // PV-MMA(kt): O += P x Vt (contraction over 64 keys, 8 k-steps)
            {
#pragma unroll
                for (int ks = 0; ks < 8; ks++) {
                    const int ch = ks >> 2;
                    const uint64_t adesc = make_desc_sw128(pb + ch * 16384) + (ks & 3) * 2;
                    const uint64_t bdesc = make_desc_sw128(vtb + ch * 8192) + (ks & 3) * 2;
                    mma_ss_tf32(TM_O, adesc, bdesc, id_64,
                                (kt > 0 || ks > 0) ? 1u : 0u);
                }
                TCG_COMMIT(mb_pv);
            }
        }
    }

    // combine row sums across column-halves
    s_l[pr][sp * 32 + lane] = lpart;
    __syncthreads();
    const int myrow = sp * 32 + lane;
    const float linv = 1.f / (s_l[0][myrow] + s_l[1][myrow]);

    // wait PV(15), read O, scale, transpose, coalesced store
    MBAR_WAIT(mb_pv, 15 & 1);
    TCG_FENCE_AFTER();
    {
        uint32_t r[32];
        TCG_LD_X32(r, TM_O + pr * 32);
        TCG_WAIT_LD();
        float* patch = reinterpret_cast<float*>(smem) + wid * (33 * 32);   // Q region reuse
        __syncthreads();
#pragma unroll
        for (int j = 0; j < 32; j++)
            patch[j * 33 + lane] = __uint_as_float(r[j]) * linv;
        __syncwarp();
        const int rbase = q0 + sp * 32;
        const int dcol  = pr * 32 + lane;
#pragma unroll
        for (int rr = 0; rr < 32; rr++) {
            O[((size_t)bh * L_ + rbase + rr) * D_ + dcol] = patch[lane * 33 + rr];
        }
    }

    TCG_FENCE_BEFORE();
    __syncthreads();
    if (wid == 0) { TCG_DEALLOC(tmem, 256); }
#else
    (void)O;
#endif
}

// ---------------------------------------------------------------------------
// Kernel 2b: attention fallback (non-a pass), tf32 mma.sync (proven, 256 thr)
// ---------------------------------------------------------------------------
#define QP 68
#define VP 72
#define SM_Q  0
#define SM_P  (128 * QP)
#define SM_K  (2 * 128 * QP)
#define SM_V  (2 * 128 * QP + 64 * QP)
#define ATTN_SMEM_FLOATS (2 * 128 * QP + 64 * QP + 64 * VP)
#define ATTN_SMEM_BYTES  (ATTN_SMEM_FLOATS * 4)

__global__ __launch_bounds__(256, 2)
void attn_mma_kernel(float* __restrict__ O)
{
#ifndef TC_OK
    extern __shared__ float sm[];
    float* Qs = sm + SM_Q;
    float* Ps = sm + SM_P;
    float* Ks = sm + SM_K;
    float* Vs = sm + SM_V;

    const int bh = blockIdx.y;
    const int q0 = blockIdx.x * 128;
    const float* __restrict__ Qb = g_Q + (size_t)bh * L_ * D_;
    const float* __restrict__ Kb = g_K + (size_t)bh * L_ * D_;
    const float* __restrict__ Vb = g_V + (size_t)bh * L_ * D_;

    const int t    = threadIdx.x;
    const int lane = t & 31;
    const int wid  = t >> 5;
    const int gid  = lane >> 2;
    const int tig  = lane & 3;
    const int qb   = wid * 16;

#pragma unroll
    for (int u = 0; u < 8; u++) {
        const int g  = u * 256 + t;
        const int r  = g >> 4;
        const int c4 = (g & 15) * 4;
        float4 v = *reinterpret_cast<const float4*>(&Qb[(size_t)(q0 + r) * D_ + c4]);
        v.x = tf32r(v.x); v.y = tf32r(v.y); v.z = tf32r(v.z); v.w = tf32r(v.w);
        *reinterpret_cast<float4*>(&Qs[r * QP + c4]) = v;
    }

    float m_i[2] = {-CUDART_INF_F, -CUDART_INF_F};
    float l_i[2] = {0.f, 0.f};
    float o[8][4];
#pragma unroll
    for (int j = 0; j < 8; j++)
#pragma unroll
        for (int c = 0; c < 4; c++) o[j][c] = 0.f;

    for (int kt = 0; kt < L_ / 64; kt++) {
        __syncthreads();
        const int k0g = kt * 64;
#pragma unroll
        for (int u = 0; u < 4; u++) {
            const int g  = u * 256 + t;
            const int r  = g >> 4;
            const int c4 = (g & 15) * 4;
            float4 kv = *reinterpret_cast<const float4*>(&Kb[(size_t)(k0g + r) * D_ + c4]);
            float4 vv = *reinterpret_cast<const float4*>(&Vb[(size_t)(k0g + r) * D_ + c4]);
            kv.x = tf32r(kv.x); kv.y = tf32r(kv.y); kv.z = tf32r(kv.z); kv.w = tf32r(kv.w);
            vv.x = tf32r(vv.x); vv.y = tf32r(vv.y); vv.z = tf32r(vv.z); vv.w = tf32r(vv.w);
            *reinterpret_cast<float4*>(&Ks[r * QP + c4]) = kv;
            *reinterpret_cast<float4*>(&Vs[r * VP + c4]) = vv;
        }
        __syncthreads();

        float s[8][4];
#pragma unroll
        for (int j = 0; j < 8; j++)
#pragma unroll
            for (int c = 0; c < 4; c++) s[j][c] = 0.f;

#pragma unroll
        for (int ks = 0; ks < 8; ks++) {
            const int k = ks * 8;
            float a[4];
            a[0] = Qs[(qb + gid) * QP + k + tig];
            a[1] = Qs[(qb + gid + 8) * QP + k + tig];
            a[2] = Qs[(qb + gid) * QP + k + tig + 4];
            a[3] = Qs[(qb + gid + 8) * QP + k + tig + 4];
            float b[8][2];
#pragma unroll
            for (int jn = 0; jn < 8; jn++) {
                const int n = jn * 8;
                b[jn][0] = Ks[(n + gid) * QP + k + tig];
                b[jn][1] = Ks[(n + gid) * QP + k + tig + 4];
            }
#pragma unroll
            for (int jn = 0; jn < 8; jn++)
                mma_tf32(s[jn], a, b[jn]);
        }

        const float scale = 0.125f;
        float mt0 = -CUDART_INF_F, mt1 = -CUDART_INF_F;
#pragma unroll
        for (int jn = 0; jn < 8; jn++) {
            mt0 = fmaxf(mt0, fmaxf(s[jn][0], s[jn][1]));
            mt1 = fmaxf(mt1, fmaxf(s[jn][2], s[jn][3]));
        }
        mt0 *= scale; mt1 *= scale;
#pragma unroll
        for (int off = 1; off < 4; off <<= 1) {
            mt0 = fmaxf(mt0, __shfl_xor_sync(0xffffffffu, mt0, off));
            mt1 = fmaxf(mt1, __shfl_xor_sync(0xffffffffu, mt1, off));
        }
        const float mn0 = fmaxf(m_i[0], mt0);
        const float mn1 = fmaxf(m_i[1], mt1);
        const float cr0 = __expf(m_i[0] - mn0);
        const float cr1 = __expf(m_i[1] - mn1);
        float rs0 = 0.f, rs1 = 0.f;
#pragma unroll
        for (int jn = 0; jn < 8; jn++) {
            s[jn][0] = __expf(fmaf(s[jn][0], scale, -mn0));
            s[jn][1] = __expf(fmaf(s[jn][1], scale, -mn0));
            s[jn][2] = __expf(fmaf(s[jn][2], scale, -mn1));
            s[jn][3] = __expf(fmaf(s[jn][3], scale, -mn1));
            rs0 += s[jn][0] + s[jn][1];
            rs1 += s[jn][2] + s[jn][3];
        }
#pragma unroll
        for (int off = 1; off < 4; off <<= 1) {
            rs0 += __shfl_xor_sync(0xffffffffu, rs0, off);
            rs1 += __shfl_xor_sync(0xffffffffu, rs1, off);
        }
        l_i[0] = l_i[0] * cr0 + rs0;  m_i[0] = mn0;
        l_i[1] = l_i[1] * cr1 + rs1;  m_i[1] = mn1;
#pragma unroll
        for (int jn = 0; jn < 8; jn++) {
            o[jn][0] *= cr0; o[jn][1] *= cr0;
            o[jn][2] *= cr1; o[jn][3] *= cr1;
        }

#pragma unroll
        for (int jn = 0; jn < 8; jn++) {
            const int c = jn * 8 + 2 * tig;
            float2 p0, p1;
            p0.x = tf32r(s[jn][0]); p0.y = tf32r(s[jn][1]);
            p1.x = tf32r(s[jn][2]); p1.y = tf32r(s[jn][3]);
            *reinterpret_cast<float2*>(&Ps[(qb + gid) * QP + c]) = p0;
            *reinterpret_cast<float2*>(&Ps[(qb + gid + 8) * QP + c]) = p1;
        }
        __syncthreads();

#pragma unroll
        for (int ks = 0; ks < 8; ks++) {
            const int k = ks * 8;
            float a[4];
            a[0] = Ps[(qb + gid) * QP + k + tig];
            a[1] = Ps[(qb + gid + 8) * QP + k + tig];
            a[2] = Ps[(qb + gid) * QP + k + tig + 4];
            a[3] = Ps[(qb + gid + 8) * QP + k + tig + 4];
            float b[8][2];
#pragma unroll
            for (int jn = 0; jn < 8; jn++) {
                const int n = jn * 8;
                b[jn][0] = Vs[(k + tig) * VP + n + gid];
                b[jn][1] = Vs[(k + tig + 4) * VP + n + gid];
            }
#pragma unroll
            for (int jn = 0; jn < 8; jn++)
                mma_tf32(o[jn], a, b[jn]);
        }
    }

    const float inv0 = 1.f / l_i[0];
    const float inv1 = 1.f / l_i[1];
    const int r0 = q0 + qb + gid;
    const int r1 = r0 + 8;
#pragma unroll
    for (int jn = 0; jn < 8; jn++) {
        const int c = jn * 8 + 2 * tig;
        float2 v0, v1;
        v0.x = o[jn][0] * inv0; v0.y = o[jn][1] * inv0;
        v1.x = o[jn][2] * inv1; v1.y = o[jn][3] * inv1;
        *reinterpret_cast<float2*>(&O[((size_t)bh * L_ + r0) * D_ + c]) = v0;
        *reinterpret_cast<float2*>(&O[((size_t)bh * L_ + r1) * D_ + c]) = v1;
    }
#else
    (void)O;
#endif
}

// ---------------------------------------------------------------------------
extern "C" void kernel_launch(void* const* d_in, const int* in_sizes, int n_in,
                              void* d_out, int out_size)
{
    const float* x  = (const float*)d_in[0];
    const float* wq = (const float*)d_in[1];
    const float* bq = (const float*)d_in[2];
    const float* wk = (const float*)d_in[3];
    const float* bk = (const float*)d_in[4];
    const float* wv = (const float*)d_in[5];
    const float* bv = (const float*)d_in[6];
    float* out = (float*)d_out;

    cudaFuncSetAttribute(qkv_tc_kernel,
                         cudaFuncAttributeMaxDynamicSharedMemorySize, QKV_TC_SMEM);
    cudaFuncSetAttribute(qkv_mma2_kernel,
                         cudaFuncAttributeMaxDynamicSharedMemorySize, QKV_MMA_SMEM);
    cudaFuncSetAttribute(attn_tc_kernel,
                         cudaFuncAttributeMaxDynamicSharedMemorySize, ATTN_TC_SMEM);
    cudaFuncSetAttribute(attn_mma_kernel,
                         cudaFuncAttributeMaxDynamicSharedMemorySize, ATTN_SMEM_BYTES);

    // fused tf32(rna) rounding of X, Wq, Wk, Wv: exact grid
    const int total4 = NX4 + 3 * NW4;            // 2883584
    cvt_all_kernel<<<total4 / 256, 256>>>((const float4*)x, (const float4*)wq,
                                          (const float4*)wk, (const float4*)wv);

    // QKV: one of the two has a body per cubin
    dim3 tgrid(E_ / 256, M_ROWS / 256, 3);
    qkv_tc_kernel<<<tgrid, 256, QKV_TC_SMEM>>>(bq, bk, bv);
    dim3 fgrid(E_ / 128, M_ROWS / 128, 3);
    qkv_mma2_kernel<<<fgrid, 256, QKV_MMA_SMEM>>>(bq, bk, bv);

    // attention: same dual-variant scheme
    dim3 agrid(L_ / 128, B_ * H_);
    attn_tc_kernel<<<agrid, 256, ATTN_TC_SMEM>>>(out);
    attn_mma_kernel<<<agrid, 256, ATTN_SMEM_BYTES>>>(out);
}

// round 15
// speedup vs baseline: 1.6574x; 1.0006x over previous
#include <cuda_runtime.h>
#include <cuda_bf16.h>
#include <math_constants.h>
#include <stdint.h>

// ---------------------------------------------------------------------------
// Arch-variant gate: tcgen05 exists only in the sm_103a pass; the harness also
// builds compute_103 (non-a). Guarded kernels; host launches both variants,
// exactly one has a body per cubin.
// ---------------------------------------------------------------------------
#if defined(__CUDA_ARCH__)
#  if defined(__CUDA_ARCH_FEAT_SM103_ALL) || \
      (defined(__CUDA_ARCH_SPECIFIC__) && (__CUDA_ARCH_SPECIFIC__ == 1030))
#    define TC_OK 1
#  endif
#endif

// ---------------------------------------------------------------------------
#define B_   8
#define L_   1024
#define E_   1024
#define H_   16
#define D_   64
#define M_ROWS (B_ * L_)

__device__ float g_Q[B_ * H_ * L_ * D_];
__device__ float g_K[B_ * H_ * L_ * D_];
__device__ float g_V[B_ * H_ * L_ * D_];
__device__ float g_X[M_ROWS * E_];
__device__ float g_W[3 * E_ * E_];

// ---------------------------------------------------------------------------
// Common helpers
// ---------------------------------------------------------------------------
__device__ __forceinline__ float tf32r(float x) {
    uint32_t u;
    asm("cvt.rna.tf32.f32 %0, %1;" : "=r"(u) : "f"(x));
    return __uint_as_float(u);
}

__device__ __forceinline__ void mma_tf32(float c[4], const float a[4], const float b[2]) {
    asm volatile(
        "mma.sync.aligned.m16n8k8.row.col.f32.tf32.tf32.f32 "
        "{%0,%1,%2,%3}, {%4,%5,%6,%7}, {%8,%9}, {%0,%1,%2,%3};"
        : "+f"(c[0]), "+f"(c[1]), "+f"(c[2]), "+f"(c[3])
        : "r"(__float_as_uint(a[0])), "r"(__float_as_uint(a[1])),
          "r"(__float_as_uint(a[2])), "r"(__float_as_uint(a[3])),
          "r"(__float_as_uint(b[0])), "r"(__float_as_uint(b[1])));
}

#define CP_ASYNC_CG(dst, src) \
    asm volatile("cp.async.cg.shared.global [%0], [%1], 16;\n" :: "r"(dst), "l"(src))
#define CP_ASYNC_COMMIT() asm volatile("cp.async.commit_group;\n" ::: "memory")
#define CP_ASYNC_WAIT(n)  asm volatile("cp.async.wait_group %0;\n" :: "n"(n) : "memory")

__device__ __forceinline__ uint32_t smem_u32(const void* p) {
    uint32_t a;
    asm("{ .reg .u64 t; cvta.to.shared.u64 t, %1; cvt.u32.u64 %0, t; }" : "=r"(a) : "l"(p));
    return a;
}

#define SWZ(o) ((o) ^ (((o) >> 3) & 0x70))

// ---------------------------------------------------------------------------
// Kernel 0: fused fp32 -> tf32(rna) for X and all three W (single launch).
// ---------------------------------------------------------------------------
#define NX4 (M_ROWS * E_ / 4)     // 2097152
#define NW4 (E_ * E_ / 4)         // 262144

__global__ void cvt_all_kernel(const float4* __restrict__ x,
                               const float4* __restrict__ wq,
                               const float4* __restrict__ wk,
                               const float4* __restrict__ wv)
{
    const int i = blockIdx.x * blockDim.x + threadIdx.x;
    const float4* src;
    float4* dst;
    if (i < NX4) {
        src = x + i;
        dst = reinterpret_cast<float4*>(g_X) + i;
    } else {
        const int j = i - NX4;
        const int w = j >> 18;                 // NW4 == 1<<18
        const int r = j & (NW4 - 1);
        src = ((w == 0) ? wq : (w == 1) ? wk : wv) + r;
        dst = reinterpret_cast<float4*>(g_W) + j;
    }
    float4 v = *src;
    v.x = tf32r(v.x); v.y = tf32r(v.y); v.z = tf32r(v.z); v.w = tf32r(v.w);
    *dst = v;
}

// ---------------------------------------------------------------------------
// tcgen05 machinery (sm_103a pass only)
// ---------------------------------------------------------------------------
#ifdef TC_OK
__device__ __forceinline__ uint32_t elect_one() {
    uint32_t pred;
    asm volatile("{\n\t.reg .pred p;\n\telect.sync _|p, 0xFFFFFFFF;\n\t"
                 "selp.b32 %0, 1, 0, p;\n\t}" : "=r"(pred));
    return pred;
}

#define MBAR_INIT(a, c) \
    asm volatile("mbarrier.init.shared.b64 [%0], %1;" :: "r"(a), "r"(c) : "memory")
#define MBAR_WAIT(a, ph) do {                                                   \
    asm volatile("{\n\t.reg .pred P1;\n\t"                                      \
        "WAIT_LOOP_%=:\n\t"                                                     \
        "mbarrier.try_wait.parity.acquire.cta.shared::cta.b64 P1, [%0], %1, 0x989680;\n\t" \
        "@P1 bra.uni WAIT_DONE_%=;\n\t"                                         \
        "bra.uni WAIT_LOOP_%=;\n\t"                                             \
        "WAIT_DONE_%=:\n\t}"                                                    \
        :: "r"(a), "r"(ph) : "memory");                                         \
} while (0)

#define TCG_ALLOC(slot, n) \
    asm volatile("tcgen05.alloc.cta_group::1.sync.aligned.shared::cta.b32 [%0], %1;" \
                 :: "r"(slot), "r"((uint32_t)(n)) : "memory")
#define TCG_DEALLOC(t, n) \
    asm volatile("tcgen05.dealloc.cta_group::1.sync.aligned.b32 %0, %1;" :: "r"(t), "r"((uint32_t)(n)))
#define TCG_RELINQ() \
    asm volatile("tcgen05.relinquish_alloc_permit.cta_group::1.sync.aligned;")
#define TCG_COMMIT(mb) \
    asm volatile("tcgen05.commit.cta_group::1.mbarrier::arrive::one.shared::cluster.b64 [%0];" \
                 :: "r"(mb) : "memory")
#define TCG_FENCE_AFTER()  asm volatile("tcgen05.fence::after_thread_sync;" ::: "memory")
#define TCG_FENCE_BEFORE() asm volatile("tcgen05.fence::before_thread_sync;" ::: "memory")
#define TCG_WAIT_LD() asm volatile("tcgen05.wait::ld.sync.aligned;" ::: "memory")

#define TCG_LD_X32(r, addr)                                                      \
    asm volatile("tcgen05.ld.sync.aligned.32x32b.x32.b32 "                       \
        "{%0,%1,%2,%3,%4,%5,%6,%7,%8,%9,%10,%11,%12,%13,%14,%15,"               \
        "%16,%17,%18,%19,%20,%21,%22,%23,%24,%25,%26,%27,%28,%29,%30,%31}, [%32];" \
        : "=r"((r)[0]), "=r"((r)[1]), "=r"((r)[2]), "=r"((r)[3]),                \
          "=r"((r)[4]), "=r"((r)[5]), "=r"((r)[6]), "=r"((r)[7]),                \
          "=r"((r)[8]), "=r"((r)[9]), "=r"((r)[10]), "=r"((r)[11]),              \
          "=r"((r)[12]), "=r"((r)[13]), "=r"((r)[14]), "=r"((r)[15]),            \
          "=r"((r)[16]), "=r"((r)[17]), "=r"((r)[18]), "=r"((r)[19]),            \
          "=r"((r)[20]), "=r"((r)[21]), "=r"((r)[22]), "=r"((r)[23]),            \
          "=r"((r)[24]), "=r"((r)[25]), "=r"((r)[26]), "=r"((r)[27]),            \
          "=r"((r)[28]), "=r"((r)[29]), "=r"((r)[30]), "=r"((r)[31])             \
        : "r"(addr))

__device__ __forceinline__ uint64_t make_desc_sw128(uint32_t addr) {
    const uint64_t base = (uint64_t(2) << 61) | (uint64_t(1) << 46)
                        | (uint64_t(64) << 32) | (uint64_t(1) << 16);
    return base | ((uint64_t)(addr >> 4) & 0x3FFF);
}

// idesc kind::tf32: dtype F32@4, a/b TF32(2)@7/10, N/8@17, M/16@24
__device__ __forceinline__ uint32_t idesc_tf32(int n) {
    return (1u << 4) | (2u << 7) | (2u << 10) | (((uint32_t)n / 8) << 17) | (8u << 24);
}

__device__ __forceinline__ void mma_ss_tf32(uint32_t d, uint64_t a, uint64_t b,
                                            uint32_t idesc, uint32_t en) {
    asm volatile(
        "{\n\t.reg .pred p;\n\tsetp.ne.u32 p, %4, 0;\n\t"
        "tcgen05.mma.cta_group::1.kind::tf32 [%0], %1, %2, %3, {%5,%5,%5,%5}, p;\n\t}"
        :: "r"(d), "l"(a), "l"(b), "r"(idesc), "r"(en), "r"(0u) : "memory");
}
#endif  // TC_OK

// ---------------------------------------------------------------------------
// Kernel 1a: QKV projection on tcgen05 (sm_103a pass).  BM=256 x BN=256, BK=32.
// (verbatim R13 — proven)
// ---------------------------------------------------------------------------
#define NSTAGE 3
#define STAGE_BYTES 65536
#define QKV_TC_SMEM (NSTAGE * STAGE_BYTES)

__global__ __launch_bounds__(256, 1)
void qkv_tc_kernel(const float* __restrict__ bq,
                   const float* __restrict__ bk,
                   const float* __restrict__ bv)
{
#ifdef TC_OK
    extern __shared__ __align__(1024) char smem[];
    __shared__ uint32_t s_tmem;
    __shared__ __align__(8) uint64_t s_mbar[NSTAGE];

    const int t    = threadIdx.x;
    const int wid  = t >> 5;
    const int lane = t & 31;
    const int z    = blockIdx.z;
    const int m0   = blockIdx.y * 256;
    const int n0   = blockIdx.x * 256;

    const float* __restrict__ Wz   = g_W + (size_t)z * E_ * E_;
    const float* __restrict__ bias = (z == 0) ? bq : (z == 1) ? bk : bv;
    float* __restrict__ out        = (z == 0) ? g_Q : (z == 1) ? g_K : g_V;

    const uint32_t smem_u = smem_u32(smem);

    if (wid == 0) {
        TCG_ALLOC(smem_u32(&s_tmem), 512);
        TCG_RELINQ();
    }
    if (t == 0) {
#pragma unroll
        for (int s = 0; s < NSTAGE; s++) MBAR_INIT(smem_u32(&s_mbar[s]), 1);
    }
    __syncthreads();
    const uint32_t tmem = s_tmem;

    uint32_t phbits = 0;
    const uint32_t idq = idesc_tf32(256);

    for (int kt = 0; kt < 34; kt++) {
        if (kt < 32) {
            const int s = kt % 3;
            const int k0 = kt * 32;
            const uint32_t stg = smem_u + (uint32_t)s * STAGE_BYTES;
            if (kt >= 3) {
                MBAR_WAIT(smem_u32(&s_mbar[s]), (phbits >> s) & 1u);
                phbits ^= (1u << s);
            }
#pragma unroll
            for (int u = 0; u < 16; u++) {
                const int f = u * 256 + t;
                const float* src;
                uint32_t dst;
                if (u < 8) {
                    const int ti  = u >> 2;
                    const int fa  = f & 1023;
                    const int row = fa >> 3;
                    const int c   = fa & 7;
                    src = g_X + (size_t)(m0 + ti * 128 + row) * E_ + k0 + c * 4;
                    dst = stg + ti * 16384 + SWZ(row * 128 + c * 16);
                } else {
                    const int fb  = f - 2048;
                    const int row = fb >> 3;
                    const int c   = fb & 7;
                    src = Wz + (size_t)(n0 + row) * E_ + k0 + c * 4;
                    dst = stg + 32768 + SWZ(row * 128 + c * 16);
                }
                CP_ASYNC_CG(dst, src);
            }
            CP_ASYNC_COMMIT();
        }
        if (kt >= 2) {
            const int c  = kt - 2;
            const int sc = c % 3;
            if (kt < 32)       { CP_ASYNC_WAIT(2); }
            else if (kt == 32) { CP_ASYNC_WAIT(1); }
            else               { CP_ASYNC_WAIT(0); }
            asm volatile("fence.proxy.async.shared::cta;" ::: "memory");
            __syncthreads();
            if (wid == 0 && elect_one()) {
                const uint32_t stc = smem_u + (uint32_t)sc * STAGE_BYTES;
                const uint64_t bdesc = make_desc_sw128(stc + 32768);
#pragma unroll
                for (int ti = 0; ti < 2; ti++) {
                    const uint64_t adesc = make_desc_sw128(stc + ti * 16384);
#pragma unroll
                    for (int ks = 0; ks < 4; ks++) {
                        mma_ss_tf32(tmem + ti * 256, adesc + ks * 2, bdesc + ks * 2,
                                    idq, (c > 0 || ks > 0) ? 1u : 0u);
                    }
                }
                TCG_COMMIT(smem_u32(&s_mbar[sc]));
            }
        }
    }

    MBAR_WAIT(smem_u32(&s_mbar[1]), (phbits >> 1) & 1u);
    TCG_FENCE_AFTER();
    __syncthreads();

    // epilogue: LDTM -> smem transpose -> tf32r(bias add) -> coalesced scatter
    {
        const int ti = wid >> 2;
        const int sp = wid & 3;
        float* patch = reinterpret_cast<float*>(smem) + wid * (33 * 32);
        const int mr_base = m0 + ti * 128 + sp * 32;
#pragma unroll
        for (int cb = 0; cb < 8; cb++) {
            const int nb  = n0 + cb * 32;
            const int h   = nb >> 6;
            const int dd0 = nb & 63;
            const float bl = bias[nb + lane];
            uint32_t r[32];
            TCG_LD_X32(r, tmem + ti * 256 + cb * 32);
            TCG_WAIT_LD();
#pragma unroll
            for (int j = 0; j < 32; j++) patch[j * 33 + lane] = __uint_as_float(r[j]);
            __syncwarp();
#pragma unroll
            for (int rr = 0; rr < 32; rr++) {
                const int m = mr_base + rr;
                const int b = m >> 10;
                const int l = m & 1023;
                out[(((size_t)(b * H_ + h)) * L_ + l) * D_ + dd0 + lane] =
                    tf32r(patch[lane * 33 + rr] + bl);
            }
            __syncwarp();
        }
    }

    TCG_FENCE_BEFORE();
    __syncthreads();
    if (wid == 0) { TCG_DEALLOC(tmem, 512); }
#else
    (void)bq; (void)bk; (void)bv;
#endif
}

// ---------------------------------------------------------------------------
// Kernel 1b: QKV fallback (non-a pass), mma.sync + cp.async (proven)
// ---------------------------------------------------------------------------
#define BK 32
#define STG_FLOATS (2 * 128 * BK)
#define STG_BYTES  (STG_FLOATS * 4)
#define NST 3
#define QKV_MMA_SMEM (NST * STG_BYTES)

__global__ __launch_bounds__(256, 2)
void qkv_mma2_kernel(const float* __restrict__ bq,
                     const float* __restrict__ bk,
                     const float* __restrict__ bv)
{
#ifndef TC_OK
    extern __shared__ __align__(128) float smemf[];

    const int t    = threadIdx.x;
    const int lane = t & 31;
    const int wid  = t >> 5;
    const int gid  = lane >> 2;
    const int tig  = lane & 3;
    const int wm   = (wid >> 1) * 32;
    const int wn   = (wid & 1) * 64;
    const int z    = blockIdx.z;
    const int m0   = blockIdx.y * 128;
    const int n0   = blockIdx.x * 128;

    const float* __restrict__ Wz   = g_W + (size_t)z * E_ * E_;
    const float* __restrict__ bias = (z == 0) ? bq : (z == 1) ? bk : bv;
    float* __restrict__ out        = (z == 0) ? g_Q : (z == 1) ? g_K : g_V;

    const uint32_t smem_b = smem_u32(smemf);
    const int lrow_base = t >> 3;
    const int lc        = (t & 7) * 16;

    float acc[2][8][4];
#pragma unroll
    for (int i = 0; i < 2; i++)
#pragma unroll
        for (int j = 0; j < 8; j++)
#pragma unroll
            for (int c = 0; c < 4; c++) acc[i][j][c] = 0.f;

    auto issue = [&](int kt, int s) {
        const uint32_t stg = smem_b + (uint32_t)s * STG_BYTES;
        const int k0 = kt * BK;
#pragma unroll
        for (int u = 0; u < 4; u++) {
            const int row = lrow_base + u * 32;
            const uint32_t sw = (uint32_t)(lc ^ ((row & 7) << 4));
            const uint32_t da = stg + (uint32_t)row * 128 + sw;
            const uint32_t db = da + 16384;
            const float* sa = g_X + (size_t)(m0 + row) * E_ + k0 + (lc >> 2);
            const float* sb = Wz  + (size_t)(n0 + row) * E_ + k0 + (lc >> 2);
            CP_ASYNC_CG(da, sa);
            CP_ASYNC_CG(db, sb);
        }
        CP_ASYNC_COMMIT();
    };

    issue(0, 0); issue(1, 1); issue(2, 2);
    const int x0 = 4 * gid;

    for (int kt = 0; kt < 32; kt++) {
        const int s = kt % 3;
        CP_ASYNC_WAIT(2);
        __syncthreads();
        const float* sA = smemf + (size_t)s * STG_FLOATS;
        const float* sB = sA + 4096;
#pragma unroll
        for (int ks = 0; ks < 4; ks++) {
            const int k  = ks * 8;
            const int c0 = (k + tig) ^ x0;
            const int c1 = (k + tig + 4) ^ x0;
            float a[2][4];
#pragma unroll
            for (int im = 0; im < 2; im++) {
                const int r0 = wm + im * 16 + gid;
                a[im][0] = sA[r0 * 32 + c0];
                a[im][1] = sA[(r0 + 8) * 32 + c0];
                a[im][2] = sA[r0 * 32 + c1];
                a[im][3] = sA[(r0 + 8) * 32 + c1];
            }
            float b[8][2];
#pragma unroll
            for (int jn = 0; jn < 8; jn++) {
                const int rn = wn + jn * 8 + gid;
                b[jn][0] = sB[rn * 32 + c0];
                b[jn][1] = sB[rn * 32 + c1];
            }
#pragma unroll
            for (int im = 0; im < 2; im++)
#pragma unroll
                for (int jn = 0; jn < 8; jn++)
                    mma_tf32(acc[im][jn], a[im], b[jn]);
        }
        __syncthreads();
        if (kt + 3 < 32) issue(kt + 3, s);
    }

#pragma unroll
    for (int im = 0; im < 2; im++) {
        const int mr = m0 + wm + im * 16 + gid;
        const int b0r = mr >> 10, l0r = mr & 1023;
        const int b1r = (mr + 8) >> 10, l1r = (mr + 8) & 1023;
#pragma unroll
        for (int jn = 0; jn < 8; jn++) {
            const int n  = n0 + wn + jn * 8 + 2 * tig;
            const int h  = n >> 6;
            const int dd = n & 63;
            const float bi0 = bias[n], bi1 = bias[n + 1];
            float2 v0, v1;
            v0.x = acc[im][jn][0] + bi0; v0.y = acc[im][jn][1] + bi1;
            v1.x = acc[im][jn][2] + bi0; v1.y = acc[im][jn][3] + bi1;
            *reinterpret_cast<float2*>(
                &out[(((size_t)(b0r * H_ + h)) * L_ + l0r) * D_ + dd]) = v0;
            *reinterpret_cast<float2*>(
                &out[(((size_t)(b1r * H_ + h)) * L_ + l1r) * D_ + dd]) = v1;
        }
    }
#else
    (void)bq; (void)bk; (void)bv;
#endif
}

// ---------------------------------------------------------------------------
// Kernel 2a: attention on tcgen05 (sm_103a pass), 2-CTA/SM (R13 base).
// ONE change vs R13: V load / Vt store remapped so every transpose STS
// instruction is bank-conflict-free (was 4-way conflicted).
//   thread (vdh=lane>>3, vrow8=lane&7) owns key = wid*8+vrow8,
//   d = m*8 + vdh*2 + jj (m=0..7, jj=0..1)  ->  bank = (K^vdh)*8 ^ perm(vrow8).
// SMEM: Q 32K @0 | K 16K @32768 | Vt 16K @49152 | P 32K @65536 = 96K.
// TMEM (alloc 256): S slots @0,@64 | O @128.
// ---------------------------------------------------------------------------
#define AQ_OFF   0
#define AK_OFF   32768
#define AVT_OFF  49152
#define AP_OFF   65536
#define ATTN_TC_SMEM 98304

__global__ __launch_bounds__(256, 2)
void attn_tc_kernel(float* __restrict__ O)
{
#ifdef TC_OK
    extern __shared__ __align__(1024) char smem[];
    __shared__ uint32_t s_tmem;
    __shared__ __align__(8) uint64_t s_mbar_s, s_mbar_pv;
    __shared__ float s_l[2][128];

    const int t    = threadIdx.x;
    const int wid  = t >> 5;
    const int lane = t & 31;
    const int pr   = wid >> 2;          // column-half (0: cols 0-31, 1: 32-63)
    const int sp   = wid & 3;           // TMEM subpartition -> rows sp*32..+31
    const int bh   = blockIdx.y;
    const int q0   = blockIdx.x * 128;

    const float* __restrict__ Qb = g_Q + (size_t)bh * L_ * D_;
    const float* __restrict__ Kb = g_K + (size_t)bh * L_ * D_;
    const float* __restrict__ Vb = g_V + (size_t)bh * L_ * D_;

    const uint32_t su   = smem_u32(smem);
    const uint32_t qb   = su + AQ_OFF;
    const uint32_t kbuf = su + AK_OFF;
    const uint32_t vtb  = su + AVT_OFF;
    const uint32_t pb   = su + AP_OFF;

    if (wid == 0) {
        TCG_ALLOC(smem_u32(&s_tmem), 256);
        TCG_RELINQ();
    }
    if (t == 0) {
        MBAR_INIT(smem_u32(&s_mbar_s), 1);
        MBAR_INIT(smem_u32(&s_mbar_pv), 1);
    }
    __syncthreads();
    const uint32_t tmem = s_tmem;
    const uint32_t TM_O = tmem + 128;
    const uint32_t mb_s  = smem_u32(&s_mbar_s);
    const uint32_t mb_pv = smem_u32(&s_mbar_pv);

    auto load_q = [&]() {
#pragma unroll
        for (int c = 0; c < 2; c++) {
#pragma unroll
            for (int u = 0; u < 4; u++) {
                const int f   = u * 256 + t;
                const int row = f >> 3;
                const int cg  = f & 7;
                const float* src = Qb + (size_t)(q0 + row) * D_ + c * 32 + cg * 4;
                CP_ASYNC_CG(qb + c * 16384 + SWZ(row * 128 + cg * 16), src);
            }
        }
    };
    auto load_k = [&](int row0) {
#pragma unroll
        for (int c = 0; c < 2; c++) {
#pragma unroll
            for (int u = 0; u < 2; u++) {
                const int g   = u * 256 + t;
                const int row = g >> 3;
                const int cg  = g & 7;
                const float* src = Kb + (size_t)(row0 + row) * D_ + c * 32 + cg * 4;
                CP_ASYNC_CG(kbuf + c * 8192 + SWZ(row * 128 + cg * 16), src);
            }
        }
    };

    // prologue: Q + K0
    load_q();
    load_k(0);
    CP_ASYNC_COMMIT();
    CP_ASYNC_WAIT(0);
    asm volatile("fence.proxy.async.shared::cta;" ::: "memory");
    __syncthreads();

    const uint32_t id_64 = idesc_tf32(64);

    // S-MMA(0)
    if (wid == 0 && elect_one()) {
#pragma unroll
        for (int c = 0; c < 2; c++) {
            const uint64_t adesc = make_desc_sw128(qb + c * 16384);
            const uint64_t bdesc = make_desc_sw128(kbuf + c * 8192);
#pragma unroll
            for (int ks = 0; ks < 4; ks++)
                mma_ss_tf32(tmem, adesc + ks * 2, bdesc + ks * 2,
                            id_64, (c > 0 || ks > 0) ? 1u : 0u);
        }
        TCG_COMMIT(mb_s);
    }

    float lpart = 0.f;
    const float scale = 0.125f;
    // V/Vt mapping (conflict-free transpose):
    //   warp -> keys [wid*8, wid*8+8); thread: vrow8 = lane&7 (key), vdh = lane>>3.
    //   thread owns d = m*8 + vdh*2 + jj  (m = 0..7, jj = 0..1).
    //   Vt chunk = wid>>2 (32 keys), col in chunk vcol = (wid&3)*8 + vrow8.
    const int vrow8 = lane & 7;
    const int vdh   = lane >> 3;
    const int vcol  = (wid & 3) * 8 + vrow8;
    const int vchnk = wid >> 2;

    for (int kt = 0; kt < 16; kt++) {
        // --- V(kt) loads: 8 x float2, d = m*8 + vdh*2, fully coalesced 32B sectors ---
        float2 vr[8];
        {
            const float* vbase = Vb + (size_t)(kt * 64 + wid * 8 + vrow8) * D_ + vdh * 2;
#pragma unroll
            for (int m = 0; m < 8; m++)
                vr[m] = *reinterpret_cast<const float2*>(vbase + m * 8);
        }

        // --- wait S(kt); kbuf now free -> issue K(kt+1) load immediately ---
        MBAR_WAIT(mb_s, kt & 1);
        TCG_FENCE_AFTER();
        if (kt < 15) {
            load_k((kt + 1) * 64);
            CP_ASYNC_COMMIT();
        }

        // --- read S(kt) + exp (one 32-col LDTM per warp) ---
        uint32_t r0[32];
        TCG_LD_X32(r0, tmem + (kt & 1) * 64 + pr * 32);
        TCG_WAIT_LD();
        float p[32];
#pragma unroll
        for (int j = 0; j < 32; j++) {
            p[j] = tf32r(__expf(__uint_as_float(r0[j]) * scale));
            lpart += p[j];
        }

        // --- wait PV(kt-1) before overwriting P and Vt ---
        if (kt > 0) MBAR_WAIT(mb_pv, (kt - 1) & 1);

        // --- store P (tf32): row = sp*32+lane, key chunk pr (conflict-free) ---
        {
            const int row = sp * 32 + lane;
#pragma unroll
            for (int jb = 0; jb < 8; jb++) {
                const uint32_t addr = pb + pr * 16384 + SWZ(row * 128 + jb * 16);
                float4 v4 = make_float4(p[jb * 4], p[jb * 4 + 1], p[jb * 4 + 2], p[jb * 4 + 3]);
                *reinterpret_cast<float4*>((char*)smem + (addr - su)) = v4;
            }
        }

        // --- store Vt(kt) transposed: conflict-free scalar stores ---
        {
            const uint32_t vdst = vtb + vchnk * 8192;
#pragma unroll
            for (int m = 0; m < 8; m++) {
                const int d0 = m * 8 + vdh * 2;
                float e0 = tf32r(vr[m].x);
                float e1 = tf32r(vr[m].y);
                *reinterpret_cast<float*>((char*)smem + (vdst + SWZ((d0 + 0) * 128 + vcol * 4) - su)) = e0;
                *reinterpret_cast<float*>((char*)smem + (vdst + SWZ((d0 + 1) * 128 + vcol * 4) - su)) = e1;
            }
        }

        // K(kt+1) completion (only group in flight), then rendezvous
        if (kt < 15) CP_ASYNC_WAIT(0);
        asm volatile("fence.proxy.async.shared::cta;" ::: "memory");
        __syncthreads();

        if (wid == 0 && elect_one()) {
            if (kt < 15) {   // S-MMA(kt+1) into the other slot
                const uint32_t dslot = tmem + ((kt + 1) & 1) * 64;
#pragma unroll
                for (int c = 0; c < 2; c++) {
                    const uint64_t adesc = make_desc_sw128(qb + c * 16384);
                    const uint64_t bdesc = make_desc_sw128(kbuf + c * 8192);
#pragma unroll
                    for (int ks = 0; ks < 4; ks++)
                        mma_ss_tf32(dslot, adesc + ks * 2, bdesc + ks * 2,
                                    id_64, (c > 0 || ks > 0) ? 1u : 0u);
                }
                TCG_COMMIT(mb_s);
            }
            // PV-MMA(kt): O += P x Vt (contraction over 64 keys, 8 k-steps)
            {
#pragma unroll
                for (int ks = 0; ks < 8; ks++) {
                    const int ch = ks >> 2;
                    const uint64_t adesc = make_desc_sw128(pb + ch * 16384) + (ks & 3) * 2;
                    const uint64_t bdesc = make_desc_sw128(vtb + ch * 8192) + (ks & 3) * 2;
                    mma_ss_tf32(TM_O, adesc, bdesc, id_64,
                                (kt > 0 || ks > 0) ? 1u : 0u);
                }
                TCG_COMMIT(mb_pv);
            }
        }
    }

    // combine row sums across column-halves
    s_l[pr][sp * 32 + lane] = lpart;
    __syncthreads();
    const int myrow = sp * 32 + lane;
    const float linv = 1.f / (s_l[0][myrow] + s_l[1][myrow]);

    // wait PV(15), read O, scale, transpose, coalesced store
    MBAR_WAIT(mb_pv, 15 & 1);
    TCG_FENCE_AFTER();
    {
        uint32_t r[32];
        TCG_LD_X32(r, TM_O + pr * 32);
        TCG_WAIT_LD();
        float* patch = reinterpret_cast<float*>(smem) + wid * (33 * 32);   // Q region reuse
        __syncthreads();
#pragma unroll
        for (int j = 0; j < 32; j++)
            patch[j * 33 + lane] = __uint_as_float(r[j]) * linv;
        __syncwarp();
        const int rbase = q0 + sp * 32;
        const int dcol  = pr * 32 + lane;
#pragma unroll
        for (int rr = 0; rr < 32; rr++) {
            O[((size_t)bh * L_ + rbase + rr) * D_ + dcol] = patch[lane * 33 + rr];
        }
    }

    TCG_FENCE_BEFORE();
    __syncthreads();
    if (wid == 0) { TCG_DEALLOC(tmem, 256); }
#else
    (void)O;
#endif
}

// ---------------------------------------------------------------------------
// Kernel 2b: attention fallback (non-a pass), tf32 mma.sync (proven, 256 thr)
// ---------------------------------------------------------------------------
#define QP 68
#define VP 72
#define SM_Q  0
#define SM_P  (128 * QP)
#define SM_K  (2 * 128 * QP)
#define SM_V  (2 * 128 * QP + 64 * QP)
#define ATTN_SMEM_FLOATS (2 * 128 * QP + 64 * QP + 64 * VP)
#define ATTN_SMEM_BYTES  (ATTN_SMEM_FLOATS * 4)

__global__ __launch_bounds__(256, 2)
void attn_mma_kernel(float* __restrict__ O)
{
#ifndef TC_OK
    extern __shared__ float sm[];
    float* Qs = sm + SM_Q;
    float* Ps = sm + SM_P;
    float* Ks = sm + SM_K;
    float* Vs = sm + SM_V;

    const int bh = blockIdx.y;
    const int q0 = blockIdx.x * 128;
    const float* __restrict__ Qb = g_Q + (size_t)bh * L_ * D_;
    const float* __restrict__ Kb = g_K + (size_t)bh * L_ * D_;
    const float* __restrict__ Vb = g_V + (size_t)bh * L_ * D_;

    const int t    = threadIdx.x;
    const int lane = t & 31;
    const int wid  = t >> 5;
    const int gid  = lane >> 2;
    const int tig  = lane & 3;
    const int qb   = wid * 16;

#pragma unroll
    for (int u = 0; u < 8; u++) {
        const int g  = u * 256 + t;
        const int r  = g >> 4;
        const int c4 = (g & 15) * 4;
        float4 v = *reinterpret_cast<const float4*>(&Qb[(size_t)(q0 + r) * D_ + c4]);
        v.x = tf32r(v.x); v.y = tf32r(v.y); v.z = tf32r(v.z); v.w = tf32r(v.w);
        *reinterpret_cast<float4*>(&Qs[r * QP + c4]) = v;
    }

    float m_i[2] = {-CUDART_INF_F, -CUDART_INF_F};
    float l_i[2] = {0.f, 0.f};
    float o[8][4];
#pragma unroll
    for (int j = 0; j < 8; j++)
#pragma unroll
        for (int c = 0; c < 4; c++) o[j][c] = 0.f;

    for (int kt = 0; kt < L_ / 64; kt++) {
        __syncthreads();
        const int k0g = kt * 64;
#pragma unroll
        for (int u = 0; u < 4; u++) {
            const int g  = u * 256 + t;
            const int r  = g >> 4;
            const int c4 = (g & 15) * 4;
            float4 kv = *reinterpret_cast<const float4*>(&Kb[(size_t)(k0g + r) * D_ + c4]);
            float4 vv = *reinterpret_cast<const float4*>(&Vb[(size_t)(k0g + r) * D_ + c4]);
            kv.x = tf32r(kv.x); kv.y = tf32r(kv.y); kv.z = tf32r(kv.z); kv.w = tf32r(kv.w);
            vv.x = tf32r(vv.x); vv.y = tf32r(vv.y); vv.z = tf32r(vv.z); vv.w = tf32r(vv.w);
            *reinterpret_cast<float4*>(&Ks[r * QP + c4]) = kv;
            *reinterpret_cast<float4*>(&Vs[r * VP + c4]) = vv;
        }
        __syncthreads();

        float s[8][4];
#pragma unroll
        for (int j = 0; j < 8; j++)
#pragma unroll
            for (int c = 0; c < 4; c++) s[j][c] = 0.f;

#pragma unroll
        for (int ks = 0; ks < 8; ks++) {
            const int k = ks * 8;
            float a[4];
            a[0] = Qs[(qb + gid) * QP + k + tig];
            a[1] = Qs[(qb + gid + 8) * QP + k + tig];
            a[2] = Qs[(qb + gid) * QP + k + tig + 4];
            a[3] = Qs[(qb + gid + 8) * QP + k + tig + 4];
            float b[8][2];
#pragma unroll
            for (int jn = 0; jn < 8; jn++) {
                const int n = jn * 8;
                b[jn][0] = Ks[(n + gid) * QP + k + tig];
                b[jn][1] = Ks[(n + gid) * QP + k + tig + 4];
            }
#pragma unroll
            for (int jn = 0; jn < 8; jn++)
                mma_tf32(s[jn], a, b[jn]);
        }

        const float scale = 0.125f;
        float mt0 = -CUDART_INF_F, mt1 = -CUDART_INF_F;
#pragma unroll
        for (int jn = 0; jn < 8; jn++) {
            mt0 = fmaxf(mt0, fmaxf(s[jn][0], s[jn][1]));
            mt1 = fmaxf(mt1, fmaxf(s[jn][2], s[jn][3]));
        }
        mt0 *= scale; mt1 *= scale;
#pragma unroll
        for (int off = 1; off < 4; off <<= 1) {
            mt0 = fmaxf(mt0, __shfl_xor_sync(0xffffffffu, mt0, off));
            mt1 = fmaxf(mt1, __shfl_xor_sync(0xffffffffu, mt1, off));
        }
        const float mn0 = fmaxf(m_i[0], mt0);
        const float mn1 = fmaxf(m_i[1], mt1);
        const float cr0 = __expf(m_i[0] - mn0);
        const float cr1 = __expf(m_i[1] - mn1);
        float rs0 = 0.f, rs1 = 0.f;
#pragma unroll
        for (int jn = 0; jn < 8; jn++) {
            s[jn][0] = __expf(fmaf(s[jn][0], scale, -mn0));
            s[jn][1] = __expf(fmaf(s[jn][1], scale, -mn0));
            s[jn][2] = __expf(fmaf(s[jn][2], scale, -mn1));
            s[jn][3] = __expf(fmaf(s[jn][3], scale, -mn1));
            rs0 += s[jn][0] + s[jn][1];
            rs1 += s[jn][2] + s[jn][3];
        }
#pragma unroll
        for (int off = 1; off < 4; off <<= 1) {
            rs0 += __shfl_xor_sync(0xffffffffu, rs0, off);
            rs1 += __shfl_xor_sync(0xffffffffu, rs1, off);
        }
        l_i[0] = l_i[0] * cr0 + rs0;  m_i[0] = mn0;
        l_i[1] = l_i[1] * cr1 + rs1;  m_i[1] = mn1;
#pragma unroll
        for (int jn = 0; jn < 8; jn++) {
            o[jn][0] *= cr0; o[jn][1] *= cr0;
            o[jn][2] *= cr1; o[jn][3] *= cr1;
        }

#pragma unroll
        for (int jn = 0; jn < 8; jn++) {
            const int c = jn * 8 + 2 * tig;
            float2 p0, p1;
            p0.x = tf32r(s[jn][0]); p0.y = tf32r(s[jn][1]);
            p1.x = tf32r(s[jn][2]); p1.y = tf32r(s[jn][3]);
            *reinterpret_cast<float2*>(&Ps[(qb + gid) * QP + c]) = p0;
            *reinterpret_cast<float2*>(&Ps[(qb + gid + 8) * QP + c]) = p1;
        }
        __syncthreads();

#pragma unroll
        for (int ks = 0; ks < 8; ks++) {
            const int k = ks * 8;
            float a[4];
            a[0] = Ps[(qb + gid) * QP + k + tig];
            a[1] = Ps[(qb + gid + 8) * QP + k + tig];
            a[2] = Ps[(qb + gid) * QP + k + tig + 4];
            a[3] = Ps[(qb + gid + 8) * QP + k + tig + 4];
            float b[8][2];
#pragma unroll
            for (int jn = 0; jn < 8; jn++) {
                const int n = jn * 8;
                b[jn][0] = Vs[(k + tig) * VP + n + gid];
                b[jn][1] = Vs[(k + tig + 4) * VP + n + gid];
            }
#pragma unroll
            for (int jn = 0; jn < 8; jn++)
                mma_tf32(o[jn], a, b[jn]);
        }
    }

    const float inv0 = 1.f / l_i[0];
    const float inv1 = 1.f / l_i[1];
    const int r0 = q0 + qb + gid;
    const int r1 = r0 + 8;
#pragma unroll
    for (int jn = 0; jn < 8; jn++) {
        const int c = jn * 8 + 2 * tig;
        float2 v0, v1;
        v0.x = o[jn][0] * inv0; v0.y = o[jn][1] * inv0;
        v1.x = o[jn][2] * inv1; v1.y = o[jn][3] * inv1;
        *reinterpret_cast<float2*>(&O[((size_t)bh * L_ + r0) * D_ + c]) = v0;
        *reinterpret_cast<float2*>(&O[((size_t)bh * L_ + r1) * D_ + c]) = v1;
    }
#else
    (void)O;
#endif
}

// ---------------------------------------------------------------------------
extern "C" void kernel_launch(void* const* d_in, const int* in_sizes, int n_in,
                              void* d_out, int out_size)
{
    const float* x  = (const float*)d_in[0];
    const float* wq = (const float*)d_in[1];
    const float* bq = (const float*)d_in[2];
    const float* wk = (const float*)d_in[3];
    const float* bk = (const float*)d_in[4];
    const float* wv = (const float*)d_in[5];
    const float* bv = (const float*)d_in[6];
    float* out = (float*)d_out;

    cudaFuncSetAttribute(qkv_tc_kernel,
                         cudaFuncAttributeMaxDynamicSharedMemorySize, QKV_TC_SMEM);
    cudaFuncSetAttribute(qkv_mma2_kernel,
                         cudaFuncAttributeMaxDynamicSharedMemorySize, QKV_MMA_SMEM);
    cudaFuncSetAttribute(attn_tc_kernel,
                         cudaFuncAttributeMaxDynamicSharedMemorySize, ATTN_TC_SMEM);
    cudaFuncSetAttribute(attn_mma_kernel,
                         cudaFuncAttributeMaxDynamicSharedMemorySize, ATTN_SMEM_BYTES);

    // fused tf32(rna) rounding of X, Wq, Wk, Wv: exact grid
    const int total4 = NX4 + 3 * NW4;            // 2883584
    cvt_all_kernel<<<total4 / 256, 256>>>((const float4*)x, (const float4*)wq,
                                          (const float4*)wk, (const float4*)wv);

    // QKV: one of the two has a body per cubin
    dim3 tgrid(E_ / 256, M_ROWS / 256, 3);
    qkv_tc_kernel<<<tgrid, 256, QKV_TC_SMEM>>>(bq, bk, bv);
    dim3 fgrid(E_ / 128, M_ROWS / 128, 3);
    qkv_mma2_kernel<<<fgrid, 256, QKV_MMA_SMEM>>>(bq, bk, bv);

    // attention: same dual-variant scheme
    dim3 agrid(L_ / 128, B_ * H_);
    attn_tc_kernel<<<agrid, 256, ATTN_TC_SMEM>>>(out);
    attn_mma_kernel<<<agrid, 256, ATTN_SMEM_BYTES>>>(out);
}

// round 16
// speedup vs baseline: 1.8142x; 1.0946x over previous
#include <cuda_runtime.h>
#include <cuda_bf16.h>
#include <math_constants.h>
#include <stdint.h>

// ---------------------------------------------------------------------------
// Arch-variant gate: tcgen05 exists only in the sm_103a pass; the harness also
// builds compute_103 (non-a). Guarded kernels; host launches both variants,
// exactly one has a body per cubin.
// ---------------------------------------------------------------------------
#if defined(__CUDA_ARCH__)
#  if defined(__CUDA_ARCH_FEAT_SM103_ALL) || \
      (defined(__CUDA_ARCH_SPECIFIC__) && (__CUDA_ARCH_SPECIFIC__ == 1030))
#    define TC_OK 1
#  endif
#endif

// ---------------------------------------------------------------------------
#define B_   8
#define L_   1024
#define E_   1024
#define H_   16
#define D_   64
#define M_ROWS (B_ * L_)

__device__ float g_Q[B_ * H_ * L_ * D_];
__device__ float g_K[B_ * H_ * L_ * D_];
__device__ float g_V[B_ * H_ * L_ * D_];
__device__ float g_X[M_ROWS * E_];
__device__ float g_W[3 * E_ * E_];

// ---------------------------------------------------------------------------
// Common helpers
// ---------------------------------------------------------------------------
__device__ __forceinline__ float tf32r(float x) {
    uint32_t u;
    asm("cvt.rna.tf32.f32 %0, %1;" : "=r"(u) : "f"(x));
    return __uint_as_float(u);
}

__device__ __forceinline__ void mma_tf32(float c[4], const float a[4], const float b[2]) {
    asm volatile(
        "mma.sync.aligned.m16n8k8.row.col.f32.tf32.tf32.f32 "
        "{%0,%1,%2,%3}, {%4,%5,%6,%7}, {%8,%9}, {%0,%1,%2,%3};"
        : "+f"(c[0]), "+f"(c[1]), "+f"(c[2]), "+f"(c[3])
        : "r"(__float_as_uint(a[0])), "r"(__float_as_uint(a[1])),
          "r"(__float_as_uint(a[2])), "r"(__float_as_uint(a[3])),
          "r"(__float_as_uint(b[0])), "r"(__float_as_uint(b[1])));
}

#define CP_ASYNC_CG(dst, src) \
    asm volatile("cp.async.cg.shared.global [%0], [%1], 16;\n" :: "r"(dst), "l"(src))
#define CP_ASYNC_COMMIT() asm volatile("cp.async.commit_group;\n" ::: "memory")
#define CP_ASYNC_WAIT(n)  asm volatile("cp.async.wait_group %0;\n" :: "n"(n) : "memory")

__device__ __forceinline__ uint32_t smem_u32(const void* p) {
    uint32_t a;
    asm("{ .reg .u64 t; cvta.to.shared.u64 t, %1; cvt.u32.u64 %0, t; }" : "=r"(a) : "l"(p));
    return a;
}

#define SWZ(o) ((o) ^ (((o) >> 3) & 0x70))

// ---------------------------------------------------------------------------
// Kernel 0: fused fp32 -> tf32(rna) for X and all three W (single launch).
// ---------------------------------------------------------------------------
#define NX4 (M_ROWS * E_ / 4)     // 2097152
#define NW4 (E_ * E_ / 4)         // 262144

__global__ void cvt_all_kernel(const float4* __restrict__ x,
                               const float4* __restrict__ wq,
                               const float4* __restrict__ wk,
                               const float4* __restrict__ wv)
{
    const int i = blockIdx.x * blockDim.x + threadIdx.x;
    const float4* src;
    float4* dst;
    if (i < NX4) {
        src = x + i;
        dst = reinterpret_cast<float4*>(g_X) + i;
    } else {
        const int j = i - NX4;
        const int w = j >> 18;                 // NW4 == 1<<18
        const int r = j & (NW4 - 1);
        src = ((w == 0) ? wq : (w == 1) ? wk : wv) + r;
        dst = reinterpret_cast<float4*>(g_W) + j;
    }
    float4 v = *src;
    v.x = tf32r(v.x); v.y = tf32r(v.y); v.z = tf32r(v.z); v.w = tf32r(v.w);
    *dst = v;
}

// ---------------------------------------------------------------------------
// tcgen05 machinery (sm_103a pass only)
// ---------------------------------------------------------------------------
#ifdef TC_OK
__device__ __forceinline__ uint32_t elect_one() {
    uint32_t pred;
    asm volatile("{\n\t.reg .pred p;\n\telect.sync _|p, 0xFFFFFFFF;\n\t"
                 "selp.b32 %0, 1, 0, p;\n\t}" : "=r"(pred));
    return pred;
}

#define MBAR_INIT(a, c) \
    asm volatile("mbarrier.init.shared.b64 [%0], %1;" :: "r"(a), "r"(c) : "memory")
#define MBAR_WAIT(a, ph) do {                                                   \
    asm volatile("{\n\t.reg .pred P1;\n\t"                                      \
        "WAIT_LOOP_%=:\n\t"                                                     \
        "mbarrier.try_wait.parity.acquire.cta.shared::cta.b64 P1, [%0], %1, 0x989680;\n\t" \
        "@P1 bra.uni WAIT_DONE_%=;\n\t"                                         \
        "bra.uni WAIT_LOOP_%=;\n\t"                                             \
        "WAIT_DONE_%=:\n\t}"                                                    \
        :: "r"(a), "r"(ph) : "memory");                                         \
} while (0)

#define TCG_ALLOC(slot, n) \
    asm volatile("tcgen05.alloc.cta_group::1.sync.aligned.shared::cta.b32 [%0], %1;" \
                 :: "r"(slot), "r"((uint32_t)(n)) : "memory")
#define TCG_DEALLOC(t, n) \
    asm volatile("tcgen05.dealloc.cta_group::1.sync.aligned.b32 %0, %1;" :: "r"(t), "r"((uint32_t)(n)))
#define TCG_RELINQ() \
    asm volatile("tcgen05.relinquish_alloc_permit.cta_group::1.sync.aligned;")
#define TCG_COMMIT(mb) \
    asm volatile("tcgen05.commit.cta_group::1.mbarrier::arrive::one.shared::cluster.b64 [%0];" \
                 :: "r"(mb) : "memory")
#define TCG_FENCE_AFTER()  asm volatile("tcgen05.fence::after_thread_sync;" ::: "memory")
#define TCG_FENCE_BEFORE() asm volatile("tcgen05.fence::before_thread_sync;" ::: "memory")
#define TCG_WAIT_LD() asm volatile("tcgen05.wait::ld.sync.aligned;" ::: "memory")
#define TCG_WAIT_ST() asm volatile("tcgen05.wait::st.sync.aligned;" ::: "memory")

#define TCG_LD_X32(r, addr)                                                      \
    asm volatile("tcgen05.ld.sync.aligned.32x32b.x32.b32 "                       \
        "{%0,%1,%2,%3,%4,%5,%6,%7,%8,%9,%10,%11,%12,%13,%14,%15,"               \
        "%16,%17,%18,%19,%20,%21,%22,%23,%24,%25,%26,%27,%28,%29,%30,%31}, [%32];" \
        : "=r"((r)[0]), "=r"((r)[1]), "=r"((r)[2]), "=r"((r)[3]),                \
          "=r"((r)[4]), "=r"((r)[5]), "=r"((r)[6]), "=r"((r)[7]),                \
          "=r"((r)[8]), "=r"((r)[9]), "=r"((r)[10]), "=r"((r)[11]),              \
          "=r"((r)[12]), "=r"((r)[13]), "=r"((r)[14]), "=r"((r)[15]),            \
          "=r"((r)[16]), "=r"((r)[17]), "=r"((r)[18]), "=r"((r)[19]),            \
          "=r"((r)[20]), "=r"((r)[21]), "=r"((r)[22]), "=r"((r)[23]),            \
          "=r"((r)[24]), "=r"((r)[25]), "=r"((r)[26]), "=r"((r)[27]),            \
          "=r"((r)[28]), "=r"((r)[29]), "=r"((r)[30]), "=r"((r)[31])             \
        : "r"(addr))

#define TCG_ST_X32(addr, r)                                                      \
    asm volatile("tcgen05.st.sync.aligned.32x32b.x32.b32 [%0], "                 \
        "{%1,%2,%3,%4,%5,%6,%7,%8,%9,%10,%11,%12,%13,%14,%15,%16,"              \
        "%17,%18,%19,%20,%21,%22,%23,%24,%25,%26,%27,%28,%29,%30,%31,%32};"      \
        :: "r"(addr),                                                            \
           "r"((r)[0]),  "r"((r)[1]),  "r"((r)[2]),  "r"((r)[3]),                \
           "r"((r)[4]),  "r"((r)[5]),  "r"((r)[6]),  "r"((r)[7]),                \
           "r"((r)[8]),  "r"((r)[9]),  "r"((r)[10]), "r"((r)[11]),               \
           "r"((r)[12]), "r"((r)[13]), "r"((r)[14]), "r"((r)[15]),               \
           "r"((r)[16]), "r"((r)[17]), "r"((r)[18]), "r"((r)[19]),               \
           "r"((r)[20]), "r"((r)[21]), "r"((r)[22]), "r"((r)[23]),               \
           "r"((r)[24]), "r"((r)[25]), "r"((r)[26]), "r"((r)[27]),               \
           "r"((r)[28]), "r"((r)[29]), "r"((r)[30]), "r"((r)[31])                \
        : "memory")

__device__ __forceinline__ uint64_t make_desc_sw128(uint32_t addr) {
    const uint64_t base = (uint64_t(2) << 61) | (uint64_t(1) << 46)
                        | (uint64_t(64) << 32) | (uint64_t(1) << 16);
    return base | ((uint64_t)(addr >> 4) & 0x3FFF);
}

// idesc kind::tf32: dtype F32@4, a/b TF32(2)@7/10, N/8@17, M/16@24
__device__ __forceinline__ uint32_t idesc_tf32(int n) {
    return (1u << 4) | (2u << 7) | (2u << 10) | (((uint32_t)n / 8) << 17) | (8u << 24);
}

__device__ __forceinline__ void mma_ss_tf32(uint32_t d, uint64_t a, uint64_t b,
                                            uint32_t idesc, uint32_t en) {
    asm volatile(
        "{\n\t.reg .pred p;\n\tsetp.ne.u32 p, %4, 0;\n\t"
        "tcgen05.mma.cta_group::1.kind::tf32 [%0], %1, %2, %3, {%5,%5,%5,%5}, p;\n\t}"
        :: "r"(d), "l"(a), "l"(b), "r"(idesc), "r"(en), "r"(0u) : "memory");
}

// TS mode: A operand in TMEM
__device__ __forceinline__ void mma_ts_tf32(uint32_t d, uint32_t a, uint64_t b,
                                            uint32_t idesc, uint32_t en) {
    asm volatile(
        "{\n\t.reg .pred p;\n\tsetp.ne.u32 p, %4, 0;\n\t"
        "tcgen05.mma.cta_group::1.kind::tf32 [%0], [%1], %2, %3, {%5,%5,%5,%5}, p;\n\t}"
        :: "r"(d), "r"(a), "l"(b), "r"(idesc), "r"(en), "r"(0u) : "memory");
}
#endif  // TC_OK

// ---------------------------------------------------------------------------
// Kernel 1a: QKV projection on tcgen05 (sm_103a pass).  BM=256 x BN=256, BK=32.
// (verbatim R14 — proven)
// ---------------------------------------------------------------------------
#define NSTAGE 3
#define STAGE_BYTES 65536
#define QKV_TC_SMEM (NSTAGE * STAGE_BYTES)

__global__ __launch_bounds__(256, 1)
void qkv_tc_kernel(const float* __restrict__ bq,
                   const float* __restrict__ bk,
                   const float* __restrict__ bv)
{
#ifdef TC_OK
    extern __shared__ __align__(1024) char smem[];
    __shared__ uint32_t s_tmem;
    __shared__ __align__(8) uint64_t s_mbar[NSTAGE];

    const int t    = threadIdx.x;
    const int wid  = t >> 5;
    const int lane = t & 31;
    const int z    = blockIdx.z;
    const int m0   = blockIdx.y * 256;
    const int n0   = blockIdx.x * 256;

    const float* __restrict__ Wz   = g_W + (size_t)z * E_ * E_;
    const float* __restrict__ bias = (z == 0) ? bq : (z == 1) ? bk : bv;
    float* __restrict__ out        = (z == 0) ? g_Q : (z == 1) ? g_K : g_V;

    const uint32_t smem_u = smem_u32(smem);

    if (wid == 0) {
        TCG_ALLOC(smem_u32(&s_tmem), 512);
        TCG_RELINQ();
    }
    if (t == 0) {
#pragma unroll
        for (int s = 0; s < NSTAGE; s++) MBAR_INIT(smem_u32(&s_mbar[s]), 1);
    }
    __syncthreads();
    const uint32_t tmem = s_tmem;

    uint32_t phbits = 0;
    const uint32_t idq = idesc_tf32(256);

    for (int kt = 0; kt < 34; kt++) {
        if (kt < 32) {
            const int s = kt % 3;
            const int k0 = kt * 32;
            const uint32_t stg = smem_u + (uint32_t)s * STAGE_BYTES;
            if (kt >= 3) {
                MBAR_WAIT(smem_u32(&s_mbar[s]), (phbits >> s) & 1u);
                phbits ^= (1u << s);
            }
#pragma unroll
            for (int u = 0; u < 16; u++) {
                const int f = u * 256 + t;
                const float* src;
                uint32_t dst;
                if (u < 8) {
                    const int ti  = u >> 2;
                    const int fa  = f & 1023;
                    const int row = fa >> 3;
                    const int c   = fa & 7;
                    src = g_X + (size_t)(m0 + ti * 128 + row) * E_ + k0 + c * 4;
                    dst = stg + ti * 16384 + SWZ(row * 128 + c * 16);
                } else {
                    const int fb  = f - 2048;
                    const int row = fb >> 3;
                    const int c   = fb & 7;
                    src = Wz + (size_t)(n0 + row) * E_ + k0 + c * 4;
                    dst = stg + 32768 + SWZ(row * 128 + c * 16);
                }
                CP_ASYNC_CG(dst, src);
            }
            CP_ASYNC_COMMIT();
        }
        if (kt >= 2) {
            const int c  = kt - 2;
            const int sc = c % 3;
            if (kt < 32)       { CP_ASYNC_WAIT(2); }
            else if (kt == 32) { CP_ASYNC_WAIT(1); }
            else               { CP_ASYNC_WAIT(0); }
            asm volatile("fence.proxy.async.shared::cta;" ::: "memory");
            __syncthreads();
            if (wid == 0 && elect_one()) {
                const uint32_t stc = smem_u + (uint32_t)sc * STAGE_BYTES;
                const uint64_t bdesc = make_desc_sw128(stc + 32768);
#pragma unroll
                for (int ti = 0; ti < 2; ti++) {
                    const uint64_t adesc = make_desc_sw128(stc + ti * 16384);
#pragma unroll
                    for (int ks = 0; ks < 4; ks++) {
                        mma_ss_tf32(tmem + ti * 256, adesc + ks * 2, bdesc + ks * 2,
                                    idq, (c > 0 || ks > 0) ? 1u : 0u);
                    }
                }
                TCG_COMMIT(smem_u32(&s_mbar[sc]));
            }
        }
    }

    MBAR_WAIT(smem_u32(&s_mbar[1]), (phbits >> 1) & 1u);
    TCG_FENCE_AFTER();
    __syncthreads();

    // epilogue: LDTM -> smem transpose -> tf32r(bias add) -> coalesced scatter
    {
        const int ti = wid >> 2;
        const int sp = wid & 3;
        float* patch = reinterpret_cast<float*>(smem) + wid * (33 * 32);
        const int mr_base = m0 + ti * 128 + sp * 32;
#pragma unroll
        for (int cb = 0; cb < 8; cb++) {
            const int nb  = n0 + cb * 32;
            const int h   = nb >> 6;
            const int dd0 = nb & 63;
            const float bl = bias[nb + lane];
            uint32_t r[32];
            TCG_LD_X32(r, tmem + ti * 256 + cb * 32);
            TCG_WAIT_LD();
#pragma unroll
            for (int j = 0; j < 32; j++) patch[j * 33 + lane] = __uint_as_float(r[j]);
            __syncwarp();
#pragma unroll
            for (int rr = 0; rr < 32; rr++) {
                const int m = mr_base + rr;
                const int b = m >> 10;
                const int l = m & 1023;
                out[(((size_t)(b * H_ + h)) * L_ + l) * D_ + dd0 + lane] =
                    tf32r(patch[lane * 33 + rr] + bl);
            }
            __syncwarp();
        }
    }

    TCG_FENCE_BEFORE();
    __syncthreads();
    if (wid == 0) { TCG_DEALLOC(tmem, 512); }
#else
    (void)bq; (void)bk; (void)bv;
#endif
}

// ---------------------------------------------------------------------------
// Kernel 1b: QKV fallback (non-a pass), mma.sync + cp.async (proven)
// ---------------------------------------------------------------------------
#define BK 32
#define STG_FLOATS (2 * 128 * BK)
#define STG_BYTES  (STG_FLOATS * 4)
#define NST 3
#define QKV_MMA_SMEM (NST * STG_BYTES)

__global__ __launch_bounds__(256, 2)
void qkv_mma2_kernel(const float* __restrict__ bq,
                     const float* __restrict__ bk,
                     const float* __restrict__ bv)
{
#ifndef TC_OK
    extern __shared__ __align__(128) float smemf[];

    const int t    = threadIdx.x;
    const int lane = t & 31;
    const int wid  = t >> 5;
    const int gid  = lane >> 2;
    const int tig  = lane & 3;
    const int wm   = (wid >> 1) * 32;
    const int wn   = (wid & 1) * 64;
    const int z    = blockIdx.z;
    const int m0   = blockIdx.y * 128;
    const int n0   = blockIdx.x * 128;

    const float* __restrict__ Wz   = g_W + (size_t)z * E_ * E_;
    const float* __restrict__ bias = (z == 0) ? bq : (z == 1) ? bk : bv;
    float* __restrict__ out        = (z == 0) ? g_Q : (z == 1) ? g_K : g_V;

    const uint32_t smem_b = smem_u32(smemf);
    const int lrow_base = t >> 3;
    const int lc        = (t & 7) * 16;

    float acc[2][8][4];
#pragma unroll
    for (int i = 0; i < 2; i++)
#pragma unroll
        for (int j = 0; j < 8; j++)
#pragma unroll
            for (int c = 0; c < 4; c++) acc[i][j][c] = 0.f;

    auto issue = [&](int kt, int s) {
        const uint32_t stg = smem_b + (uint32_t)s * STG_BYTES;
        const int k0 = kt * BK;
#pragma unroll
        for (int u = 0; u < 4; u++) {
            const int row = lrow_base + u * 32;
            const uint32_t sw = (uint32_t)(lc ^ ((row & 7) << 4));
            const uint32_t da = stg + (uint32_t)row * 128 + sw;
            const uint32_t db = da + 16384;
            const float* sa = g_X + (size_t)(m0 + row) * E_ + k0 + (lc >> 2);
            const float* sb = Wz  + (size_t)(n0 + row) * E_ + k0 + (lc >> 2);
            CP_ASYNC_CG(da, sa);
            CP_ASYNC_CG(db, sb);
        }
        CP_ASYNC_COMMIT();
    };

    issue(0, 0); issue(1, 1); issue(2, 2);
    const int x0 = 4 * gid;

    for (int kt = 0; kt < 32; kt++) {
        const int s = kt % 3;
        CP_ASYNC_WAIT(2);
        __syncthreads();
        const float* sA = smemf + (size_t)s * STG_FLOATS;
        const float* sB = sA + 4096;
#pragma unroll
        for (int ks = 0; ks < 4; ks++) {
            const int k  = ks * 8;
            const int c0 = (k + tig) ^ x0;
            const int c1 = (k + tig + 4) ^ x0;
            float a[2][4];
#pragma unroll
            for (int im = 0; im < 2; im++) {
                const int r0 = wm + im * 16 + gid;
                a[im][0] = sA[r0 * 32 + c0];
                a[im][1] = sA[(r0 + 8) * 32 + c0];
                a[im][2] = sA[r0 * 32 + c1];
                a[im][3] = sA[(r0 + 8) * 32 + c1];
            }
            float b[8][2];
#pragma unroll
            for (int jn = 0; jn < 8; jn++) {
                const int rn = wn + jn * 8 + gid;
                b[jn][0] = sB[rn * 32 + c0];
                b[jn][1] = sB[rn * 32 + c1];
            }
#pragma unroll
            for (int im = 0; im < 2; im++)
#pragma unroll
                for (int jn = 0; jn < 8; jn++)
                    mma_tf32(acc[im][jn], a[im], b[jn]);
        }
        __syncthreads();
        if (kt + 3 < 32) issue(kt + 3, s);
    }

#pragma unroll
    for (int im = 0; im < 2; im++) {
        const int mr = m0 + wm + im * 16 + gid;
        const int b0r = mr >> 10, l0r = mr & 1023;
        const int b1r = (mr + 8) >> 10, l1r = (mr + 8) & 1023;
#pragma unroll
        for (int jn = 0; jn < 8; jn++) {
            const int n  = n0 + wn + jn * 8 + 2 * tig;
            const int h  = n >> 6;
            const int dd = n & 63;
            const float bi0 = bias[n], bi1 = bias[n + 1];
            float2 v0, v1;
            v0.x = acc[im][jn][0] + bi0; v0.y = acc[im][jn][1] + bi1;
            v1.x = acc[im][jn][2] + bi0; v1.y = acc[im][jn][3] + bi1;
            *reinterpret_cast<float2*>(
                &out[(((size_t)(b0r * H_ + h)) * L_ + l0r) * D_ + dd]) = v0;
            *reinterpret_cast<float2*>(
                &out[(((size_t)(b1r * H_ + h)) * L_ + l1r) * D_ + dd]) = v1;
        }
    }
#else
    (void)bq; (void)bk; (void)bv;
#endif
}

// ---------------------------------------------------------------------------
// Kernel 2a: attention on tcgen05 (sm_103a pass), 2-CTA/SM (R14 base).
// ONE change vs R14: P goes to TMEM via tcgen05.st (STTM) and PV-MMA runs in
// TS mode (A = P in TMEM). P smem region removed (96K -> 64K smem).
// SMEM: Q 32K @0 | K 16K @32768 | Vt 16K @49152 = 64K.
// TMEM (alloc 256): S slots @0,@64 | O @128 | P @192.
// ---------------------------------------------------------------------------
#define AQ_OFF   0
#define AK_OFF   32768
#define AVT_OFF  49152
#define ATTN_TC_SMEM 65536

__global__ __launch_bounds__(256, 2)
void attn_tc_kernel(float* __restrict__ O)
{
#ifdef TC_OK
    extern __shared__ __align__(1024) char smem[];
    __shared__ uint32_t s_tmem;
    __shared__ __align__(8) uint64_t s_mbar_s, s_mbar_pv;
    __shared__ float s_l[2][128];

    const int t    = threadIdx.x;
    const int wid  = t >> 5;
    const int lane = t & 31;
    const int pr   = wid >> 2;          // column-half (0: cols 0-31, 1: 32-63)
    const int sp   = wid & 3;           // TMEM subpartition -> rows sp*32..+31
    const int bh   = blockIdx.y;
    const int q0   = blockIdx.x * 128;

    const float* __restrict__ Qb = g_Q + (size_t)bh * L_ * D_;
    const float* __restrict__ Kb = g_K + (size_t)bh * L_ * D_;
    const float* __restrict__ Vb = g_V + (size_t)bh * L_ * D_;

    const uint32_t su   = smem_u32(smem);
    const uint32_t qb   = su + AQ_OFF;
    const uint32_t kbuf = su + AK_OFF;
    const uint32_t vtb  = su + AVT_OFF;

    if (wid == 0) {
        TCG_ALLOC(smem_u32(&s_tmem), 256);
        TCG_RELINQ();
    }
    if (t == 0) {
        MBAR_INIT(smem_u32(&s_mbar_s), 1);
        MBAR_INIT(smem_u32(&s_mbar_pv), 1);
    }
    __syncthreads();
    const uint32_t tmem = s_tmem;
    const uint32_t TM_O = tmem + 128;
    const uint32_t TM_P = tmem + 192;
    const uint32_t mb_s  = smem_u32(&s_mbar_s);
    const uint32_t mb_pv = smem_u32(&s_mbar_pv);

    auto load_q = [&]() {
#pragma unroll
        for (int c = 0; c < 2; c++) {
#pragma unroll
            for (int u = 0; u < 4; u++) {
                const int f   = u * 256 + t;
                const int row = f >> 3;
                const int cg  = f & 7;
                const float* src = Qb + (size_t)(q0 + row) * D_ + c * 32 + cg * 4;
                CP_ASYNC_CG(qb + c * 16384 + SWZ(row * 128 + cg * 16), src);
            }
        }
    };
    auto load_k = [&](int row0) {
#pragma unroll
        for (int c = 0; c < 2; c++) {
#pragma unroll
            for (int u = 0; u < 2; u++) {
                const int g   = u * 256 + t;
                const int row = g >> 3;
                const int cg  = g & 7;
                const float* src = Kb + (size_t)(row0 + row) * D_ + c * 32 + cg * 4;
                CP_ASYNC_CG(kbuf + c * 8192 + SWZ(row * 128 + cg * 16), src);
            }
        }
    };

    // prologue: Q + K0
    load_q();
    load_k(0);
    CP_ASYNC_COMMIT();
    CP_ASYNC_WAIT(0);
    asm volatile("fence.proxy.async.shared::cta;" ::: "memory");
    __syncthreads();

    const uint32_t id_64 = idesc_tf32(64);

    // S-MMA(0)
    if (wid == 0 && elect_one()) {
#pragma unroll
        for (int c = 0; c < 2; c++) {
            const uint64_t adesc = make_desc_sw128(qb + c * 16384);
            const uint64_t bdesc = make_desc_sw128(kbuf + c * 8192);
#pragma unroll
            for (int ks = 0; ks < 4; ks++)
                mma_ss_tf32(tmem, adesc + ks * 2, bdesc + ks * 2,
                            id_64, (c > 0 || ks > 0) ? 1u : 0u);
        }
        TCG_COMMIT(mb_s);
    }

    float lpart = 0.f;
    const float scale = 0.125f;
    // V/Vt mapping (conflict-free transpose) — unchanged from R14:
    const int vrow8 = lane & 7;
    const int vdh   = lane >> 3;
    const int vcol  = (wid & 3) * 8 + vrow8;
    const int vchnk = wid >> 2;

    for (int kt = 0; kt < 16; kt++) {
        // --- V(kt) loads: 8 x float2, coalesced ---
        float2 vr[8];
        {
            const float* vbase = Vb + (size_t)(kt * 64 + wid * 8 + vrow8) * D_ + vdh * 2;
#pragma unroll
            for (int m = 0; m < 8; m++)
                vr[m] = *reinterpret_cast<const float2*>(vbase + m * 8);
        }

        // --- wait S(kt); kbuf now free -> issue K(kt+1) load immediately ---
        MBAR_WAIT(mb_s, kt & 1);
        TCG_FENCE_AFTER();
        if (kt < 15) {
            load_k((kt + 1) * 64);
            CP_ASYNC_COMMIT();
        }

        // --- read S(kt) + exp (one 32-col LDTM per warp) ---
        uint32_t r0[32];
        TCG_LD_X32(r0, tmem + (kt & 1) * 64 + pr * 32);
        TCG_WAIT_LD();
        uint32_t pu[32];
#pragma unroll
        for (int j = 0; j < 32; j++) {
            float f = tf32r(__expf(__uint_as_float(r0[j]) * scale));
            lpart += f;
            pu[j] = __float_as_uint(f);
        }

        // --- wait PV(kt-1) before overwriting P (TMEM) and Vt ---
        if (kt > 0) MBAR_WAIT(mb_pv, (kt - 1) & 1);
        TCG_FENCE_AFTER();

        // --- store P (tf32) to TMEM: warp's subpartition rows, cols pr*32 ---
        TCG_ST_X32(TM_P + pr * 32, pu);
        TCG_WAIT_ST();

        // --- store Vt(kt) transposed: conflict-free scalar stores ---
        {
            const uint32_t vdst = vtb + vchnk * 8192;
#pragma unroll
            for (int m = 0; m < 8; m++) {
                const int d0 = m * 8 + vdh * 2;
                float e0 = tf32r(vr[m].x);
                float e1 = tf32r(vr[m].y);
                *reinterpret_cast<float*>((char*)smem + (vdst + SWZ((d0 + 0) * 128 + vcol * 4) - su)) = e0;
                *reinterpret_cast<float*>((char*)smem + (vdst + SWZ((d0 + 1) * 128 + vcol * 4) - su)) = e1;
            }
        }

        // K(kt+1) completion (only group in flight), then rendezvous
        if (kt < 15) CP_ASYNC_WAIT(0);
        asm volatile("fence.proxy.async.shared::cta;" ::: "memory");
        TCG_FENCE_BEFORE();
        __syncthreads();

        if (wid == 0 && elect_one()) {
            TCG_FENCE_AFTER();
            if (kt < 15) {   // S-MMA(kt+1) into the other slot
                const uint32_t dslot = tmem + ((kt + 1) & 1) * 64;
#pragma unroll
                for (int c = 0; c < 2; c++) {
                    const uint64_t adesc = make_desc_sw128(qb + c * 16384);
                    const uint64_t bdesc = make_desc_sw128(kbuf + c * 8192);
#pragma unroll
                    for (int ks = 0; ks < 4; ks++)
                        mma_ss_tf32(dslot, adesc + ks * 2, bdesc + ks * 2,
                                    id_64, (c > 0 || ks > 0) ? 1u : 0u);
                }
                TCG_COMMIT(mb_s);
            }
            // PV-MMA(kt): O += P(TMEM) x Vt(smem), TS mode, 8 k-steps
            {
#pragma unroll
                for (int ks = 0; ks < 8; ks++) {
                    const int ch = ks >> 2;
                    const uint32_t a_tm  = TM_P + ks * 8;
                    const uint64_t bdesc = make_desc_sw128(vtb + ch * 8192) + (ks & 3) * 2;
                    mma_ts_tf32(TM_O, a_tm, bdesc, id_64,
                                (kt > 0 || ks > 0) ? 1u : 0u);
                }
                TCG_COMMIT(mb_pv);
            }
        }
    }

    // combine row sums across column-halves
    s_l[pr][sp * 32 + lane] = lpart;
    __syncthreads();
    const int myrow = sp * 32 + lane;
    const float linv = 1.f / (s_l[0][myrow] + s_l[1][myrow]);

    // wait PV(15), read O, scale, transpose, coalesced store
    MBAR_WAIT(mb_pv, 15 & 1);
    TCG_FENCE_AFTER();
    {
        uint32_t r[32];
        TCG_LD_X32(r, TM_O + pr * 32);
        TCG_WAIT_LD();
        float* patch = reinterpret_cast<float*>(smem) + wid * (33 * 32);   // Q region reuse
        __syncthreads();
#pragma unroll
        for (int j = 0; j < 32; j++)
            patch[j * 33 + lane] = __uint_as_float(r[j]) * linv;
        __syncwarp();
        const int rbase = q0 + sp * 32;
        const int dcol  = pr * 32 + lane;
#pragma unroll
        for (int rr = 0; rr < 32; rr++) {
            O[((size_t)bh * L_ + rbase + rr) * D_ + dcol] = patch[lane * 33 + rr];
        }
    }

    TCG_FENCE_BEFORE();
    __syncthreads();
    if (wid == 0) { TCG_DEALLOC(tmem, 256); }
#else
    (void)O;
#endif
}

// ---------------------------------------------------------------------------
// Kernel 2b: attention fallback (non-a pass), tf32 mma.sync (proven, 256 thr)
// ---------------------------------------------------------------------------
#define QP 68
#define VP 72
#define SM_Q  0
#define SM_P  (128 * QP)
#define SM_K  (2 * 128 * QP)
#define SM_V  (2 * 128 * QP + 64 * QP)
#define ATTN_SMEM_FLOATS (2 * 128 * QP + 64 * QP + 64 * VP)
#define ATTN_SMEM_BYTES  (ATTN_SMEM_FLOATS * 4)

__global__ __launch_bounds__(256, 2)
void attn_mma_kernel(float* __restrict__ O)
{
#ifndef TC_OK
    extern __shared__ float sm[];
    float* Qs = sm + SM_Q;
    float* Ps = sm + SM_P;
    float* Ks = sm + SM_K;
    float* Vs = sm + SM_V;

    const int bh = blockIdx.y;
    const int q0 = blockIdx.x * 128;
    const float* __restrict__ Qb = g_Q + (size_t)bh * L_ * D_;
    const float* __restrict__ Kb = g_K + (size_t)bh * L_ * D_;
    const float* __restrict__ Vb = g_V + (size_t)bh * L_ * D_;

    const int t    = threadIdx.x;
    const int lane = t & 31;
    const int wid  = t >> 5;
    const int gid  = lane >> 2;
    const int tig  = lane & 3;
    const int qb   = wid * 16;

#pragma unroll
    for (int u = 0; u < 8; u++) {
        const int g  = u * 256 + t;
        const int r  = g >> 4;
        const int c4 = (g & 15) * 4;
        float4 v = *reinterpret_cast<const float4*>(&Qb[(size_t)(q0 + r) * D_ + c4]);
        v.x = tf32r(v.x); v.y = tf32r(v.y); v.z = tf32r(v.z); v.w = tf32r(v.w);
        *reinterpret_cast<float4*>(&Qs[r * QP + c4]) = v;
    }

    float m_i[2] = {-CUDART_INF_F, -CUDART_INF_F};
    float l_i[2] = {0.f, 0.f};
    float o[8][4];
#pragma unroll
    for (int j = 0; j < 8; j++)
#pragma unroll
        for (int c = 0; c < 4; c++) o[j][c] = 0.f;

    for (int kt = 0; kt < L_ / 64; kt++) {
        __syncthreads();
        const int k0g = kt * 64;
#pragma unroll
        for (int u = 0; u < 4; u++) {
            const int g  = u * 256 + t;
            const int r  = g >> 4;
            const int c4 = (g & 15) * 4;
            float4 kv = *reinterpret_cast<const float4*>(&Kb[(size_t)(k0g + r) * D_ + c4]);
            float4 vv = *reinterpret_cast<const float4*>(&Vb[(size_t)(k0g + r) * D_ + c4]);
            kv.x = tf32r(kv.x); kv.y = tf32r(kv.y); kv.z = tf32r(kv.z); kv.w = tf32r(kv.w);
            vv.x = tf32r(vv.x); vv.y = tf32r(vv.y); vv.z = tf32r(vv.z); vv.w = tf32r(vv.w);
            *reinterpret_cast<float4*>(&Ks[r * QP + c4]) = kv;
            *reinterpret_cast<float4*>(&Vs[r * VP + c4]) = vv;
        }
        __syncthreads();

        float s[8][4];
#pragma unroll
        for (int j = 0; j < 8; j++)
#pragma unroll
            for (int c = 0; c < 4; c++) s[j][c] = 0.f;

#pragma unroll
        for (int ks = 0; ks < 8; ks++) {
            const int k = ks * 8;
            float a[4];
            a[0] = Qs[(qb + gid) * QP + k + tig];
            a[1] = Qs[(qb + gid + 8) * QP + k + tig];
            a[2] = Qs[(qb + gid) * QP + k + tig + 4];
            a[3] = Qs[(qb + gid + 8) * QP + k + tig + 4];
            float b[8][2];
#pragma unroll
            for (int jn = 0; jn < 8; jn++) {
                const int n = jn * 8;
                b[jn][0] = Ks[(n + gid) * QP + k + tig];
                b[jn][1] = Ks[(n + gid) * QP + k + tig + 4];
            }
#pragma unroll
            for (int jn = 0; jn < 8; jn++)
                mma_tf32(s[jn], a, b[jn]);
        }

        const float scale = 0.125f;
        float mt0 = -CUDART_INF_F, mt1 = -CUDART_INF_F;
#pragma unroll
        for (int jn = 0; jn < 8; jn++) {
            mt0 = fmaxf(mt0, fmaxf(s[jn][0], s[jn][1]));
            mt1 = fmaxf(mt1, fmaxf(s[jn][2], s[jn][3]));
        }
        mt0 *= scale; mt1 *= scale;
#pragma unroll
        for (int off = 1; off < 4; off <<= 1) {
            mt0 = fmaxf(mt0, __shfl_xor_sync(0xffffffffu, mt0, off));
            mt1 = fmaxf(mt1, __shfl_xor_sync(0xffffffffu, mt1, off));
        }
        const float mn0 = fmaxf(m_i[0], mt0);
        const float mn1 = fmaxf(m_i[1], mt1);
        const float cr0 = __expf(m_i[0] - mn0);
        const float cr1 = __expf(m_i[1] - mn1);
        float rs0 = 0.f, rs1 = 0.f;
#pragma unroll
        for (int jn = 0; jn < 8; jn++) {
            s[jn][0] = __expf(fmaf(s[jn][0], scale, -mn0));
            s[jn][1] = __expf(fmaf(s[jn][1], scale, -mn0));
            s[jn][2] = __expf(fmaf(s[jn][2], scale, -mn1));
            s[jn][3] = __expf(fmaf(s[jn][3], scale, -mn1));
            rs0 += s[jn][0] + s[jn][1];
            rs1 += s[jn][2] + s[jn][3];
        }
#pragma unroll
        for (int off = 1; off < 4; off <<= 1) {
            rs0 += __shfl_xor_sync(0xffffffffu, rs0, off);
            rs1 += __shfl_xor_sync(0xffffffffu, rs1, off);
        }
        l_i[0] = l_i[0] * cr0 + rs0;  m_i[0] = mn0;
        l_i[1] = l_i[1] * cr1 + rs1;  m_i[1] = mn1;
#pragma unroll
        for (int jn = 0; jn < 8; jn++) {
            o[jn][0] *= cr0; o[jn][1] *= cr0;
            o[jn][2] *= cr1; o[jn][3] *= cr1;
        }

#pragma unroll
        for (int jn = 0; jn < 8; jn++) {
            const int c = jn * 8 + 2 * tig;
            float2 p0, p1;
            p0.x = tf32r(s[jn][0]); p0.y = tf32r(s[jn][1]);
            p1.x = tf32r(s[jn][2]); p1.y = tf32r(s[jn][3]);
            *reinterpret_cast<float2*>(&Ps[(qb + gid) * QP + c]) = p0;
            *reinterpret_cast<float2*>(&Ps[(qb + gid + 8) * QP + c]) = p1;
        }
        __syncthreads();

#pragma unroll
        for (int ks = 0; ks < 8; ks++) {
            const int k = ks * 8;
            float a[4];
            a[0] = Ps[(qb + gid) * QP + k + tig];
            a[1] = Ps[(qb + gid + 8) * QP + k + tig];
            a[2] = Ps[(qb + gid) * QP + k + tig + 4];
            a[3] = Ps[(qb + gid + 8) * QP + k + tig + 4];
            float b[8][2];
#pragma unroll
            for (int jn = 0; jn < 8; jn++) {
                const int n = jn * 8;
                b[jn][0] = Vs[(k + tig) * VP + n + gid];
                b[jn][1] = Vs[(k + tig + 4) * VP + n + gid];
            }
#pragma unroll
            for (int jn = 0; jn < 8; jn++)
                mma_tf32(o[jn], a, b[jn]);
        }
    }

    const float inv0 = 1.f / l_i[0];
    const float inv1 = 1.f / l_i[1];
    const int r0 = q0 + qb + gid;
    const int r1 = r0 + 8;
#pragma unroll
    for (int jn = 0; jn < 8; jn++) {
        const int c = jn * 8 + 2 * tig;
        float2 v0, v1;
        v0.x = o[jn][0] * inv0; v0.y = o[jn][1] * inv0;
        v1.x = o[jn][2] * inv1; v1.y = o[jn][3] * inv1;
        *reinterpret_cast<float2*>(&O[((size_t)bh * L_ + r0) * D_ + c]) = v0;
        *reinterpret_cast<float2*>(&O[((size_t)bh * L_ + r1) * D_ + c]) = v1;
    }
#else
    (void)O;
#endif
}

// ---------------------------------------------------------------------------
extern "C" void kernel_launch(void* const* d_in, const int* in_sizes, int n_in,
                              void* d_out, int out_size)
{
    const float* x  = (const float*)d_in[0];
    const float* wq = (const float*)d_in[1];
    const float* bq = (const float*)d_in[2];
    const float* wk = (const float*)d_in[3];
    const float* bk = (const float*)d_in[4];
    const float* wv = (const float*)d_in[5];
    const float* bv = (const float*)d_in[6];
    float* out = (float*)d_out;

    cudaFuncSetAttribute(qkv_tc_kernel,
                         cudaFuncAttributeMaxDynamicSharedMemorySize, QKV_TC_SMEM);
    cudaFuncSetAttribute(qkv_mma2_kernel,
                         cudaFuncAttributeMaxDynamicSharedMemorySize, QKV_MMA_SMEM);
    cudaFuncSetAttribute(attn_tc_kernel,
                         cudaFuncAttributeMaxDynamicSharedMemorySize, ATTN_TC_SMEM);
    cudaFuncSetAttribute(attn_mma_kernel,
                         cudaFuncAttributeMaxDynamicSharedMemorySize, ATTN_SMEM_BYTES);

    // fused tf32(rna) rounding of X, Wq, Wk, Wv: exact grid
    const int total4 = NX4 + 3 * NW4;            // 2883584
    cvt_all_kernel<<<total4 / 256, 256>>>((const float4*)x, (const float4*)wq,
                                          (const float4*)wk, (const float4*)wv);

    // QKV: one of the two has a body per cubin
    dim3 tgrid(E_ / 256, M_ROWS / 256, 3);
    qkv_tc_kernel<<<tgrid, 256, QKV_TC_SMEM>>>(bq, bk, bv);
    dim3 fgrid(E_ / 128, M_ROWS / 128, 3);
    qkv_mma2_kernel<<<fgrid, 256, QKV_MMA_SMEM>>>(bq, bk, bv);

    // attention: same dual-variant scheme
    dim3 agrid(L_ / 128, B_ * H_);
    attn_tc_kernel<<<agrid, 256, ATTN_TC_SMEM>>>(out);
    attn_mma_kernel<<<agrid, 256, ATTN_SMEM_BYTES>>>(out);
}